// round 3
// baseline (speedup 1.0000x reference)
#include <cuda_runtime.h>
#include <math.h>

#define TSZ 2048
#define HN  16
#define DH  64

// Scratch: 5 projections in (B,H,T,64) layout + o2d in (B*T, H*64) layout.
__device__ float g_proj[5][(size_t)64 * TSZ * DH];   // 5 * 32 MB
__device__ float g_o2d[(size_t)8192 * 1024];         // 32 MB

__device__ __forceinline__ float f2tf32(float f) {
    unsigned u;
    asm("cvt.rna.tf32.f32 %0, %1;" : "=r"(u) : "f"(f));
    return __uint_as_float(u);
}
__device__ __forceinline__ float4 cvt4(float4 v) {
    float4 r;
    r.x = f2tf32(v.x); r.y = f2tf32(v.y); r.z = f2tf32(v.z); r.w = f2tf32(v.w);
    return r;
}

// ---------------------------------------------------------------------------
// TF32 tensor-core GEMM, double-buffered smem (1 barrier / ktile).
// C = A(MxK)*B(KxN) [+bias,sigmoid]; 128x128 CTA tile, ktile 32,
// 8 warps = 2(m) x 4(n), warp tile 64x32, mma m16n8k8 tf32.
// mode 0: row-major store; mode 1: permuted (b,h,t,d); mode 2: mode1+sigmoid.
// Dynamic smem: 2 * (128*36 + 32*136) floats = 71.7 KB.
// ---------------------------------------------------------------------------
#define AS_STRIDE 36
#define BS_STRIDE 136
#define AS_ELEMS  (128 * AS_STRIDE)
#define BS_ELEMS  (32 * BS_STRIDE)
#define GEMM_SMEM_BYTES ((2 * (AS_ELEMS + BS_ELEMS)) * (int)sizeof(float))

__global__ __launch_bounds__(256) void gemm_tf32_kernel(
    const float* __restrict__ A, const float* __restrict__ B,
    const float* __restrict__ bias, float* __restrict__ C,
    int M, int N, int K, int mode)
{
    extern __shared__ float smem[];
    float* AsBase = smem;                       // [2][128][36]
    float* BsBase = smem + 2 * AS_ELEMS;        // [2][32][136]

    const int tid  = threadIdx.x;
    const int lane = tid & 31;
    const int warpId = tid >> 5;
    const int wm = warpId & 1;
    const int wn = warpId >> 1;
    const int g  = lane >> 2;        // 0..7
    const int tg = lane & 3;         // 0..3
    const int rowBase = blockIdx.y * 128;
    const int colBase = blockIdx.x * 128;

    float acc[4][4][4];
#pragma unroll
    for (int i = 0; i < 4; i++)
#pragma unroll
        for (int j = 0; j < 4; j++)
#pragma unroll
            for (int e = 0; e < 4; e++) acc[i][j][e] = 0.f;

    const int am  = tid >> 1;            // A row 0..127
    const int ak0 = (tid & 1) << 4;      // A k base 0 or 16
    const int bk  = tid >> 3;            // B k row 0..31
    const int bn0 = (tid & 7) << 2;      // B n base 0..28

    const float* Aptr = A + (size_t)(rowBase + am) * K + ak0;
    const float* Bptr = B + (size_t)bk * N + colBase + bn0;

    float4 ra[4], rb[4];
#pragma unroll
    for (int i = 0; i < 4; i++) ra[i] = *(const float4*)(Aptr + i * 4);
#pragma unroll
    for (int i = 0; i < 4; i++) rb[i] = *(const float4*)(Bptr + i * 32);

    // stage 0 store
    {
        float* as = AsBase + am * AS_STRIDE + ak0;
#pragma unroll
        for (int i = 0; i < 4; i++) *(float4*)(as + i * 4) = cvt4(ra[i]);
        float* bs = BsBase + bk * BS_STRIDE + bn0;
#pragma unroll
        for (int i = 0; i < 4; i++) *(float4*)(bs + (i << 5)) = cvt4(rb[i]);
    }
    __syncthreads();

    const int KT = K >> 5;
    for (int kt = 0; kt < KT; kt++) {
        const int cur = kt & 1;
        const bool more = (kt + 1 < KT);
        if (more) {
            Aptr += 32;
            Bptr += (size_t)32 * N;
#pragma unroll
            for (int i = 0; i < 4; i++) ra[i] = *(const float4*)(Aptr + i * 4);
#pragma unroll
            for (int i = 0; i < 4; i++) rb[i] = *(const float4*)(Bptr + i * 32);
        }

        const float* As = AsBase + cur * AS_ELEMS;
        const float* Bs = BsBase + cur * BS_ELEMS;
#pragma unroll
        for (int kk = 0; kk < 4; kk++) {
            unsigned af[4][4];
#pragma unroll
            for (int mi = 0; mi < 4; mi++) {
                const int m0 = wm * 64 + mi * 16 + g;
                const float* a0 = As + m0 * AS_STRIDE + kk * 8 + tg;
                const float* a1 = As + (m0 + 8) * AS_STRIDE + kk * 8 + tg;
                af[mi][0] = __float_as_uint(a0[0]);
                af[mi][1] = __float_as_uint(a1[0]);
                af[mi][2] = __float_as_uint(a0[4]);
                af[mi][3] = __float_as_uint(a1[4]);
            }
            unsigned bf[4][2];
#pragma unroll
            for (int ni = 0; ni < 4; ni++) {
                const int n0 = wn * 32 + ni * 8 + g;
                bf[ni][0] = __float_as_uint(Bs[(kk * 8 + tg) * BS_STRIDE + n0]);
                bf[ni][1] = __float_as_uint(Bs[(kk * 8 + tg + 4) * BS_STRIDE + n0]);
            }
#pragma unroll
            for (int mi = 0; mi < 4; mi++)
#pragma unroll
                for (int ni = 0; ni < 4; ni++) {
                    asm volatile(
                        "mma.sync.aligned.m16n8k8.row.col.f32.tf32.tf32.f32 "
                        "{%0,%1,%2,%3}, {%4,%5,%6,%7}, {%8,%9}, {%0,%1,%2,%3};\n"
                        : "+f"(acc[mi][ni][0]), "+f"(acc[mi][ni][1]),
                          "+f"(acc[mi][ni][2]), "+f"(acc[mi][ni][3])
                        : "r"(af[mi][0]), "r"(af[mi][1]),
                          "r"(af[mi][2]), "r"(af[mi][3]),
                          "r"(bf[ni][0]), "r"(bf[ni][1]));
                }
        }

        if (more) {
            const int nst = cur ^ 1;
            float* as = AsBase + nst * AS_ELEMS + am * AS_STRIDE + ak0;
#pragma unroll
            for (int i = 0; i < 4; i++) *(float4*)(as + i * 4) = cvt4(ra[i]);
            float* bs = BsBase + nst * BS_ELEMS + bk * BS_STRIDE + bn0;
#pragma unroll
            for (int i = 0; i < 4; i++) *(float4*)(bs + (i << 5)) = cvt4(rb[i]);
            __syncthreads();
        }
    }

    // epilogue
#pragma unroll
    for (int mi = 0; mi < 4; mi++) {
        const int gr0 = rowBase + wm * 64 + mi * 16 + g;
#pragma unroll
        for (int ni = 0; ni < 4; ni++) {
            const int gc = colBase + wn * 32 + ni * 8 + 2 * tg;  // even
#pragma unroll
            for (int half = 0; half < 2; half++) {
                const int gr = gr0 + 8 * half;
                float v0 = acc[mi][ni][2 * half];
                float v1 = acc[mi][ni][2 * half + 1];
                if (mode == 0) {
                    float2 st = make_float2(v0, v1);
                    *(float2*)&C[(size_t)gr * N + gc] = st;
                } else {
                    if (mode == 2) {
                        v0 = 1.f / (1.f + __expf(-(v0 + bias[gc])));
                        v1 = 1.f / (1.f + __expf(-(v1 + bias[gc + 1])));
                    }
                    const int b = gr >> 11, t = gr & 2047;
                    const int h = gc >> 6,  d = gc & 63;
                    float2 st = make_float2(v0, v1);
                    *(float2*)&C[((size_t)((b * HN + h) * TSZ + t)) * DH + d] = st;
                }
            }
        }
    }
}

// ---------------------------------------------------------------------------
// Scan kernel v3: 128 CTAs = (bh, half). Each CTA handles 32 of the 64 value
// columns (Cq, G, kc, o are column-independent); the 64x64 S_K state + u
// reduction are duplicated in both halves (cheap). 256 threads.
//   Sk ownership:  (ty 0..3) x (tx 0..63): 16 rows x 1 col
//   Cq/G ownership: rg = ty + 4*(tx>>5) (0..7), c = tx&31: 8 rows x 1 col
// Software-pipelined input vectors (LDG t+2, double-buffered smem).
// ---------------------------------------------------------------------------
__global__ __launch_bounds__(256) void scan_kernel(
    const float* __restrict__ qp, const float* __restrict__ kp,
    const float* __restrict__ vp, const float* __restrict__ aKp,
    const float* __restrict__ aCp, float* __restrict__ o2d)
{
    const int bh   = blockIdx.x >> 1;     // 0..63
    const int half = blockIdx.x & 1;      // 0..1
    const int b = bh >> 4, h = bh & 15;
    const size_t base = (size_t)bh * TSZ * DH;
    const int tid = threadIdx.x;
    const int ty = tid >> 6;              // 0..3
    const int tx = tid & 63;              // 0..63
    const int c  = tx & 31;               // 0..31  (local value column)
    const int rg = ty + ((tx >> 5) << 2); // 0..7   (8-row group for Cq/G)

    __shared__ float svec[2][5][64];      // double-buffered q,k,v,aK,aC
    __shared__ float redA[8][32];         // kc partials
    __shared__ float redB[4][64];         // u partials
    __shared__ float redC[8][32];         // qg partials
    __shared__ float redD[8][32];         // o partials
    __shared__ float ssu[64], sqg[32];

    float Sk[16], Cq[8], G[8];
#pragma unroll
    for (int r = 0; r < 16; r++) Sk[r] = 0.f;
#pragma unroll
    for (int r = 0; r < 8; r++) { Cq[r] = 0.f; G[r] = 0.f; }

    const float* pb = (tid < 64) ? qp : (tid < 128) ? kp : (tid < 192) ? vp : aKp;

    float pr0[2], pr1[2];
    {
        pr0[0] = pb[base + tx];
        pr0[1] = pb[base + DH + tx];
        pr1[0] = (tid < 64) ? aCp[base + tx] : 0.f;
        pr1[1] = (tid < 64) ? aCp[base + DH + tx] : 0.f;
    }
    {
        float* svf = &svec[0][0][0];
        svf[tid] = pr0[0];
        if (tid < 64) svf[256 + tid] = pr1[0];
    }
    __syncthreads();

#pragma unroll 2
    for (int t = 0; t < TSZ; t++) {
        const int cur = t & 1;
        const int nxt = cur ^ 1;
        const int ldslot = t & 1;
        const int stslot = (t + 1) & 1;

        {   // prefetch t+2
            int tp = t + 2; if (tp > TSZ - 1) tp = TSZ - 1;
            const size_t voff = base + (size_t)tp * DH;
            pr0[ldslot] = pb[voff + tx];
            if (tid < 64) pr1[ldslot] = aCp[voff + tx];
        }

        const float* sq  = svec[cur][0];
        const float* sk  = svec[cur][1];
        const float* sv  = svec[cur][2];
        const float* saK = svec[cur][3];
        const float* saC = svec[cur][4];

        // ---- reduction 1: kc[c] = sum_i k_i*aC_i*Cq_old[i][c]
        float p1 = 0.f;
#pragma unroll
        for (int r = 0; r < 8; r++) {
            const int i = rg * 8 + r;
            p1 += sk[i] * saC[i] * Cq[r];
        }
        redA[rg][c] = p1;
        __syncthreads();                                        // S1
        float kc = 0.f;
#pragma unroll
        for (int gg = 0; gg < 8; gg++) kc += redA[gg][c];

        // ---- S_K update (full 64 cols, duplicated) + u partial
        const float ktx  = sk[tx];
        const float aKtx = saK[tx];
        float pu = 0.f;
#pragma unroll
        for (int r = 0; r < 16; r++) {
            const int i = ty * 16 + r;
            Sk[r] = saK[i] * aKtx * Sk[r] + sk[i] * ktx;
            pu += sq[i] * Sk[r];
        }
        // ---- Cq / G updates (8 rows x local col) + qg partial
        const float vcl = sv[half * 32 + c];
        float pg = 0.f;
#pragma unroll
        for (int r = 0; r < 8; r++) {
            const int i = rg * 8 + r;
            Cq[r] = saC[i] * Cq[r] + sq[i] * vcl;
            G[r]  = saK[i] * G[r]  + sk[i] * kc;
            pg += sq[i] * G[r];
        }
        redB[ty][tx] = pu;
        redC[rg][c] = pg;
        __syncthreads();                                        // S2
        if (tid < 64)
            ssu[tid] = redB[0][tid] + redB[1][tid] + redB[2][tid] + redB[3][tid];
        else if (tid < 96) {
            const int cc = tid - 64;
            float s = 0.f;
#pragma unroll
            for (int gg = 0; gg < 8; gg++) s += redC[gg][cc];
            sqg[cc] = s;
        }
        {   // stage t+1 vectors into other buffer
            float* svf = &svec[nxt][0][0];
            svf[tid] = pr0[stslot];
            if (tid < 64) svf[256 + tid] = pr1[stslot];
        }
        __syncthreads();                                        // S3

        // ---- o[c] = sum_j su[j]*Cq_new[j][c] - qg[c]
        float p3 = 0.f;
#pragma unroll
        for (int r = 0; r < 8; r++) {
            p3 += ssu[rg * 8 + r] * Cq[r];
        }
        redD[rg][c] = p3;
        __syncthreads();                                        // S4
        if (tid < 32) {
            float o = -sqg[tid];
#pragma unroll
            for (int gg = 0; gg < 8; gg++) o += redD[gg][tid];
            o2d[(size_t)(b * TSZ + t) * 1024 + h * DH + half * 32 + tid] = o;
        }
    }
}

// ---------------------------------------------------------------------------
extern "C" void kernel_launch(void* const* d_in, const int* in_sizes, int n_in,
                              void* d_out, int out_size)
{
    const float* x   = (const float*)d_in[0];
    const float* Wq  = (const float*)d_in[1];
    const float* Wk  = (const float*)d_in[2];
    const float* Wv  = (const float*)d_in[3];
    const float* WgK = (const float*)d_in[4];
    const float* bgK = (const float*)d_in[5];
    const float* WgC = (const float*)d_in[6];
    const float* bgC = (const float*)d_in[7];
    const float* Wo  = (const float*)d_in[8];
    float* out = (float*)d_out;

    float* proj = nullptr;
    float* o2d  = nullptr;
    cudaGetSymbolAddress((void**)&proj, g_proj);
    cudaGetSymbolAddress((void**)&o2d,  g_o2d);
    const size_t PS = (size_t)64 * TSZ * DH;

    cudaFuncSetAttribute(gemm_tf32_kernel,
                         cudaFuncAttributeMaxDynamicSharedMemorySize,
                         GEMM_SMEM_BYTES);

    const int M = 8192, N = 1024, K = 1024;
    dim3 grid(N / 128, M / 128), blk(256);
    const int shmem = GEMM_SMEM_BYTES;

    gemm_tf32_kernel<<<grid, blk, shmem>>>(x, Wq,  nullptr, proj + 0 * PS, M, N, K, 1);
    gemm_tf32_kernel<<<grid, blk, shmem>>>(x, Wk,  nullptr, proj + 1 * PS, M, N, K, 1);
    gemm_tf32_kernel<<<grid, blk, shmem>>>(x, Wv,  nullptr, proj + 2 * PS, M, N, K, 1);
    gemm_tf32_kernel<<<grid, blk, shmem>>>(x, WgK, bgK,     proj + 3 * PS, M, N, K, 2);
    gemm_tf32_kernel<<<grid, blk, shmem>>>(x, WgC, bgC,     proj + 4 * PS, M, N, K, 2);

    scan_kernel<<<128, 256>>>(proj, proj + PS, proj + 2 * PS,
                              proj + 3 * PS, proj + 4 * PS, o2d);

    gemm_tf32_kernel<<<grid, blk, shmem>>>(o2d, Wo, nullptr, out, M, N, K, 0);
}

// round 4
// speedup vs baseline: 1.9067x; 1.9067x over previous
#include <cuda_runtime.h>
#include <math.h>

#define TSZ 2048
#define HN  16
#define DH  64
#define CL  64                 // chunk length
#define NCHUNK (TSZ / CL)      // 32
#define TS  72                 // smem tile row stride (floats)
#define TILE_F (64 * TS)

// Scratch: 5 projections in (B,H,T,64) layout + o2d in (B*T, H*64) layout.
__device__ float g_proj[5][(size_t)64 * TSZ * DH];   // 5 * 32 MB
__device__ float g_o2d[(size_t)8192 * 1024];         // 32 MB

__device__ __forceinline__ float f2tf32(float f) {
    unsigned u;
    asm("cvt.rna.tf32.f32 %0, %1;" : "=r"(u) : "f"(f));
    return __uint_as_float(u);
}
__device__ __forceinline__ float4 cvt4(float4 v) {
    float4 r;
    r.x = f2tf32(v.x); r.y = f2tf32(v.y); r.z = f2tf32(v.z); r.w = f2tf32(v.w);
    return r;
}

// ---------------------------------------------------------------------------
// TF32 tensor-core GEMM (unchanged from round 3): 128x128 CTA tile, ktile 32,
// double-buffered smem, 8 warps = 2(m) x 4(n), mma m16n8k8 tf32.
// ---------------------------------------------------------------------------
#define AS_STRIDE 36
#define BS_STRIDE 136
#define AS_ELEMS  (128 * AS_STRIDE)
#define BS_ELEMS  (32 * BS_STRIDE)
#define GEMM_SMEM_BYTES ((2 * (AS_ELEMS + BS_ELEMS)) * (int)sizeof(float))

__global__ __launch_bounds__(256) void gemm_tf32_kernel(
    const float* __restrict__ A, const float* __restrict__ B,
    const float* __restrict__ bias, float* __restrict__ C,
    int M, int N, int K, int mode)
{
    extern __shared__ float smem[];
    float* AsBase = smem;
    float* BsBase = smem + 2 * AS_ELEMS;

    const int tid  = threadIdx.x;
    const int lane = tid & 31;
    const int warpId = tid >> 5;
    const int wm = warpId & 1;
    const int wn = warpId >> 1;
    const int g  = lane >> 2;
    const int tg = lane & 3;
    const int rowBase = blockIdx.y * 128;
    const int colBase = blockIdx.x * 128;

    float acc[4][4][4];
#pragma unroll
    for (int i = 0; i < 4; i++)
#pragma unroll
        for (int j = 0; j < 4; j++)
#pragma unroll
            for (int e = 0; e < 4; e++) acc[i][j][e] = 0.f;

    const int am  = tid >> 1;
    const int ak0 = (tid & 1) << 4;
    const int bk  = tid >> 3;
    const int bn0 = (tid & 7) << 2;

    const float* Aptr = A + (size_t)(rowBase + am) * K + ak0;
    const float* Bptr = B + (size_t)bk * N + colBase + bn0;

    float4 ra[4], rb[4];
#pragma unroll
    for (int i = 0; i < 4; i++) ra[i] = *(const float4*)(Aptr + i * 4);
#pragma unroll
    for (int i = 0; i < 4; i++) rb[i] = *(const float4*)(Bptr + i * 32);

    {
        float* as = AsBase + am * AS_STRIDE + ak0;
#pragma unroll
        for (int i = 0; i < 4; i++) *(float4*)(as + i * 4) = cvt4(ra[i]);
        float* bs = BsBase + bk * BS_STRIDE + bn0;
#pragma unroll
        for (int i = 0; i < 4; i++) *(float4*)(bs + (i << 5)) = cvt4(rb[i]);
    }
    __syncthreads();

    const int KT = K >> 5;
    for (int kt = 0; kt < KT; kt++) {
        const int cur = kt & 1;
        const bool more = (kt + 1 < KT);
        if (more) {
            Aptr += 32;
            Bptr += (size_t)32 * N;
#pragma unroll
            for (int i = 0; i < 4; i++) ra[i] = *(const float4*)(Aptr + i * 4);
#pragma unroll
            for (int i = 0; i < 4; i++) rb[i] = *(const float4*)(Bptr + i * 32);
        }

        const float* As = AsBase + cur * AS_ELEMS;
        const float* Bs = BsBase + cur * BS_ELEMS;
#pragma unroll
        for (int kk = 0; kk < 4; kk++) {
            unsigned af[4][4];
#pragma unroll
            for (int mi = 0; mi < 4; mi++) {
                const int m0 = wm * 64 + mi * 16 + g;
                const float* a0 = As + m0 * AS_STRIDE + kk * 8 + tg;
                const float* a1 = As + (m0 + 8) * AS_STRIDE + kk * 8 + tg;
                af[mi][0] = __float_as_uint(a0[0]);
                af[mi][1] = __float_as_uint(a1[0]);
                af[mi][2] = __float_as_uint(a0[4]);
                af[mi][3] = __float_as_uint(a1[4]);
            }
            unsigned bf[4][2];
#pragma unroll
            for (int ni = 0; ni < 4; ni++) {
                const int n0 = wn * 32 + ni * 8 + g;
                bf[ni][0] = __float_as_uint(Bs[(kk * 8 + tg) * BS_STRIDE + n0]);
                bf[ni][1] = __float_as_uint(Bs[(kk * 8 + tg + 4) * BS_STRIDE + n0]);
            }
#pragma unroll
            for (int mi = 0; mi < 4; mi++)
#pragma unroll
                for (int ni = 0; ni < 4; ni++) {
                    asm volatile(
                        "mma.sync.aligned.m16n8k8.row.col.f32.tf32.tf32.f32 "
                        "{%0,%1,%2,%3}, {%4,%5,%6,%7}, {%8,%9}, {%0,%1,%2,%3};\n"
                        : "+f"(acc[mi][ni][0]), "+f"(acc[mi][ni][1]),
                          "+f"(acc[mi][ni][2]), "+f"(acc[mi][ni][3])
                        : "r"(af[mi][0]), "r"(af[mi][1]),
                          "r"(af[mi][2]), "r"(af[mi][3]),
                          "r"(bf[ni][0]), "r"(bf[ni][1]));
                }
        }

        if (more) {
            const int nst = cur ^ 1;
            float* as = AsBase + nst * AS_ELEMS + am * AS_STRIDE + ak0;
#pragma unroll
            for (int i = 0; i < 4; i++) *(float4*)(as + i * 4) = cvt4(ra[i]);
            float* bs = BsBase + nst * BS_ELEMS + bk * BS_STRIDE + bn0;
#pragma unroll
            for (int i = 0; i < 4; i++) *(float4*)(bs + (i << 5)) = cvt4(rb[i]);
            __syncthreads();
        }
    }

#pragma unroll
    for (int mi = 0; mi < 4; mi++) {
        const int gr0 = rowBase + wm * 64 + mi * 16 + g;
#pragma unroll
        for (int ni = 0; ni < 4; ni++) {
            const int gc = colBase + wn * 32 + ni * 8 + 2 * tg;
#pragma unroll
            for (int half = 0; half < 2; half++) {
                const int gr = gr0 + 8 * half;
                float v0 = acc[mi][ni][2 * half];
                float v1 = acc[mi][ni][2 * half + 1];
                if (mode == 0) {
                    float2 st = make_float2(v0, v1);
                    *(float2*)&C[(size_t)gr * N + gc] = st;
                } else {
                    if (mode == 2) {
                        v0 = 1.f / (1.f + __expf(-(v0 + bias[gc])));
                        v1 = 1.f / (1.f + __expf(-(v1 + bias[gc + 1])));
                    }
                    const int b = gr >> 11, t = gr & 2047;
                    const int h = gc >> 6,  d = gc & 63;
                    float2 st = make_float2(v0, v1);
                    *(float2*)&C[((size_t)((b * HN + h) * TSZ + t)) * DH + d] = st;
                }
            }
        }
    }
}

// ---------------------------------------------------------------------------
// Chunked scan: one CTA per (b,h); 32 sequential chunks of L=64.
// All chunk math = 14 tf32 mma 64x64x64 matmuls on smem tiles.
// ---------------------------------------------------------------------------
__device__ __forceinline__ void zero_acc(float (&acc)[4][4]) {
#pragma unroll
    for (int i = 0; i < 4; i++)
#pragma unroll
        for (int j = 0; j < 4; j++) acc[i][j] = 0.f;
}

// OUT(64x64) += opA(A) @ opB(B), warp computes its 16x32 region.
// TRA: A[m][k] = Atile[k][m].  TRB: B[k][n] = Btile[n][k] (i.e. B = tile^T).
// CVTB: round B elements (fp32 state tiles) to tf32.  NEGA: negate A.
template<bool TRA, bool TRB, bool CVTB, bool NEGA>
__device__ __forceinline__ void mm64(const float* __restrict__ A,
                                     const float* __restrict__ B,
                                     float (&acc)[4][4],
                                     int g, int tg, int mb, int nb)
{
#pragma unroll
    for (int k0 = 0; k0 < 64; k0 += 8) {
        unsigned a[4];
        if (!TRA) {
            a[0] = __float_as_uint(A[(mb + g) * TS + k0 + tg]);
            a[1] = __float_as_uint(A[(mb + g + 8) * TS + k0 + tg]);
            a[2] = __float_as_uint(A[(mb + g) * TS + k0 + tg + 4]);
            a[3] = __float_as_uint(A[(mb + g + 8) * TS + k0 + tg + 4]);
        } else {
            a[0] = __float_as_uint(A[(k0 + tg) * TS + mb + g]);
            a[1] = __float_as_uint(A[(k0 + tg) * TS + mb + g + 8]);
            a[2] = __float_as_uint(A[(k0 + tg + 4) * TS + mb + g]);
            a[3] = __float_as_uint(A[(k0 + tg + 4) * TS + mb + g + 8]);
        }
        if (NEGA) {
#pragma unroll
            for (int i = 0; i < 4; i++) a[i] ^= 0x80000000u;
        }
#pragma unroll
        for (int ni = 0; ni < 4; ni++) {
            const int n0 = nb + ni * 8;
            unsigned b0, b1;
            if (!TRB) {
                b0 = __float_as_uint(B[(k0 + tg) * TS + n0 + g]);
                b1 = __float_as_uint(B[(k0 + tg + 4) * TS + n0 + g]);
            } else {
                b0 = __float_as_uint(B[(n0 + g) * TS + k0 + tg]);
                b1 = __float_as_uint(B[(n0 + g) * TS + k0 + tg + 4]);
            }
            if (CVTB) {
                asm("cvt.rna.tf32.f32 %0, %0;" : "+r"(b0));
                asm("cvt.rna.tf32.f32 %0, %0;" : "+r"(b1));
            }
            asm volatile(
                "mma.sync.aligned.m16n8k8.row.col.f32.tf32.tf32.f32 "
                "{%0,%1,%2,%3}, {%4,%5,%6,%7}, {%8,%9}, {%0,%1,%2,%3};\n"
                : "+f"(acc[ni][0]), "+f"(acc[ni][1]),
                  "+f"(acc[ni][2]), "+f"(acc[ni][3])
                : "r"(a[0]), "r"(a[1]), "r"(a[2]), "r"(a[3]),
                  "r"(b0), "r"(b1));
        }
    }
}

// MASK: 0 none, 1 inclusive (keep c<=r), 2 strict (keep c<r).
// SCALE: multiply by scl tile elementwise. Always rounds to tf32 on store.
template<int MASK, bool SCALE>
__device__ __forceinline__ void store_tile(float* __restrict__ O,
    const float* __restrict__ scl, float (&acc)[4][4],
    int g, int tg, int mb, int nb)
{
#pragma unroll
    for (int ni = 0; ni < 4; ni++) {
        const int c0 = nb + ni * 8 + 2 * tg;
#pragma unroll
        for (int hh = 0; hh < 2; hh++) {
            const int r = mb + g + 8 * hh;
#pragma unroll
            for (int e = 0; e < 2; e++) {
                const int c = c0 + e;
                float v = acc[ni][2 * hh + e];
                if (MASK == 1 && c > r)  v = 0.f;
                if (MASK == 2 && c >= r) v = 0.f;
                if (SCALE) v *= scl[r * TS + c];
                O[r * TS + c] = f2tf32(v);
            }
        }
    }
}

// KIND 0: S[r][c] = rs[r]*rs[c]*(S+d); 1/2: St[r][c] = rs[r]*(St+d)
template<int KIND>
__device__ __forceinline__ void update_state(float* __restrict__ St,
    const float* __restrict__ rs, float (&acc)[4][4],
    int g, int tg, int mb, int nb)
{
#pragma unroll
    for (int ni = 0; ni < 4; ni++) {
        const int c0 = nb + ni * 8 + 2 * tg;
#pragma unroll
        for (int hh = 0; hh < 2; hh++) {
            const int r = mb + g + 8 * hh;
            const float rrs = rs[r];
#pragma unroll
            for (int e = 0; e < 2; e++) {
                const int c = c0 + e;
                float s = rrs;
                if (KIND == 0) s *= rs[c];
                St[r * TS + c] = s * (St[r * TS + c] + acc[ni][2 * hh + e]);
            }
        }
    }
}

__device__ __forceinline__ void load_tile64(float* __restrict__ dst,
    const float* __restrict__ src, int tid)
{
#pragma unroll
    for (int i = 0; i < 4; i++) {
        const int e = (tid + i * 256) * 4;        // 0..4092
        const int r = e >> 6, c = e & 63;
        *(float4*)(dst + r * TS + c) = *(const float4*)(src + e);
    }
}

#define SCAN_SMEM_BYTES (12 * TILE_F * (int)sizeof(float))

__global__ __launch_bounds__(256) void scan_chunked(
    const float* __restrict__ qp, const float* __restrict__ kp,
    const float* __restrict__ vp, const float* __restrict__ aKp,
    const float* __restrict__ aCp, float* __restrict__ o2d)
{
    extern __shared__ float sm[];
    float* S   = sm + 0  * TILE_F;   // state S_K  (fp32)
    float* Cst = sm + 1  * TILE_F;   // state C_QV (fp32)
    float* G   = sm + 2  * TILE_F;   // state G    (fp32)
    float* Qh  = sm + 3  * TILE_F;   // Q-hat = q * aKcum
    float* Kt  = sm + 4  * TILE_F;   // K-tilde = k / aKcum
    float* Qt  = sm + 5  * TILE_F;   // Q-tilde = q / aCcum
    float* Kh  = sm + 6  * TILE_F;   // K-hat = k * aCcum
    float* V   = sm + 7  * TILE_F;
    float* SCL = sm + 8  * TILE_F;   // aKcum*aCcum, later Sc2
    float* P   = sm + 9  * TILE_F;
    float* T1  = sm + 10 * TILE_F;   // aKcum -> R -> Uhat
    float* T2  = sm + 11 * TILE_F;   // aCcum -> KC
    __shared__ float aKL[64], aCL[64];

    const int bh = blockIdx.x;
    const int b = bh >> 4, h = bh & 15;
    const size_t base = (size_t)bh * TSZ * DH;
    const int tid  = threadIdx.x;
    const int lane = tid & 31, w = tid >> 5;
    const int g = lane >> 2, tg = lane & 3;
    const int mb = (w & 3) * 16, nb = (w >> 2) * 32;

    for (int i = tid; i < TILE_F; i += 256) { S[i] = 0.f; Cst[i] = 0.f; G[i] = 0.f; }
    __syncthreads();

    for (int ch = 0; ch < NCHUNK; ch++) {
        const size_t off = base + (size_t)ch * CL * DH;
        load_tile64(Qh, qp + off, tid);   // raw q
        load_tile64(Kt, kp + off, tid);   // raw k
        load_tile64(V,  vp + off, tid);
        load_tile64(T1, aKp + off, tid);  // raw aK
        load_tile64(T2, aCp + off, tid);  // raw aC
        __syncthreads();

        // cumulative products down the 64 rows (per column), 2 segments
        {
            float* Tt = (tid < 128) ? T1 : T2;
            const int col = tid & 63;
            const int seg = (tid >> 6) & 1;
            const int r0 = seg * 32;
            float p = 1.f;
#pragma unroll
            for (int r = 0; r < 32; r++) {
                p *= Tt[(r0 + r) * TS + col];
                Tt[(r0 + r) * TS + col] = p;
            }
            __syncthreads();
            if (seg == 1) {
                const float p0 = Tt[31 * TS + col];
#pragma unroll
                for (int r = 32; r < 64; r++) Tt[r * TS + col] *= p0;
            }
        }
        __syncthreads();

        if (tid < 64)        aKL[tid]       = T1[63 * TS + tid];
        else if (tid < 128)  aCL[tid - 64]  = T2[63 * TS + (tid - 64)];

        // elementwise derive (each thread: 16 elements)
#pragma unroll
        for (int i = 0; i < 16; i++) {
            const int e = tid + i * 256;
            const int idx = (e >> 6) * TS + (e & 63);
            const float ak = T1[idx], ac = T2[idx];
            const float qv = Qh[idx], kv = Kt[idx];
            Qh[idx]  = f2tf32(qv * ak);
            Kt[idx]  = f2tf32(kv / ak);
            Qt[idx]  = f2tf32(qv / ac);
            Kh[idx]  = f2tf32(kv * ac);
            SCL[idx] = ak * ac;
            V[idx]   = f2tf32(V[idx]);
        }
        __syncthreads();

        float acc[4][4];

        // phase A: R = (K-hat @ Q-tilde^T) strict  -> T1
        //          P = (Q-hat @ K-tilde^T) incl    -> P
        zero_acc(acc);
        mm64<false, true, false, false>(Kh, Qt, acc, g, tg, mb, nb);
        store_tile<2, false>(T1, nullptr, acc, g, tg, mb, nb);
        zero_acc(acc);
        mm64<false, true, false, false>(Qh, Kt, acc, g, tg, mb, nb);
        store_tile<1, false>(P, nullptr, acc, g, tg, mb, nb);
        __syncthreads();

        // phase B: KC = K-hat @ C0 + R @ V  -> T2
        zero_acc(acc);
        mm64<false, false, true,  false>(Kh, Cst, acc, g, tg, mb, nb);
        mm64<false, false, false, false>(T1, V,   acc, g, tg, mb, nb);
        store_tile<0, false>(T2, nullptr, acc, g, tg, mb, nb);
        __syncthreads();

        // phase C: Uhat = (Q-hat @ S0 + P @ K-tilde) * SCL  -> T1
        zero_acc(acc);
        mm64<false, false, true,  false>(Qh, S,  acc, g, tg, mb, nb);
        mm64<false, false, false, false>(P,  Kt, acc, g, tg, mb, nb);
        store_tile<0, true>(T1, SCL, acc, g, tg, mb, nb);
        __syncthreads();

        // phase D: Sc2 = (Uhat @ Q-tilde^T) incl  -> SCL
        zero_acc(acc);
        mm64<false, true, false, false>(T1, Qt, acc, g, tg, mb, nb);
        store_tile<1, false>(SCL, nullptr, acc, g, tg, mb, nb);
        __syncthreads();

        // phase E: O = Uhat@C0 + Sc2@V - Qhat@G0 - P@KC  -> gmem
        zero_acc(acc);
        mm64<false, false, true,  false>(T1,  Cst, acc, g, tg, mb, nb);
        mm64<false, false, false, false>(SCL, V,   acc, g, tg, mb, nb);
        mm64<false, false, true,  true >(Qh,  G,   acc, g, tg, mb, nb);
        mm64<false, false, false, true >(P,   T2,  acc, g, tg, mb, nb);
        {
            const int t0 = ch * CL;
#pragma unroll
            for (int ni = 0; ni < 4; ni++) {
                const int c0 = nb + ni * 8 + 2 * tg;
#pragma unroll
                for (int hh = 0; hh < 2; hh++) {
                    const int r = mb + g + 8 * hh;
                    float2 st = make_float2(acc[ni][2 * hh], acc[ni][2 * hh + 1]);
                    *(float2*)&o2d[(size_t)(b * TSZ + t0 + r) * 1024 + h * DH + c0] = st;
                }
            }
        }
        __syncthreads();

        // phase F: state updates (each warp owns disjoint regions)
        zero_acc(acc);
        mm64<true, false, false, false>(Kt, Kt, acc, g, tg, mb, nb);
        update_state<0>(S, aKL, acc, g, tg, mb, nb);
        zero_acc(acc);
        mm64<true, false, false, false>(Qt, V, acc, g, tg, mb, nb);
        update_state<1>(Cst, aCL, acc, g, tg, mb, nb);
        zero_acc(acc);
        mm64<true, false, false, false>(Kt, T2, acc, g, tg, mb, nb);
        update_state<2>(G, aKL, acc, g, tg, mb, nb);
        __syncthreads();
    }
}

// ---------------------------------------------------------------------------
extern "C" void kernel_launch(void* const* d_in, const int* in_sizes, int n_in,
                              void* d_out, int out_size)
{
    const float* x   = (const float*)d_in[0];
    const float* Wq  = (const float*)d_in[1];
    const float* Wk  = (const float*)d_in[2];
    const float* Wv  = (const float*)d_in[3];
    const float* WgK = (const float*)d_in[4];
    const float* bgK = (const float*)d_in[5];
    const float* WgC = (const float*)d_in[6];
    const float* bgC = (const float*)d_in[7];
    const float* Wo  = (const float*)d_in[8];
    float* out = (float*)d_out;

    float* proj = nullptr;
    float* o2d  = nullptr;
    cudaGetSymbolAddress((void**)&proj, g_proj);
    cudaGetSymbolAddress((void**)&o2d,  g_o2d);
    const size_t PS = (size_t)64 * TSZ * DH;

    cudaFuncSetAttribute(gemm_tf32_kernel,
                         cudaFuncAttributeMaxDynamicSharedMemorySize,
                         GEMM_SMEM_BYTES);
    cudaFuncSetAttribute(scan_chunked,
                         cudaFuncAttributeMaxDynamicSharedMemorySize,
                         SCAN_SMEM_BYTES);

    const int M = 8192, N = 1024, K = 1024;
    dim3 grid(N / 128, M / 128), blk(256);
    const int shmem = GEMM_SMEM_BYTES;

    gemm_tf32_kernel<<<grid, blk, shmem>>>(x, Wq,  nullptr, proj + 0 * PS, M, N, K, 1);
    gemm_tf32_kernel<<<grid, blk, shmem>>>(x, Wk,  nullptr, proj + 1 * PS, M, N, K, 1);
    gemm_tf32_kernel<<<grid, blk, shmem>>>(x, Wv,  nullptr, proj + 2 * PS, M, N, K, 1);
    gemm_tf32_kernel<<<grid, blk, shmem>>>(x, WgK, bgK,     proj + 3 * PS, M, N, K, 2);
    gemm_tf32_kernel<<<grid, blk, shmem>>>(x, WgC, bgC,     proj + 4 * PS, M, N, K, 2);

    scan_chunked<<<64, 256, SCAN_SMEM_BYTES>>>(proj, proj + PS, proj + 2 * PS,
                                               proj + 3 * PS, proj + 4 * PS, o2d);

    gemm_tf32_kernel<<<grid, blk, shmem>>>(o2d, Wo, nullptr, out, M, N, K, 0);
}

// round 5
// speedup vs baseline: 2.0508x; 1.0756x over previous
#include <cuda_runtime.h>
#include <math.h>

#define TSZ 2048
#define HN  16
#define DH  64
#define CL  64
#define NCHUNK (TSZ / CL)
#define TS  72
#define TILE_F (64 * TS)

#define GM 8192
#define GN 1024
#define GK 1024

// Scratch: 5 projections in (B,H,T,64) layout + o2d in (B*T, H*64) layout.
__device__ float g_proj[5][(size_t)64 * TSZ * DH];   // 5 * 32 MB
__device__ float g_o2d[(size_t)GM * GN];             // 32 MB

__device__ __forceinline__ float f2tf32(float f) {
    unsigned u;
    asm("cvt.rna.tf32.f32 %0, %1;" : "=r"(u) : "f"(f));
    return __uint_as_float(u);
}
__device__ __forceinline__ float4 cvt4(float4 v) {
    float4 r;
    r.x = f2tf32(v.x); r.y = f2tf32(v.y); r.z = f2tf32(v.z); r.w = f2tf32(v.w);
    return r;
}
__device__ __forceinline__ unsigned cvt_tf32_u(unsigned u) {
    asm("cvt.rna.tf32.f32 %0, %0;" : "+r"(u));
    return u;
}

// ---------------------------------------------------------------------------
// TF32 GEMM: 128x256 CTA tile, ktile 32, 8 warps = 2(m) x 4(n), warp 64x64.
// A: LDG->reg->cvt->STS (double buffered). B: cp.async (double buffered).
// One barrier per ktile. multi=1: blockIdx.z selects the 5 projection weights,
// permuted (b,h,t,d) store (+sigmoid for z>=3). multi=0: plain store of A@W0.
// ---------------------------------------------------------------------------
#define AST 36
#define BST 264
#define AS_EL (128 * AST)
#define BS_EL (32 * BST)
#define GEMM_SMEM_BYTES ((2 * (AS_EL + BS_EL)) * (int)sizeof(float))

__global__ __launch_bounds__(256, 1) void gemm_tf32_big(
    const float* __restrict__ A,
    const float* __restrict__ W0, const float* __restrict__ W1,
    const float* __restrict__ W2, const float* __restrict__ W3,
    const float* __restrict__ W4,
    const float* __restrict__ b3, const float* __restrict__ b4,
    float* __restrict__ Cb, int multi)
{
    extern __shared__ float smem[];
    float* AsB = smem;                 // [2][128][36]
    float* BsB = smem + 2 * AS_EL;     // [2][32][264]

    const int tid  = threadIdx.x;
    const int lane = tid & 31;
    const int warpId = tid >> 5;
    const int wm = warpId & 1;
    const int wn = warpId >> 1;        // 0..3
    const int g  = lane >> 2;
    const int tg = lane & 3;
    const int rowBase = blockIdx.y * 128;
    const int colBase = blockIdx.x * 256;

    const size_t PS = (size_t)64 * TSZ * DH;
    const float* W; const float* bias; float* C; int mode;
    if (multi) {
        const int z = blockIdx.z;
        W = (z == 0) ? W0 : (z == 1) ? W1 : (z == 2) ? W2 : (z == 3) ? W3 : W4;
        bias = (z == 3) ? b3 : (z == 4) ? b4 : nullptr;
        C = Cb + (size_t)z * PS;
        mode = (z >= 3) ? 2 : 1;
    } else {
        W = W0; bias = nullptr; C = Cb; mode = 0;
    }

    float acc[4][8][4];
#pragma unroll
    for (int i = 0; i < 4; i++)
#pragma unroll
        for (int j = 0; j < 8; j++)
#pragma unroll
            for (int e = 0; e < 4; e++) acc[i][j][e] = 0.f;

    // A loader: thread -> row am, k-half ak0 (4 float4)
    const int am  = tid >> 1;
    const int ak0 = (tid & 1) << 4;
    const float* Aptr = A + (size_t)(rowBase + am) * GK + ak0;
    // B loader: thread -> k row bk, n cols bn0 + 32j (8 float4 via cp.async)
    const int bk  = tid >> 3;
    const int bn0 = (tid & 7) << 2;
    const float* Bptr = W + (size_t)bk * GN + colBase + bn0;

    unsigned bsAddr;
    {
        float* p = BsB + bk * BST + bn0;
        bsAddr = (unsigned)__cvta_generic_to_shared(p);
    }
    float* asPtr = AsB + am * AST + ak0;

    float4 ra[4];
#pragma unroll
    for (int i = 0; i < 4; i++) ra[i] = *(const float4*)(Aptr + i * 4);
#pragma unroll
    for (int j = 0; j < 8; j++) {
        asm volatile("cp.async.cg.shared.global [%0], [%1], 16;\n"
                     :: "r"(bsAddr + j * 32 * 4), "l"(Bptr + j * 32));
    }
    asm volatile("cp.async.commit_group;\n");

    const int KT = GK / 32;
    for (int kt = 0; kt < KT; kt++) {
        const int cur = kt & 1;
        // STS A(kt) into A-buf[cur]
        {
            float* as = asPtr + cur * AS_EL;
#pragma unroll
            for (int i = 0; i < 4; i++) *(float4*)(as + i * 4) = cvt4(ra[i]);
        }
        asm volatile("cp.async.wait_group 0;\n");
        __syncthreads();

        if (kt + 1 < KT) {
            Aptr += 32;
            Bptr += (size_t)32 * GN;
#pragma unroll
            for (int i = 0; i < 4; i++) ra[i] = *(const float4*)(Aptr + i * 4);
            const unsigned bdst = bsAddr + (cur ^ 1) * BS_EL * 4;
#pragma unroll
            for (int j = 0; j < 8; j++) {
                asm volatile("cp.async.cg.shared.global [%0], [%1], 16;\n"
                             :: "r"(bdst + j * 32 * 4), "l"(Bptr + j * 32));
            }
            asm volatile("cp.async.commit_group;\n");
        }

        const float* As = AsB + cur * AS_EL;
        const float* Bs = BsB + cur * BS_EL;
#pragma unroll
        for (int kk = 0; kk < 4; kk++) {
            unsigned af[4][4];
#pragma unroll
            for (int mi = 0; mi < 4; mi++) {
                const int m0 = wm * 64 + mi * 16 + g;
                const float* a0 = As + m0 * AST + kk * 8 + tg;
                const float* a1 = As + (m0 + 8) * AST + kk * 8 + tg;
                af[mi][0] = __float_as_uint(a0[0]);
                af[mi][1] = __float_as_uint(a1[0]);
                af[mi][2] = __float_as_uint(a0[4]);
                af[mi][3] = __float_as_uint(a1[4]);
            }
#pragma unroll
            for (int ni = 0; ni < 8; ni++) {
                const int n0 = wn * 64 + ni * 8 + g;
                unsigned b0 = cvt_tf32_u(__float_as_uint(Bs[(kk * 8 + tg) * BST + n0]));
                unsigned b1 = cvt_tf32_u(__float_as_uint(Bs[(kk * 8 + tg + 4) * BST + n0]));
#pragma unroll
                for (int mi = 0; mi < 4; mi++) {
                    asm volatile(
                        "mma.sync.aligned.m16n8k8.row.col.f32.tf32.tf32.f32 "
                        "{%0,%1,%2,%3}, {%4,%5,%6,%7}, {%8,%9}, {%0,%1,%2,%3};\n"
                        : "+f"(acc[mi][ni][0]), "+f"(acc[mi][ni][1]),
                          "+f"(acc[mi][ni][2]), "+f"(acc[mi][ni][3])
                        : "r"(af[mi][0]), "r"(af[mi][1]),
                          "r"(af[mi][2]), "r"(af[mi][3]),
                          "r"(b0), "r"(b1));
                }
            }
        }
    }

    // epilogue: warp col range is 64-aligned -> single h per warp in mode 1/2
#pragma unroll
    for (int mi = 0; mi < 4; mi++) {
        const int gr0 = rowBase + wm * 64 + mi * 16 + g;
#pragma unroll
        for (int ni = 0; ni < 8; ni++) {
            const int gc = colBase + wn * 64 + ni * 8 + 2 * tg;
#pragma unroll
            for (int half = 0; half < 2; half++) {
                const int gr = gr0 + 8 * half;
                float v0 = acc[mi][ni][2 * half];
                float v1 = acc[mi][ni][2 * half + 1];
                if (mode == 0) {
                    *(float2*)&C[(size_t)gr * GN + gc] = make_float2(v0, v1);
                } else {
                    if (mode == 2) {
                        v0 = 1.f / (1.f + __expf(-(v0 + bias[gc])));
                        v1 = 1.f / (1.f + __expf(-(v1 + bias[gc + 1])));
                    }
                    const int b = gr >> 11, t = gr & 2047;
                    const int h = gc >> 6,  d = gc & 63;
                    *(float2*)&C[((size_t)((b * HN + h) * TSZ + t)) * DH + d] =
                        make_float2(v0, v1);
                }
            }
        }
    }
}

// ---------------------------------------------------------------------------
// Chunked scan, 512 threads = 16 warps, warp tile 16x16 per 64x64 matmul.
// ---------------------------------------------------------------------------
__device__ __forceinline__ void zero_acc2(float (&acc)[2][4]) {
#pragma unroll
    for (int i = 0; i < 2; i++)
#pragma unroll
        for (int j = 0; j < 4; j++) acc[i][j] = 0.f;
}

template<bool TRA, bool TRB, bool CVTB, bool NEGA>
__device__ __forceinline__ void mm64(const float* __restrict__ A,
                                     const float* __restrict__ B,
                                     float (&acc)[2][4],
                                     int g, int tg, int mb, int nb)
{
#pragma unroll
    for (int k0 = 0; k0 < 64; k0 += 8) {
        unsigned a[4];
        if (!TRA) {
            a[0] = __float_as_uint(A[(mb + g) * TS + k0 + tg]);
            a[1] = __float_as_uint(A[(mb + g + 8) * TS + k0 + tg]);
            a[2] = __float_as_uint(A[(mb + g) * TS + k0 + tg + 4]);
            a[3] = __float_as_uint(A[(mb + g + 8) * TS + k0 + tg + 4]);
        } else {
            a[0] = __float_as_uint(A[(k0 + tg) * TS + mb + g]);
            a[1] = __float_as_uint(A[(k0 + tg) * TS + mb + g + 8]);
            a[2] = __float_as_uint(A[(k0 + tg + 4) * TS + mb + g]);
            a[3] = __float_as_uint(A[(k0 + tg + 4) * TS + mb + g + 8]);
        }
        if (NEGA) {
#pragma unroll
            for (int i = 0; i < 4; i++) a[i] ^= 0x80000000u;
        }
#pragma unroll
        for (int ni = 0; ni < 2; ni++) {
            const int n0 = nb + ni * 8;
            unsigned b0, b1;
            if (!TRB) {
                b0 = __float_as_uint(B[(k0 + tg) * TS + n0 + g]);
                b1 = __float_as_uint(B[(k0 + tg + 4) * TS + n0 + g]);
            } else {
                b0 = __float_as_uint(B[(n0 + g) * TS + k0 + tg]);
                b1 = __float_as_uint(B[(n0 + g) * TS + k0 + tg + 4]);
            }
            if (CVTB) { b0 = cvt_tf32_u(b0); b1 = cvt_tf32_u(b1); }
            asm volatile(
                "mma.sync.aligned.m16n8k8.row.col.f32.tf32.tf32.f32 "
                "{%0,%1,%2,%3}, {%4,%5,%6,%7}, {%8,%9}, {%0,%1,%2,%3};\n"
                : "+f"(acc[ni][0]), "+f"(acc[ni][1]),
                  "+f"(acc[ni][2]), "+f"(acc[ni][3])
                : "r"(a[0]), "r"(a[1]), "r"(a[2]), "r"(a[3]),
                  "r"(b0), "r"(b1));
        }
    }
}

template<int MASK, bool SCALE>
__device__ __forceinline__ void store_tile(float* __restrict__ O,
    const float* __restrict__ scl, float (&acc)[2][4],
    int g, int tg, int mb, int nb)
{
#pragma unroll
    for (int ni = 0; ni < 2; ni++) {
        const int c0 = nb + ni * 8 + 2 * tg;
#pragma unroll
        for (int hh = 0; hh < 2; hh++) {
            const int r = mb + g + 8 * hh;
#pragma unroll
            for (int e = 0; e < 2; e++) {
                const int c = c0 + e;
                float v = acc[ni][2 * hh + e];
                if (MASK == 1 && c > r)  v = 0.f;
                if (MASK == 2 && c >= r) v = 0.f;
                if (SCALE) v *= scl[r * TS + c];
                O[r * TS + c] = f2tf32(v);
            }
        }
    }
}

template<int KIND>
__device__ __forceinline__ void update_state(float* __restrict__ St,
    const float* __restrict__ rs, float (&acc)[2][4],
    int g, int tg, int mb, int nb)
{
#pragma unroll
    for (int ni = 0; ni < 2; ni++) {
        const int c0 = nb + ni * 8 + 2 * tg;
#pragma unroll
        for (int hh = 0; hh < 2; hh++) {
            const int r = mb + g + 8 * hh;
            const float rrs = rs[r];
#pragma unroll
            for (int e = 0; e < 2; e++) {
                const int c = c0 + e;
                float s = rrs;
                if (KIND == 0) s *= rs[c];
                St[r * TS + c] = s * (St[r * TS + c] + acc[ni][2 * hh + e]);
            }
        }
    }
}

__device__ __forceinline__ void load_tile64(float* __restrict__ dst,
    const float* __restrict__ src, int tid)
{
#pragma unroll
    for (int i = 0; i < 2; i++) {
        const int e = (tid + i * 512) * 4;
        const int r = e >> 6, c = e & 63;
        *(float4*)(dst + r * TS + c) = *(const float4*)(src + e);
    }
}

#define SCAN_SMEM_BYTES (12 * TILE_F * (int)sizeof(float))

__global__ __launch_bounds__(512) void scan_chunked(
    const float* __restrict__ qp, const float* __restrict__ kp,
    const float* __restrict__ vp, const float* __restrict__ aKp,
    const float* __restrict__ aCp, float* __restrict__ o2d)
{
    extern __shared__ float sm[];
    float* S   = sm + 0  * TILE_F;
    float* Cst = sm + 1  * TILE_F;
    float* G   = sm + 2  * TILE_F;
    float* Qh  = sm + 3  * TILE_F;
    float* Kt  = sm + 4  * TILE_F;
    float* Qt  = sm + 5  * TILE_F;
    float* Kh  = sm + 6  * TILE_F;
    float* V   = sm + 7  * TILE_F;
    float* SCL = sm + 8  * TILE_F;
    float* P   = sm + 9  * TILE_F;
    float* T1  = sm + 10 * TILE_F;
    float* T2  = sm + 11 * TILE_F;
    __shared__ float aKL[64], aCL[64];

    const int bh = blockIdx.x;
    const int b = bh >> 4, h = bh & 15;
    const size_t base = (size_t)bh * TSZ * DH;
    const int tid  = threadIdx.x;
    const int lane = tid & 31, w = tid >> 5;       // w 0..15
    const int g = lane >> 2, tg = lane & 3;
    const int mb = (w & 3) * 16, nb = (w >> 2) * 16;

    for (int i = tid; i < TILE_F; i += 512) { S[i] = 0.f; Cst[i] = 0.f; G[i] = 0.f; }
    __syncthreads();

    for (int ch = 0; ch < NCHUNK; ch++) {
        const size_t off = base + (size_t)ch * CL * DH;
        load_tile64(Qh, qp + off, tid);
        load_tile64(Kt, kp + off, tid);
        load_tile64(V,  vp + off, tid);
        load_tile64(T1, aKp + off, tid);
        load_tile64(T2, aCp + off, tid);
        __syncthreads();

        // cumulative products: 4 segments of 16 rows per column, then fixup
        {
            float* Tt = (tid < 256) ? T1 : T2;
            const int col = tid & 63;
            const int seg = (tid >> 6) & 3;
            const int r0 = seg * 16;
            float p = 1.f;
#pragma unroll
            for (int r = 0; r < 16; r++) {
                p *= Tt[(r0 + r) * TS + col];
                Tt[(r0 + r) * TS + col] = p;
            }
            __syncthreads();
            float pref = 1.f;
#pragma unroll
            for (int s = 0; s < 3; s++)
                if (s < seg) pref *= Tt[(s * 16 + 15) * TS + col];
            __syncthreads();   // boundary reads complete before scaling writes
            if (seg > 0) {
#pragma unroll
                for (int r = 0; r < 16; r++) Tt[(r0 + r) * TS + col] *= pref;
            }
        }
        __syncthreads();

        if (tid < 64)        aKL[tid]      = T1[63 * TS + tid];
        else if (tid < 128)  aCL[tid - 64] = T2[63 * TS + (tid - 64)];

        // elementwise derive (8 elements per thread)
#pragma unroll
        for (int i = 0; i < 8; i++) {
            const int e = tid + i * 512;
            const int idx = (e >> 6) * TS + (e & 63);
            const float ak = T1[idx], ac = T2[idx];
            const float qv = Qh[idx], kv = Kt[idx];
            Qh[idx]  = f2tf32(qv * ak);
            Kt[idx]  = f2tf32(kv / ak);
            Qt[idx]  = f2tf32(qv / ac);
            Kh[idx]  = f2tf32(kv * ac);
            SCL[idx] = ak * ac;
            V[idx]   = f2tf32(V[idx]);
        }
        __syncthreads();

        float acc[2][4];

        // A: R = (Kh @ Qt^T) strict -> T1 ; P = (Qh @ Kt^T) incl -> P
        zero_acc2(acc);
        mm64<false, true, false, false>(Kh, Qt, acc, g, tg, mb, nb);
        store_tile<2, false>(T1, nullptr, acc, g, tg, mb, nb);
        zero_acc2(acc);
        mm64<false, true, false, false>(Qh, Kt, acc, g, tg, mb, nb);
        store_tile<1, false>(P, nullptr, acc, g, tg, mb, nb);
        __syncthreads();

        // B: KC = Kh @ C0 + R @ V -> T2
        zero_acc2(acc);
        mm64<false, false, true,  false>(Kh, Cst, acc, g, tg, mb, nb);
        mm64<false, false, false, false>(T1, V,   acc, g, tg, mb, nb);
        store_tile<0, false>(T2, nullptr, acc, g, tg, mb, nb);
        __syncthreads();

        // C: Uhat = (Qh @ S0 + P @ Kt) * SCL -> T1
        zero_acc2(acc);
        mm64<false, false, true,  false>(Qh, S,  acc, g, tg, mb, nb);
        mm64<false, false, false, false>(P,  Kt, acc, g, tg, mb, nb);
        store_tile<0, true>(T1, SCL, acc, g, tg, mb, nb);
        __syncthreads();

        // D: Sc2 = (Uhat @ Qt^T) incl -> SCL
        zero_acc2(acc);
        mm64<false, true, false, false>(T1, Qt, acc, g, tg, mb, nb);
        store_tile<1, false>(SCL, nullptr, acc, g, tg, mb, nb);
        __syncthreads();

        // E: O = Uhat@C0 + Sc2@V - Qh@G0 - P@KC -> gmem
        zero_acc2(acc);
        mm64<false, false, true,  false>(T1,  Cst, acc, g, tg, mb, nb);
        mm64<false, false, false, false>(SCL, V,   acc, g, tg, mb, nb);
        mm64<false, false, true,  true >(Qh,  G,   acc, g, tg, mb, nb);
        mm64<false, false, false, true >(P,   T2,  acc, g, tg, mb, nb);
        {
            const int t0 = ch * CL;
#pragma unroll
            for (int ni = 0; ni < 2; ni++) {
                const int c0 = nb + ni * 8 + 2 * tg;
#pragma unroll
                for (int hh = 0; hh < 2; hh++) {
                    const int r = mb + g + 8 * hh;
                    float2 st = make_float2(acc[ni][2 * hh], acc[ni][2 * hh + 1]);
                    *(float2*)&o2d[(size_t)(b * TSZ + t0 + r) * 1024 + h * DH + c0] = st;
                }
            }
        }
        __syncthreads();

        // F: state updates
        zero_acc2(acc);
        mm64<true, false, false, false>(Kt, Kt, acc, g, tg, mb, nb);
        update_state<0>(S, aKL, acc, g, tg, mb, nb);
        zero_acc2(acc);
        mm64<true, false, false, false>(Qt, V, acc, g, tg, mb, nb);
        update_state<1>(Cst, aCL, acc, g, tg, mb, nb);
        zero_acc2(acc);
        mm64<true, false, false, false>(Kt, T2, acc, g, tg, mb, nb);
        update_state<2>(G, aKL, acc, g, tg, mb, nb);
        __syncthreads();
    }
}

// ---------------------------------------------------------------------------
extern "C" void kernel_launch(void* const* d_in, const int* in_sizes, int n_in,
                              void* d_out, int out_size)
{
    const float* x   = (const float*)d_in[0];
    const float* Wq  = (const float*)d_in[1];
    const float* Wk  = (const float*)d_in[2];
    const float* Wv  = (const float*)d_in[3];
    const float* WgK = (const float*)d_in[4];
    const float* bgK = (const float*)d_in[5];
    const float* WgC = (const float*)d_in[6];
    const float* bgC = (const float*)d_in[7];
    const float* Wo  = (const float*)d_in[8];
    float* out = (float*)d_out;

    float* proj = nullptr;
    float* o2d  = nullptr;
    cudaGetSymbolAddress((void**)&proj, g_proj);
    cudaGetSymbolAddress((void**)&o2d,  g_o2d);
    const size_t PS = (size_t)64 * TSZ * DH;

    cudaFuncSetAttribute(gemm_tf32_big,
                         cudaFuncAttributeMaxDynamicSharedMemorySize,
                         GEMM_SMEM_BYTES);
    cudaFuncSetAttribute(scan_chunked,
                         cudaFuncAttributeMaxDynamicSharedMemorySize,
                         SCAN_SMEM_BYTES);

    dim3 blk(256);
    dim3 gridProj(GN / 256, GM / 128, 5);
    dim3 gridOut(GN / 256, GM / 128, 1);

    // 5 projections in one launch
    gemm_tf32_big<<<gridProj, blk, GEMM_SMEM_BYTES>>>(
        x, Wq, Wk, Wv, WgK, WgC, bgK, bgC, proj, 1);

    scan_chunked<<<64, 512, SCAN_SMEM_BYTES>>>(proj, proj + PS, proj + 2 * PS,
                                               proj + 3 * PS, proj + 4 * PS, o2d);

    gemm_tf32_big<<<gridOut, blk, GEMM_SMEM_BYTES>>>(
        o2d, Wo, nullptr, nullptr, nullptr, nullptr, nullptr, nullptr, out, 0);
}

// round 6
// speedup vs baseline: 2.2534x; 1.0988x over previous
#include <cuda_runtime.h>
#include <math.h>

#define TSZ 2048
#define HN  16
#define DH  64
#define CL  64
#define NCHUNK (TSZ / CL)
#define TS  72                 // stride for 64-wide tiles
#define HS  40                 // stride for 32-wide tiles
#define TSF (64 * TS)
#define HSF (64 * HS)

#define GM 8192
#define GN 1024
#define GK 1024

__device__ float g_proj[5][(size_t)64 * TSZ * DH];   // 5 * 32 MB
__device__ float g_o2d[(size_t)GM * GN];             // 32 MB

__device__ __forceinline__ float f2tf32(float f) {
    unsigned u;
    asm("cvt.rna.tf32.f32 %0, %1;" : "=r"(u) : "f"(f));
    return __uint_as_float(u);
}
__device__ __forceinline__ float4 cvt4(float4 v) {
    float4 r;
    r.x = f2tf32(v.x); r.y = f2tf32(v.y); r.z = f2tf32(v.z); r.w = f2tf32(v.w);
    return r;
}
__device__ __forceinline__ unsigned cvt_tf32_u(unsigned u) {
    asm("cvt.rna.tf32.f32 %0, %0;" : "+r"(u));
    return u;
}

// ---------------------------------------------------------------------------
// TF32 GEMM (unchanged from round 5): 128x256 CTA tile, ktile 32, 8 warps,
// warp 64x64, cp.async B, double-buffered, one barrier/ktile.
// ---------------------------------------------------------------------------
#define AST 36
#define BST 264
#define AS_EL (128 * AST)
#define BS_EL (32 * BST)
#define GEMM_SMEM_BYTES ((2 * (AS_EL + BS_EL)) * (int)sizeof(float))

__global__ __launch_bounds__(256, 1) void gemm_tf32_big(
    const float* __restrict__ A,
    const float* __restrict__ W0, const float* __restrict__ W1,
    const float* __restrict__ W2, const float* __restrict__ W3,
    const float* __restrict__ W4,
    const float* __restrict__ b3, const float* __restrict__ b4,
    float* __restrict__ Cb, int multi)
{
    extern __shared__ float smem[];
    float* AsB = smem;
    float* BsB = smem + 2 * AS_EL;

    const int tid  = threadIdx.x;
    const int lane = tid & 31;
    const int warpId = tid >> 5;
    const int wm = warpId & 1;
    const int wn = warpId >> 1;
    const int g  = lane >> 2;
    const int tg = lane & 3;
    const int rowBase = blockIdx.y * 128;
    const int colBase = blockIdx.x * 256;

    const size_t PS = (size_t)64 * TSZ * DH;
    const float* W; const float* bias; float* C; int mode;
    if (multi) {
        const int z = blockIdx.z;
        W = (z == 0) ? W0 : (z == 1) ? W1 : (z == 2) ? W2 : (z == 3) ? W3 : W4;
        bias = (z == 3) ? b3 : (z == 4) ? b4 : nullptr;
        C = Cb + (size_t)z * PS;
        mode = (z >= 3) ? 2 : 1;
    } else {
        W = W0; bias = nullptr; C = Cb; mode = 0;
    }

    float acc[4][8][4];
#pragma unroll
    for (int i = 0; i < 4; i++)
#pragma unroll
        for (int j = 0; j < 8; j++)
#pragma unroll
            for (int e = 0; e < 4; e++) acc[i][j][e] = 0.f;

    const int am  = tid >> 1;
    const int ak0 = (tid & 1) << 4;
    const float* Aptr = A + (size_t)(rowBase + am) * GK + ak0;
    const int bk  = tid >> 3;
    const int bn0 = (tid & 7) << 2;
    const float* Bptr = W + (size_t)bk * GN + colBase + bn0;

    unsigned bsAddr;
    {
        float* p = BsB + bk * BST + bn0;
        bsAddr = (unsigned)__cvta_generic_to_shared(p);
    }
    float* asPtr = AsB + am * AST + ak0;

    float4 ra[4];
#pragma unroll
    for (int i = 0; i < 4; i++) ra[i] = *(const float4*)(Aptr + i * 4);
#pragma unroll
    for (int j = 0; j < 8; j++) {
        asm volatile("cp.async.cg.shared.global [%0], [%1], 16;\n"
                     :: "r"(bsAddr + j * 32 * 4), "l"(Bptr + j * 32));
    }
    asm volatile("cp.async.commit_group;\n");

    const int KT = GK / 32;
    for (int kt = 0; kt < KT; kt++) {
        const int cur = kt & 1;
        {
            float* as = asPtr + cur * AS_EL;
#pragma unroll
            for (int i = 0; i < 4; i++) *(float4*)(as + i * 4) = cvt4(ra[i]);
        }
        asm volatile("cp.async.wait_group 0;\n");
        __syncthreads();

        if (kt + 1 < KT) {
            Aptr += 32;
            Bptr += (size_t)32 * GN;
#pragma unroll
            for (int i = 0; i < 4; i++) ra[i] = *(const float4*)(Aptr + i * 4);
            const unsigned bdst = bsAddr + (cur ^ 1) * BS_EL * 4;
#pragma unroll
            for (int j = 0; j < 8; j++) {
                asm volatile("cp.async.cg.shared.global [%0], [%1], 16;\n"
                             :: "r"(bdst + j * 32 * 4), "l"(Bptr + j * 32));
            }
            asm volatile("cp.async.commit_group;\n");
        }

        const float* As = AsB + cur * AS_EL;
        const float* Bs = BsB + cur * BS_EL;
#pragma unroll
        for (int kk = 0; kk < 4; kk++) {
            unsigned af[4][4];
#pragma unroll
            for (int mi = 0; mi < 4; mi++) {
                const int m0 = wm * 64 + mi * 16 + g;
                const float* a0 = As + m0 * AST + kk * 8 + tg;
                const float* a1 = As + (m0 + 8) * AST + kk * 8 + tg;
                af[mi][0] = __float_as_uint(a0[0]);
                af[mi][1] = __float_as_uint(a1[0]);
                af[mi][2] = __float_as_uint(a0[4]);
                af[mi][3] = __float_as_uint(a1[4]);
            }
#pragma unroll
            for (int ni = 0; ni < 8; ni++) {
                const int n0 = wn * 64 + ni * 8 + g;
                unsigned b0 = cvt_tf32_u(__float_as_uint(Bs[(kk * 8 + tg) * BST + n0]));
                unsigned b1 = cvt_tf32_u(__float_as_uint(Bs[(kk * 8 + tg + 4) * BST + n0]));
#pragma unroll
                for (int mi = 0; mi < 4; mi++) {
                    asm volatile(
                        "mma.sync.aligned.m16n8k8.row.col.f32.tf32.tf32.f32 "
                        "{%0,%1,%2,%3}, {%4,%5,%6,%7}, {%8,%9}, {%0,%1,%2,%3};\n"
                        : "+f"(acc[mi][ni][0]), "+f"(acc[mi][ni][1]),
                          "+f"(acc[mi][ni][2]), "+f"(acc[mi][ni][3])
                        : "r"(af[mi][0]), "r"(af[mi][1]),
                          "r"(af[mi][2]), "r"(af[mi][3]),
                          "r"(b0), "r"(b1));
                }
            }
        }
    }

#pragma unroll
    for (int mi = 0; mi < 4; mi++) {
        const int gr0 = rowBase + wm * 64 + mi * 16 + g;
#pragma unroll
        for (int ni = 0; ni < 8; ni++) {
            const int gc = colBase + wn * 64 + ni * 8 + 2 * tg;
#pragma unroll
            for (int half = 0; half < 2; half++) {
                const int gr = gr0 + 8 * half;
                float v0 = acc[mi][ni][2 * half];
                float v1 = acc[mi][ni][2 * half + 1];
                if (mode == 0) {
                    *(float2*)&C[(size_t)gr * GN + gc] = make_float2(v0, v1);
                } else {
                    if (mode == 2) {
                        v0 = 1.f / (1.f + __expf(-(v0 + bias[gc])));
                        v1 = 1.f / (1.f + __expf(-(v1 + bias[gc + 1])));
                    }
                    const int b = gr >> 11, t = gr & 2047;
                    const int h = gc >> 6,  d = gc & 63;
                    *(float2*)&C[((size_t)((b * HN + h) * TSZ + t)) * DH + d] =
                        make_float2(v0, v1);
                }
            }
        }
    }
}

// ---------------------------------------------------------------------------
// Chunked scan, dv-split: 128 CTAs = (bh, half). 256 threads, 8 warps.
// N=64 matmuls: warp tile 16x32 (nb64); N=32 matmuls: 16x16 (nb32).
// ---------------------------------------------------------------------------
template<int NI>
__device__ __forceinline__ void zacc(float (&acc)[NI][4]) {
#pragma unroll
    for (int i = 0; i < NI; i++)
#pragma unroll
        for (int j = 0; j < 4; j++) acc[i][j] = 0.f;
}

// acc(16 x NI*8) += opA(A) @ opB(B). A tiles always stride TS.
template<int NI, bool TRA, bool TRB, bool CVTB, bool NEGA, int BSTR>
__device__ __forceinline__ void mmk(const float* __restrict__ A,
                                    const float* __restrict__ B,
                                    float (&acc)[NI][4],
                                    int g, int tg, int mb, int nb)
{
#pragma unroll
    for (int k0 = 0; k0 < 64; k0 += 8) {
        unsigned a[4];
        if (!TRA) {
            a[0] = __float_as_uint(A[(mb + g) * TS + k0 + tg]);
            a[1] = __float_as_uint(A[(mb + g + 8) * TS + k0 + tg]);
            a[2] = __float_as_uint(A[(mb + g) * TS + k0 + tg + 4]);
            a[3] = __float_as_uint(A[(mb + g + 8) * TS + k0 + tg + 4]);
        } else {
            a[0] = __float_as_uint(A[(k0 + tg) * TS + mb + g]);
            a[1] = __float_as_uint(A[(k0 + tg) * TS + mb + g + 8]);
            a[2] = __float_as_uint(A[(k0 + tg + 4) * TS + mb + g]);
            a[3] = __float_as_uint(A[(k0 + tg + 4) * TS + mb + g + 8]);
        }
        if (NEGA) {
#pragma unroll
            for (int i = 0; i < 4; i++) a[i] ^= 0x80000000u;
        }
#pragma unroll
        for (int ni = 0; ni < NI; ni++) {
            const int n0 = nb + ni * 8;
            unsigned b0, b1;
            if (!TRB) {
                b0 = __float_as_uint(B[(k0 + tg) * BSTR + n0 + g]);
                b1 = __float_as_uint(B[(k0 + tg + 4) * BSTR + n0 + g]);
            } else {
                b0 = __float_as_uint(B[(n0 + g) * BSTR + k0 + tg]);
                b1 = __float_as_uint(B[(n0 + g) * BSTR + k0 + tg + 4]);
            }
            if (CVTB) { b0 = cvt_tf32_u(b0); b1 = cvt_tf32_u(b1); }
            asm volatile(
                "mma.sync.aligned.m16n8k8.row.col.f32.tf32.tf32.f32 "
                "{%0,%1,%2,%3}, {%4,%5,%6,%7}, {%8,%9}, {%0,%1,%2,%3};\n"
                : "+f"(acc[ni][0]), "+f"(acc[ni][1]),
                  "+f"(acc[ni][2]), "+f"(acc[ni][3])
                : "r"(a[0]), "r"(a[1]), "r"(a[2]), "r"(a[3]),
                  "r"(b0), "r"(b1));
        }
    }
}

// MASK: 0 none, 1 inclusive (keep c<=r), 2 strict (keep c<r). scl stride TS.
template<int NI, int MASK, bool SCALE, int OSTR>
__device__ __forceinline__ void store_tile(float* __restrict__ O,
    const float* __restrict__ scl, float (&acc)[NI][4],
    int g, int tg, int mb, int nb)
{
#pragma unroll
    for (int ni = 0; ni < NI; ni++) {
        const int c0 = nb + ni * 8 + 2 * tg;
#pragma unroll
        for (int hh = 0; hh < 2; hh++) {
            const int r = mb + g + 8 * hh;
#pragma unroll
            for (int e = 0; e < 2; e++) {
                const int c = c0 + e;
                float v = acc[ni][2 * hh + e];
                if (MASK == 1 && c > r)  v = 0.f;
                if (MASK == 2 && c >= r) v = 0.f;
                if (SCALE) v *= scl[r * TS + c];
                O[r * OSTR + c] = f2tf32(v);
            }
        }
    }
}

// KIND 0: S=rs[r]*rs[c]*(S+d); 1/2: S=rs[r]*(S+d)
template<int NI, int KIND, int OSTR>
__device__ __forceinline__ void update_state(float* __restrict__ St,
    const float* __restrict__ rs, float (&acc)[NI][4],
    int g, int tg, int mb, int nb)
{
#pragma unroll
    for (int ni = 0; ni < NI; ni++) {
        const int c0 = nb + ni * 8 + 2 * tg;
#pragma unroll
        for (int hh = 0; hh < 2; hh++) {
            const int r = mb + g + 8 * hh;
            const float rrs = rs[r];
#pragma unroll
            for (int e = 0; e < 2; e++) {
                const int c = c0 + e;
                float s = rrs;
                if (KIND == 0) s *= rs[c];
                St[r * OSTR + c] = s * (St[r * OSTR + c] + acc[ni][2 * hh + e]);
            }
        }
    }
}

__device__ __forceinline__ void load_tile64(float* __restrict__ dst,
    const float* __restrict__ src, int tid)
{
#pragma unroll
    for (int i = 0; i < 4; i++) {
        const int e = (tid + i * 256) * 4;
        const int r = e >> 6, c = e & 63;
        *(float4*)(dst + r * TS + c) = *(const float4*)(src + e);
    }
}

// smem: 8 TS tiles + 4 HS tiles
#define SCAN_SMEM_BYTES ((8 * TSF + 4 * HSF) * (int)sizeof(float))

__global__ __launch_bounds__(256) void scan_chunked(
    const float* __restrict__ qp, const float* __restrict__ kp,
    const float* __restrict__ vp, const float* __restrict__ aKp,
    const float* __restrict__ aCp, float* __restrict__ o2d)
{
    extern __shared__ float sm[];
    float* S   = sm;                       // TS  state S_K (full, fp32)
    float* Qh  = S   + TSF;                // TS  raw q -> q*akcum
    float* Kt  = Qh  + TSF;                // TS  raw k -> k/akcum
    float* Qt  = Kt  + TSF;                // TS  q/accum
    float* Kh  = Qt  + TSF;                // TS  k*accum
    float* SCL = Kh  + TSF;                // TS  raw aK -> akcum -> ak*ac -> Uhat
    float* P   = SCL + TSF;                // TS  raw aC -> accum -> P scores
    float* T1  = P   + TSF;                // TS  R -> Sc2
    float* Cst = T1  + TSF;                // HS  state C_QV (half)
    float* G   = Cst + HSF;                // HS  state G (half)
    float* V   = G   + HSF;                // HS  v half (tf32)
    float* T2  = V   + HSF;                // HS  KC (half)
    __shared__ float aKL[64], aCL[64];

    const int bh   = blockIdx.x >> 1;
    const int half = blockIdx.x & 1;
    const int b = bh >> 4, h = bh & 15;
    const size_t base = (size_t)bh * TSZ * DH;
    const int tid  = threadIdx.x;
    const int lane = tid & 31, w = tid >> 5;
    const int g = lane >> 2, tg = lane & 3;
    const int mb   = (w & 3) * 16;
    const int nb64 = (w >> 2) * 32;
    const int nb32 = (w >> 2) * 16;

    for (int i = tid; i < TSF; i += 256) S[i] = 0.f;
    for (int i = tid; i < HSF; i += 256) { Cst[i] = 0.f; G[i] = 0.f; }
    __syncthreads();

    for (int ch = 0; ch < NCHUNK; ch++) {
        const size_t off = base + (size_t)ch * CL * DH;
        load_tile64(Qh,  qp  + off, tid);
        load_tile64(Kt,  kp  + off, tid);
        load_tile64(SCL, aKp + off, tid);
        load_tile64(P,   aCp + off, tid);
        // V half: 64 rows x 32 cols
#pragma unroll
        for (int i = 0; i < 2; i++) {
            const int e = (tid + i * 256) * 4;
            const int r = e >> 5, c = e & 31;
            *(float4*)(V + r * HS + c) =
                *(const float4*)(vp + off + r * DH + half * 32 + c);
        }
        __syncthreads();                                     // S1 loads

        // cumulative products down rows of SCL (aK) and P (aC)
        {
            float* Tt = (tid < 128) ? SCL : P;
            const int col = tid & 63;
            const int seg = (tid >> 6) & 1;
            const int r0 = seg * 32;
            float p = 1.f;
#pragma unroll
            for (int r = 0; r < 32; r++) {
                p *= Tt[(r0 + r) * TS + col];
                Tt[(r0 + r) * TS + col] = p;
            }
            __syncthreads();                                 // S2 segment
            if (seg == 1) {
                const float p0 = Tt[31 * TS + col];
#pragma unroll
                for (int r = 32; r < 64; r++) Tt[r * TS + col] *= p0;
            }
        }
        __syncthreads();                                     // S3 fixup

        // derive (also extracts last-row gates into aKL/aCL)
#pragma unroll
        for (int i = 0; i < 16; i++) {
            const int e = tid + i * 256;
            const int r = e >> 6, c = e & 63;
            const int idx = r * TS + c;
            const float ak = SCL[idx], ac = P[idx];
            const float qv = Qh[idx],  kv = Kt[idx];
            if (r == 63) { aKL[c] = ak; aCL[c] = ac; }
            Qh[idx]  = f2tf32(qv * ak);
            Kt[idx]  = f2tf32(kv / ak);
            Qt[idx]  = f2tf32(qv / ac);
            Kh[idx]  = f2tf32(kv * ac);
            SCL[idx] = ak * ac;
        }
#pragma unroll
        for (int i = 0; i < 8; i++) {
            const int e = tid + i * 256;
            const int idx = (e >> 5) * HS + (e & 31);
            V[idx] = f2tf32(V[idx]);
        }
        __syncthreads();                                     // S4 derive

        float acc4[4][4];
        float acc2[2][4];

        // phase A: R = (Kh @ Qt^T) strict -> T1 ; P = (Qh @ Kt^T) incl -> P
        zacc(acc4);
        mmk<4, false, true, false, false, TS>(Kh, Qt, acc4, g, tg, mb, nb64);
        store_tile<4, 2, false, TS>(T1, nullptr, acc4, g, tg, mb, nb64);
        zacc(acc4);
        mmk<4, false, true, false, false, TS>(Qh, Kt, acc4, g, tg, mb, nb64);
        store_tile<4, 1, false, TS>(P, nullptr, acc4, g, tg, mb, nb64);
        __syncthreads();                                     // S5

        // phase B+C: KC = Kh@C0 + R@V -> T2 ;  Uhat = (Qh@S0 + P@Kt)*SCL -> SCL
        zacc(acc2);
        mmk<2, false, false, true,  false, HS>(Kh, Cst, acc2, g, tg, mb, nb32);
        mmk<2, false, false, false, false, HS>(T1, V,   acc2, g, tg, mb, nb32);
        store_tile<2, 0, false, HS>(T2, nullptr, acc2, g, tg, mb, nb32);
        zacc(acc4);
        mmk<4, false, false, true,  false, TS>(Qh, S,  acc4, g, tg, mb, nb64);
        mmk<4, false, false, false, false, TS>(P,  Kt, acc4, g, tg, mb, nb64);
        store_tile<4, 0, true, TS>(SCL, SCL, acc4, g, tg, mb, nb64);
        __syncthreads();                                     // S6

        // phase D: Sc2 = (Uhat @ Qt^T) incl -> T1
        zacc(acc4);
        mmk<4, false, true, false, false, TS>(SCL, Qt, acc4, g, tg, mb, nb64);
        store_tile<4, 1, false, TS>(T1, nullptr, acc4, g, tg, mb, nb64);
        __syncthreads();                                     // S7

        // phase E: O = Uhat@C0 + Sc2@V - Qh@G0 - P@KC -> gmem (half cols)
        zacc(acc2);
        mmk<2, false, false, true,  false, HS>(SCL, Cst, acc2, g, tg, mb, nb32);
        mmk<2, false, false, false, false, HS>(T1,  V,   acc2, g, tg, mb, nb32);
        mmk<2, false, false, true,  true,  HS>(Qh,  G,   acc2, g, tg, mb, nb32);
        mmk<2, false, false, false, true,  HS>(P,   T2,  acc2, g, tg, mb, nb32);
        {
            const int t0 = ch * CL;
#pragma unroll
            for (int ni = 0; ni < 2; ni++) {
                const int c0 = nb32 + ni * 8 + 2 * tg;
#pragma unroll
                for (int hh = 0; hh < 2; hh++) {
                    const int r = mb + g + 8 * hh;
                    float2 st = make_float2(acc2[ni][2 * hh], acc2[ni][2 * hh + 1]);
                    *(float2*)&o2d[(size_t)(b * TSZ + t0 + r) * 1024 +
                                   h * DH + half * 32 + c0] = st;
                }
            }
        }
        __syncthreads();                                     // S8

        // phase F: state updates
        zacc(acc4);
        mmk<4, true, false, false, false, TS>(Kt, Kt, acc4, g, tg, mb, nb64);
        update_state<4, 0, TS>(S, aKL, acc4, g, tg, mb, nb64);
        zacc(acc2);
        mmk<2, true, false, false, false, HS>(Qt, V, acc2, g, tg, mb, nb32);
        update_state<2, 1, HS>(Cst, aCL, acc2, g, tg, mb, nb32);
        zacc(acc2);
        mmk<2, true, false, false, false, HS>(Kt, T2, acc2, g, tg, mb, nb32);
        update_state<2, 2, HS>(G, aKL, acc2, g, tg, mb, nb32);
        __syncthreads();                                     // S9
    }
}

// ---------------------------------------------------------------------------
extern "C" void kernel_launch(void* const* d_in, const int* in_sizes, int n_in,
                              void* d_out, int out_size)
{
    const float* x   = (const float*)d_in[0];
    const float* Wq  = (const float*)d_in[1];
    const float* Wk  = (const float*)d_in[2];
    const float* Wv  = (const float*)d_in[3];
    const float* WgK = (const float*)d_in[4];
    const float* bgK = (const float*)d_in[5];
    const float* WgC = (const float*)d_in[6];
    const float* bgC = (const float*)d_in[7];
    const float* Wo  = (const float*)d_in[8];
    float* out = (float*)d_out;

    float* proj = nullptr;
    float* o2d  = nullptr;
    cudaGetSymbolAddress((void**)&proj, g_proj);
    cudaGetSymbolAddress((void**)&o2d,  g_o2d);
    const size_t PS = (size_t)64 * TSZ * DH;

    cudaFuncSetAttribute(gemm_tf32_big,
                         cudaFuncAttributeMaxDynamicSharedMemorySize,
                         GEMM_SMEM_BYTES);
    cudaFuncSetAttribute(scan_chunked,
                         cudaFuncAttributeMaxDynamicSharedMemorySize,
                         SCAN_SMEM_BYTES);

    dim3 blk(256);
    dim3 gridProj(GN / 256, GM / 128, 5);
    dim3 gridOut(GN / 256, GM / 128, 1);

    gemm_tf32_big<<<gridProj, blk, GEMM_SMEM_BYTES>>>(
        x, Wq, Wk, Wv, WgK, WgC, bgK, bgC, proj, 1);

    scan_chunked<<<128, 256, SCAN_SMEM_BYTES>>>(proj, proj + PS, proj + 2 * PS,
                                                proj + 3 * PS, proj + 4 * PS, o2d);

    gemm_tf32_big<<<gridOut, blk, GEMM_SMEM_BYTES>>>(
        o2d, Wo, nullptr, nullptr, nullptr, nullptr, nullptr, nullptr, out, 0);
}

// round 8
// speedup vs baseline: 2.3761x; 1.0545x over previous
#include <cuda_runtime.h>
#include <math.h>
#include <stdint.h>

#define TSZ 2048
#define HN  16
#define DH  64
#define CL  64
#define NCHUNK 32
#define TS  72
#define HS  40
#define TSF (64 * TS)
#define HSF (64 * HS)

#define GM 8192
#define GN 1024
#define GK 1024

// Scratch
__device__ float g_proj[5][(size_t)64 * TSZ * DH];   // 5 * 32 MB
__device__ float g_o2d[(size_t)GM * GN];             // 32 MB (tf32-rounded)
__device__ float g_xr[(size_t)GM * GK];              // 32 MB x, tf32-rounded
__device__ float g_wt[6][(size_t)GK * GN];           // 24 MB W, tf32-rounded

__device__ __forceinline__ float f2tf32(float f) {
    unsigned u;
    asm("cvt.rna.tf32.f32 %0, %1;" : "=r"(u) : "f"(f));
    return __uint_as_float(u);
}
__device__ __forceinline__ float4 cvt4(float4 v) {
    float4 r;
    r.x = f2tf32(v.x); r.y = f2tf32(v.y); r.z = f2tf32(v.z); r.w = f2tf32(v.w);
    return r;
}
__device__ __forceinline__ unsigned cvt_tf32_u(unsigned u) {
    asm("cvt.rna.tf32.f32 %0, %0;" : "+r"(u));
    return u;
}

// ---------------------------------------------------------------------------
// Prep: round x and the 6 weight matrices to tf32 (layouts unchanged).
// ---------------------------------------------------------------------------
__global__ __launch_bounds__(256) void round_x_kernel(
    const float* __restrict__ x, float* __restrict__ xr)
{
    size_t i = ((size_t)blockIdx.x * 256 + threadIdx.x) * 4;
    *(float4*)(xr + i) = cvt4(*(const float4*)(x + i));
}

__global__ __launch_bounds__(256) void round_w_kernel(
    const float* __restrict__ Wq, const float* __restrict__ Wk,
    const float* __restrict__ Wv, const float* __restrict__ WgK,
    const float* __restrict__ WgC, const float* __restrict__ Wo,
    float* __restrict__ wt)
{
    const int z = blockIdx.z;
    const float* W = (z == 0) ? Wq : (z == 1) ? Wk : (z == 2) ? Wv
                   : (z == 3) ? WgK : (z == 4) ? WgC : Wo;
    size_t i = ((size_t)blockIdx.x * 256 + threadIdx.x) * 4;
    *(float4*)(wt + (size_t)z * GK * GN + i) = cvt4(*(const float4*)(W + i));
}

// ---------------------------------------------------------------------------
// TF32 mma GEMM, fragment-pipelined.  CTA 128x256, ktile 32, 8 warps (2m x 4n),
// warp tile 64x64.  A and B staged via cp.async (inputs pre-rounded to tf32,
// so no cvt anywhere on the critical path).  Fragments double-buffered over kk.
// multi=1: blockIdx.z selects the 5 projection weights; permuted (b,h,t,d)
// store, sigmoid for z>=3.  multi=0: plain row-major store.
// ---------------------------------------------------------------------------
#define AST 36
#define BST 264
#define AS_EL (128 * AST)
#define BS_EL (32 * BST)
#define GEMM_SMEM_BYTES ((2 * (AS_EL + BS_EL)) * (int)sizeof(float))

__device__ __forceinline__ void gemm_fill(const float* __restrict__ A,
                                          const float* __restrict__ W,
                                          int rowBase, int colBase,
                                          int tid, float* AsD, float* BsD, int kt)
{
    const int k0 = kt * 32;
    // A: 128 rows x 32 floats = 1024 16B chunks, 4 per thread
#pragma unroll
    for (int i = 0; i < 4; i++) {
        const int id = tid + i * 256;
        const int r = id >> 3, c4 = (id & 7) * 4;
        const float* src = A + (size_t)(rowBase + r) * GK + k0 + c4;
        unsigned dst = (unsigned)__cvta_generic_to_shared(AsD + r * AST + c4);
        asm volatile("cp.async.cg.shared.global [%0], [%1], 16;" :: "r"(dst), "l"(src));
    }
    // B: 32 rows x 256 floats = 2048 chunks, 8 per thread
#pragma unroll
    for (int i = 0; i < 8; i++) {
        const int id = tid + i * 256;
        const int r = id >> 6, c4 = (id & 63) * 4;
        const float* src = W + (size_t)(k0 + r) * GN + colBase + c4;
        unsigned dst = (unsigned)__cvta_generic_to_shared(BsD + r * BST + c4);
        asm volatile("cp.async.cg.shared.global [%0], [%1], 16;" :: "r"(dst), "l"(src));
    }
    asm volatile("cp.async.commit_group;");
}

__global__ __launch_bounds__(256, 1) void gemm_mma(
    const float* __restrict__ A, const float* __restrict__ Wall,
    const float* __restrict__ b3, const float* __restrict__ b4,
    float* __restrict__ Cb, int multi)
{
    extern __shared__ float smem[];
    float* AsB = smem;
    float* BsB = smem + 2 * AS_EL;

    const int tid  = threadIdx.x;
    const int lane = tid & 31;
    const int warpId = tid >> 5;
    const int wm = warpId & 1;
    const int wn = warpId >> 1;
    const int g  = lane >> 2;
    const int tg = lane & 3;
    const int rowBase = blockIdx.y * 128;
    const int colBase = blockIdx.x * 256;

    const float* W; const float* bias; float* C; int mode;
    if (multi) {
        const int z = blockIdx.z;
        W = Wall + (size_t)z * GK * GN;
        bias = (z == 3) ? b3 : (z == 4) ? b4 : nullptr;
        C = Cb + (size_t)z * ((size_t)64 * TSZ * DH);
        mode = (z >= 3) ? 2 : 1;
    } else {
        W = Wall; bias = nullptr; C = Cb; mode = 0;
    }

    float acc[4][8][4];
#pragma unroll
    for (int i = 0; i < 4; i++)
#pragma unroll
        for (int j = 0; j < 8; j++)
#pragma unroll
            for (int e = 0; e < 4; e++) acc[i][j][e] = 0.f;

    gemm_fill(A, W, rowBase, colBase, tid, AsB, BsB, 0);

    const int KT = GK / 32;
    for (int kt = 0; kt < KT; kt++) {
        const int cur = kt & 1;
        asm volatile("cp.async.wait_group 0;");
        __syncthreads();
        if (kt + 1 < KT)
            gemm_fill(A, W, rowBase, colBase, tid,
                      AsB + (cur ^ 1) * AS_EL, BsB + (cur ^ 1) * BS_EL, kt + 1);

        const float* As = AsB + cur * AS_EL;
        const float* Bs = BsB + cur * BS_EL;

        unsigned af[2][4][4], bf[2][8][2];
        // preload kk=0 fragments
#pragma unroll
        for (int mi = 0; mi < 4; mi++) {
            const int m0 = wm * 64 + mi * 16 + g;
            af[0][mi][0] = __float_as_uint(As[m0 * AST + tg]);
            af[0][mi][1] = __float_as_uint(As[(m0 + 8) * AST + tg]);
            af[0][mi][2] = __float_as_uint(As[m0 * AST + tg + 4]);
            af[0][mi][3] = __float_as_uint(As[(m0 + 8) * AST + tg + 4]);
        }
#pragma unroll
        for (int ni = 0; ni < 8; ni++) {
            const int n0 = wn * 64 + ni * 8 + g;
            bf[0][ni][0] = __float_as_uint(Bs[tg * BST + n0]);
            bf[0][ni][1] = __float_as_uint(Bs[(tg + 4) * BST + n0]);
        }

#pragma unroll
        for (int kk = 0; kk < 4; kk++) {
            const int cb = kk & 1, nx = cb ^ 1;
            if (kk < 3) {
                const int kb = (kk + 1) * 8;
#pragma unroll
                for (int mi = 0; mi < 4; mi++) {
                    const int m0 = wm * 64 + mi * 16 + g;
                    af[nx][mi][0] = __float_as_uint(As[m0 * AST + kb + tg]);
                    af[nx][mi][1] = __float_as_uint(As[(m0 + 8) * AST + kb + tg]);
                    af[nx][mi][2] = __float_as_uint(As[m0 * AST + kb + tg + 4]);
                    af[nx][mi][3] = __float_as_uint(As[(m0 + 8) * AST + kb + tg + 4]);
                }
#pragma unroll
                for (int ni = 0; ni < 8; ni++) {
                    const int n0 = wn * 64 + ni * 8 + g;
                    bf[nx][ni][0] = __float_as_uint(Bs[(kb + tg) * BST + n0]);
                    bf[nx][ni][1] = __float_as_uint(Bs[(kb + tg + 4) * BST + n0]);
                }
            }
#pragma unroll
            for (int ni = 0; ni < 8; ni++)
#pragma unroll
                for (int mi = 0; mi < 4; mi++) {
                    asm volatile(
                        "mma.sync.aligned.m16n8k8.row.col.f32.tf32.tf32.f32 "
                        "{%0,%1,%2,%3}, {%4,%5,%6,%7}, {%8,%9}, {%0,%1,%2,%3};\n"
                        : "+f"(acc[mi][ni][0]), "+f"(acc[mi][ni][1]),
                          "+f"(acc[mi][ni][2]), "+f"(acc[mi][ni][3])
                        : "r"(af[cb][mi][0]), "r"(af[cb][mi][1]),
                          "r"(af[cb][mi][2]), "r"(af[cb][mi][3]),
                          "r"(bf[cb][ni][0]), "r"(bf[cb][ni][1]));
                }
        }
    }

#pragma unroll
    for (int mi = 0; mi < 4; mi++) {
        const int gr0 = rowBase + wm * 64 + mi * 16 + g;
#pragma unroll
        for (int ni = 0; ni < 8; ni++) {
            const int gc = colBase + wn * 64 + ni * 8 + 2 * tg;
#pragma unroll
            for (int half = 0; half < 2; half++) {
                const int gr = gr0 + 8 * half;
                float v0 = acc[mi][ni][2 * half];
                float v1 = acc[mi][ni][2 * half + 1];
                if (mode == 0) {
                    *(float2*)&C[(size_t)gr * GN + gc] = make_float2(v0, v1);
                } else {
                    if (mode == 2) {
                        v0 = 1.f / (1.f + __expf(-(v0 + bias[gc])));
                        v1 = 1.f / (1.f + __expf(-(v1 + bias[gc + 1])));
                    }
                    const int b = gr >> 11, t = gr & 2047;
                    const int h = gc >> 6,  d = gc & 63;
                    *(float2*)&C[((size_t)((b * HN + h) * TSZ + t)) * DH + d] =
                        make_float2(v0, v1);
                }
            }
        }
    }
}

// ---------------------------------------------------------------------------
// Chunked scan, dv-split (round-6 version; o2d stored tf32-rounded).
// ---------------------------------------------------------------------------
template<int NI>
__device__ __forceinline__ void zacc(float (&acc)[NI][4]) {
#pragma unroll
    for (int i = 0; i < NI; i++)
#pragma unroll
        for (int j = 0; j < 4; j++) acc[i][j] = 0.f;
}

template<int NI, bool TRA, bool TRB, bool CVTB, bool NEGA, int BSTR>
__device__ __forceinline__ void mmk(const float* __restrict__ A,
                                    const float* __restrict__ B,
                                    float (&acc)[NI][4],
                                    int g, int tg, int mb, int nb)
{
#pragma unroll
    for (int k0 = 0; k0 < 64; k0 += 8) {
        unsigned a[4];
        if (!TRA) {
            a[0] = __float_as_uint(A[(mb + g) * TS + k0 + tg]);
            a[1] = __float_as_uint(A[(mb + g + 8) * TS + k0 + tg]);
            a[2] = __float_as_uint(A[(mb + g) * TS + k0 + tg + 4]);
            a[3] = __float_as_uint(A[(mb + g + 8) * TS + k0 + tg + 4]);
        } else {
            a[0] = __float_as_uint(A[(k0 + tg) * TS + mb + g]);
            a[1] = __float_as_uint(A[(k0 + tg) * TS + mb + g + 8]);
            a[2] = __float_as_uint(A[(k0 + tg + 4) * TS + mb + g]);
            a[3] = __float_as_uint(A[(k0 + tg + 4) * TS + mb + g + 8]);
        }
        if (NEGA) {
#pragma unroll
            for (int i = 0; i < 4; i++) a[i] ^= 0x80000000u;
        }
#pragma unroll
        for (int ni = 0; ni < NI; ni++) {
            const int n0 = nb + ni * 8;
            unsigned b0, b1;
            if (!TRB) {
                b0 = __float_as_uint(B[(k0 + tg) * BSTR + n0 + g]);
                b1 = __float_as_uint(B[(k0 + tg + 4) * BSTR + n0 + g]);
            } else {
                b0 = __float_as_uint(B[(n0 + g) * BSTR + k0 + tg]);
                b1 = __float_as_uint(B[(n0 + g) * BSTR + k0 + tg + 4]);
            }
            if (CVTB) { b0 = cvt_tf32_u(b0); b1 = cvt_tf32_u(b1); }
            asm volatile(
                "mma.sync.aligned.m16n8k8.row.col.f32.tf32.tf32.f32 "
                "{%0,%1,%2,%3}, {%4,%5,%6,%7}, {%8,%9}, {%0,%1,%2,%3};\n"
                : "+f"(acc[ni][0]), "+f"(acc[ni][1]),
                  "+f"(acc[ni][2]), "+f"(acc[ni][3])
                : "r"(a[0]), "r"(a[1]), "r"(a[2]), "r"(a[3]),
                  "r"(b0), "r"(b1));
        }
    }
}

template<int NI, int MASK, bool SCALE, int OSTR>
__device__ __forceinline__ void store_tile(float* __restrict__ O,
    const float* __restrict__ scl, float (&acc)[NI][4],
    int g, int tg, int mb, int nb)
{
#pragma unroll
    for (int ni = 0; ni < NI; ni++) {
        const int c0 = nb + ni * 8 + 2 * tg;
#pragma unroll
        for (int hh = 0; hh < 2; hh++) {
            const int r = mb + g + 8 * hh;
#pragma unroll
            for (int e = 0; e < 2; e++) {
                const int c = c0 + e;
                float v = acc[ni][2 * hh + e];
                if (MASK == 1 && c > r)  v = 0.f;
                if (MASK == 2 && c >= r) v = 0.f;
                if (SCALE) v *= scl[r * TS + c];
                O[r * OSTR + c] = f2tf32(v);
            }
        }
    }
}

template<int NI, int KIND, int OSTR>
__device__ __forceinline__ void update_state(float* __restrict__ St,
    const float* __restrict__ rs, float (&acc)[NI][4],
    int g, int tg, int mb, int nb)
{
#pragma unroll
    for (int ni = 0; ni < NI; ni++) {
        const int c0 = nb + ni * 8 + 2 * tg;
#pragma unroll
        for (int hh = 0; hh < 2; hh++) {
            const int r = mb + g + 8 * hh;
            const float rrs = rs[r];
#pragma unroll
            for (int e = 0; e < 2; e++) {
                const int c = c0 + e;
                float s = rrs;
                if (KIND == 0) s *= rs[c];
                St[r * OSTR + c] = s * (St[r * OSTR + c] + acc[ni][2 * hh + e]);
            }
        }
    }
}

__device__ __forceinline__ void load_tile64(float* __restrict__ dst,
    const float* __restrict__ src, int tid)
{
#pragma unroll
    for (int i = 0; i < 4; i++) {
        const int e = (tid + i * 256) * 4;
        const int r = e >> 6, c = e & 63;
        *(float4*)(dst + r * TS + c) = *(const float4*)(src + e);
    }
}

#define SCAN_SMEM_BYTES ((8 * TSF + 4 * HSF) * (int)sizeof(float))

__global__ __launch_bounds__(256) void scan_chunked(
    const float* __restrict__ qp, const float* __restrict__ kp,
    const float* __restrict__ vp, const float* __restrict__ aKp,
    const float* __restrict__ aCp, float* __restrict__ o2d)
{
    extern __shared__ float sm[];
    float* S   = sm;
    float* Qh  = S   + TSF;
    float* Kt  = Qh  + TSF;
    float* Qt  = Kt  + TSF;
    float* Kh  = Qt  + TSF;
    float* SCL = Kh  + TSF;
    float* P   = SCL + TSF;
    float* T1  = P   + TSF;
    float* Cst = T1  + TSF;
    float* G   = Cst + HSF;
    float* V   = G   + HSF;
    float* T2  = V   + HSF;
    __shared__ float aKL[64], aCL[64];

    const int bh   = blockIdx.x >> 1;
    const int half = blockIdx.x & 1;
    const int b = bh >> 4, h = bh & 15;
    const size_t base = (size_t)bh * TSZ * DH;
    const int tid  = threadIdx.x;
    const int lane = tid & 31, w = tid >> 5;
    const int g = lane >> 2, tg = lane & 3;
    const int mb   = (w & 3) * 16;
    const int nb64 = (w >> 2) * 32;
    const int nb32 = (w >> 2) * 16;

    for (int i = tid; i < TSF; i += 256) S[i] = 0.f;
    for (int i = tid; i < HSF; i += 256) { Cst[i] = 0.f; G[i] = 0.f; }
    __syncthreads();

    for (int ch = 0; ch < NCHUNK; ch++) {
        const size_t off = base + (size_t)ch * CL * DH;
        load_tile64(Qh,  qp  + off, tid);
        load_tile64(Kt,  kp  + off, tid);
        load_tile64(SCL, aKp + off, tid);
        load_tile64(P,   aCp + off, tid);
#pragma unroll
        for (int i = 0; i < 2; i++) {
            const int e = (tid + i * 256) * 4;
            const int r = e >> 5, c = e & 31;
            *(float4*)(V + r * HS + c) =
                *(const float4*)(vp + off + r * DH + half * 32 + c);
        }
        __syncthreads();

        {
            float* Tt = (tid < 128) ? SCL : P;
            const int col = tid & 63;
            const int seg = (tid >> 6) & 1;
            const int r0 = seg * 32;
            float p = 1.f;
#pragma unroll
            for (int r = 0; r < 32; r++) {
                p *= Tt[(r0 + r) * TS + col];
                Tt[(r0 + r) * TS + col] = p;
            }
            __syncthreads();
            if (seg == 1) {
                const float p0 = Tt[31 * TS + col];
#pragma unroll
                for (int r = 32; r < 64; r++) Tt[r * TS + col] *= p0;
            }
        }
        __syncthreads();

#pragma unroll
        for (int i = 0; i < 16; i++) {
            const int e = tid + i * 256;
            const int r = e >> 6, c = e & 63;
            const int idx = r * TS + c;
            const float ak = SCL[idx], ac = P[idx];
            const float qv = Qh[idx],  kv = Kt[idx];
            if (r == 63) { aKL[c] = ak; aCL[c] = ac; }
            Qh[idx]  = f2tf32(qv * ak);
            Kt[idx]  = f2tf32(kv / ak);
            Qt[idx]  = f2tf32(qv / ac);
            Kh[idx]  = f2tf32(kv * ac);
            SCL[idx] = ak * ac;
        }
#pragma unroll
        for (int i = 0; i < 8; i++) {
            const int e = tid + i * 256;
            const int idx = (e >> 5) * HS + (e & 31);
            V[idx] = f2tf32(V[idx]);
        }
        __syncthreads();

        float acc4[4][4];
        float acc2[2][4];

        zacc(acc4);
        mmk<4, false, true, false, false, TS>(Kh, Qt, acc4, g, tg, mb, nb64);
        store_tile<4, 2, false, TS>(T1, nullptr, acc4, g, tg, mb, nb64);
        zacc(acc4);
        mmk<4, false, true, false, false, TS>(Qh, Kt, acc4, g, tg, mb, nb64);
        store_tile<4, 1, false, TS>(P, nullptr, acc4, g, tg, mb, nb64);
        __syncthreads();

        zacc(acc2);
        mmk<2, false, false, true,  false, HS>(Kh, Cst, acc2, g, tg, mb, nb32);
        mmk<2, false, false, false, false, HS>(T1, V,   acc2, g, tg, mb, nb32);
        store_tile<2, 0, false, HS>(T2, nullptr, acc2, g, tg, mb, nb32);
        zacc(acc4);
        mmk<4, false, false, true,  false, TS>(Qh, S,  acc4, g, tg, mb, nb64);
        mmk<4, false, false, false, false, TS>(P,  Kt, acc4, g, tg, mb, nb64);
        store_tile<4, 0, true, TS>(SCL, SCL, acc4, g, tg, mb, nb64);
        __syncthreads();

        zacc(acc4);
        mmk<4, false, true, false, false, TS>(SCL, Qt, acc4, g, tg, mb, nb64);
        store_tile<4, 1, false, TS>(T1, nullptr, acc4, g, tg, mb, nb64);
        __syncthreads();

        zacc(acc2);
        mmk<2, false, false, true,  false, HS>(SCL, Cst, acc2, g, tg, mb, nb32);
        mmk<2, false, false, false, false, HS>(T1,  V,   acc2, g, tg, mb, nb32);
        mmk<2, false, false, true,  true,  HS>(Qh,  G,   acc2, g, tg, mb, nb32);
        mmk<2, false, false, false, true,  HS>(P,   T2,  acc2, g, tg, mb, nb32);
        {
            const int t0 = ch * CL;
#pragma unroll
            for (int ni = 0; ni < 2; ni++) {
                const int c0 = nb32 + ni * 8 + 2 * tg;
#pragma unroll
                for (int hh = 0; hh < 2; hh++) {
                    const int r = mb + g + 8 * hh;
                    float2 st = make_float2(f2tf32(acc2[ni][2 * hh]),
                                            f2tf32(acc2[ni][2 * hh + 1]));
                    *(float2*)&o2d[(size_t)(b * TSZ + t0 + r) * 1024 +
                                   h * DH + half * 32 + c0] = st;
                }
            }
        }
        __syncthreads();

        zacc(acc4);
        mmk<4, true, false, false, false, TS>(Kt, Kt, acc4, g, tg, mb, nb64);
        update_state<4, 0, TS>(S, aKL, acc4, g, tg, mb, nb64);
        zacc(acc2);
        mmk<2, true, false, false, false, HS>(Qt, V, acc2, g, tg, mb, nb32);
        update_state<2, 1, HS>(Cst, aCL, acc2, g, tg, mb, nb32);
        zacc(acc2);
        mmk<2, true, false, false, false, HS>(Kt, T2, acc2, g, tg, mb, nb32);
        update_state<2, 2, HS>(G, aKL, acc2, g, tg, mb, nb32);
        __syncthreads();
    }
}

// ---------------------------------------------------------------------------
extern "C" void kernel_launch(void* const* d_in, const int* in_sizes, int n_in,
                              void* d_out, int out_size)
{
    const float* x   = (const float*)d_in[0];
    const float* Wq  = (const float*)d_in[1];
    const float* Wk  = (const float*)d_in[2];
    const float* Wv  = (const float*)d_in[3];
    const float* WgK = (const float*)d_in[4];
    const float* bgK = (const float*)d_in[5];
    const float* WgC = (const float*)d_in[6];
    const float* bgC = (const float*)d_in[7];
    const float* Wo  = (const float*)d_in[8];
    float* out = (float*)d_out;

    float *proj = nullptr, *o2d = nullptr, *xr = nullptr, *wt = nullptr;
    cudaGetSymbolAddress((void**)&proj, g_proj);
    cudaGetSymbolAddress((void**)&o2d,  g_o2d);
    cudaGetSymbolAddress((void**)&xr,   g_xr);
    cudaGetSymbolAddress((void**)&wt,   g_wt);
    const size_t PS = (size_t)64 * TSZ * DH;

    cudaFuncSetAttribute(gemm_mma,
                         cudaFuncAttributeMaxDynamicSharedMemorySize,
                         GEMM_SMEM_BYTES);
    cudaFuncSetAttribute(scan_chunked,
                         cudaFuncAttributeMaxDynamicSharedMemorySize,
                         SCAN_SMEM_BYTES);

    round_x_kernel<<<(GM * GK) / 1024, 256>>>(x, xr);
    round_w_kernel<<<dim3((GK * GN) / 1024, 1, 6), 256>>>(
        Wq, Wk, Wv, WgK, WgC, Wo, wt);

    gemm_mma<<<dim3(GN / 256, GM / 128, 5), 256, GEMM_SMEM_BYTES>>>(
        xr, wt, bgK, bgC, proj, 1);

    scan_chunked<<<128, 256, SCAN_SMEM_BYTES>>>(proj, proj + PS, proj + 2 * PS,
                                                proj + 3 * PS, proj + 4 * PS, o2d);

    gemm_mma<<<dim3(GN / 256, GM / 128, 1), 256, GEMM_SMEM_BYTES>>>(
        o2d, wt + (size_t)5 * GK * GN, nullptr, nullptr, out, 0);
}

// round 9
// speedup vs baseline: 3.1124x; 1.3099x over previous
#include <cuda_runtime.h>
#include <cuda_fp16.h>
#include <math.h>
#include <stdint.h>

#define TSZ 2048
#define HN  16
#define DH  64
#define CL  64
#define NCHUNK 32
#define TS  72
#define HS  40
#define TSF (64 * TS)
#define HSF (64 * HS)

#define GM 8192
#define GN 1024
#define GK 1024

// Scratch
__device__ float  g_proj[5][(size_t)64 * TSZ * DH];   // 5 * 32 MB
__device__ __half g_o2dh[(size_t)GM * GN];            // 16 MB
__device__ __half g_xh[(size_t)GM * GK];              // 16 MB
__device__ __half g_wth[6][(size_t)GN * GK];          // 12 MB  W^T [z][n][k]

__device__ __forceinline__ float f2tf32(float f) {
    unsigned u;
    asm("cvt.rna.tf32.f32 %0, %1;" : "=r"(u) : "f"(f));
    return __uint_as_float(u);
}
__device__ __forceinline__ unsigned cvt_tf32_u(unsigned u) {
    asm("cvt.rna.tf32.f32 %0, %0;" : "+r"(u));
    return u;
}

// ---------------------------------------------------------------------------
// Prep: fp16(x) and fp16(W^T).
// ---------------------------------------------------------------------------
__global__ __launch_bounds__(256) void half_x_kernel(
    const float* __restrict__ x, __half* __restrict__ xh)
{
    size_t i = ((size_t)blockIdx.x * 256 + threadIdx.x) * 8;
    float4 v0 = *(const float4*)(x + i);
    float4 v1 = *(const float4*)(x + i + 4);
    __half2 h[4];
    h[0] = __floats2half2_rn(v0.x, v0.y);
    h[1] = __floats2half2_rn(v0.z, v0.w);
    h[2] = __floats2half2_rn(v1.x, v1.y);
    h[3] = __floats2half2_rn(v1.z, v1.w);
    *(uint4*)(xh + i) = *(uint4*)h;
}

__global__ __launch_bounds__(256) void half_wt_kernel(
    const float* __restrict__ Wq, const float* __restrict__ Wk,
    const float* __restrict__ Wv, const float* __restrict__ WgK,
    const float* __restrict__ WgC, const float* __restrict__ Wo,
    __half* __restrict__ wth)
{
    __shared__ float tile[32][33];
    const int z = blockIdx.z;
    const float* W = (z == 0) ? Wq : (z == 1) ? Wk : (z == 2) ? Wv
                   : (z == 3) ? WgK : (z == 4) ? WgC : Wo;
    const int n0 = blockIdx.x * 32, k0 = blockIdx.y * 32;
    const int tx = threadIdx.x & 31, ty = threadIdx.x >> 5;  // 32 x 8
#pragma unroll
    for (int i = 0; i < 4; i++)
        tile[ty + i * 8][tx] = W[(size_t)(k0 + ty + i * 8) * GN + n0 + tx];
    __syncthreads();
    __half* dst = wth + (size_t)z * GN * GK;
#pragma unroll
    for (int i = 0; i < 4; i++)
        dst[(size_t)(n0 + ty + i * 8) * GK + k0 + tx] =
            __float2half_rn(tile[tx][ty + i * 8]);
}

// ---------------------------------------------------------------------------
// FP16 mma GEMM (m16n8k16, fp32 accum).  CTA 128x256, ktile 64 halves,
// 8 warps (2m x 4n), warp tile 64x64.  A [m][k] and B=W^T [n][k] in smem via
// cp.async (double buffered); fragments double-buffered over the 4 k16 steps.
// multi=1: blockIdx.z selects projection; permuted (b,h,t,d) store, sigmoid
// for z>=3.  multi=0: plain row-major store.
// ---------------------------------------------------------------------------
#define AST2 72                        // halves
#define BST2 72
#define AS2_EL (128 * AST2)            // halves
#define BS2_EL (256 * BST2)
#define GEMM2_SMEM ((2 * (AS2_EL + BS2_EL)) * (int)sizeof(__half))  // 110592 B

__device__ __forceinline__ void gemm2_fill(const __half* __restrict__ A,
                                           const __half* __restrict__ BT,
                                           int rowBase, int colBase, int tid,
                                           __half* AsD, __half* BsD, int kt)
{
    const int k0 = kt * 64;
    // A: 128 rows x 8 x 16B chunks = 1024, 4/thread
#pragma unroll
    for (int i = 0; i < 4; i++) {
        const int id = tid + i * 256;
        const int r = id >> 3, c = (id & 7) * 8;          // halves
        const __half* src = A + (size_t)(rowBase + r) * GK + k0 + c;
        unsigned dst = (unsigned)__cvta_generic_to_shared(AsD + r * AST2 + c);
        asm volatile("cp.async.cg.shared.global [%0], [%1], 16;" :: "r"(dst), "l"(src));
    }
    // B: 256 rows x 8 chunks = 2048, 8/thread
#pragma unroll
    for (int i = 0; i < 8; i++) {
        const int id = tid + i * 256;
        const int r = id >> 3, c = (id & 7) * 8;
        const __half* src = BT + (size_t)(colBase + r) * GK + k0 + c;
        unsigned dst = (unsigned)__cvta_generic_to_shared(BsD + r * BST2 + c);
        asm volatile("cp.async.cg.shared.global [%0], [%1], 16;" :: "r"(dst), "l"(src));
    }
    asm volatile("cp.async.commit_group;");
}

__global__ __launch_bounds__(256, 1) void gemm_fp16(
    const __half* __restrict__ A, const __half* __restrict__ WTall,
    const float* __restrict__ b3, const float* __restrict__ b4,
    float* __restrict__ Cb, int multi)
{
    extern __shared__ __half smem[];
    __half* AsB = smem;
    __half* BsB = smem + 2 * AS2_EL;

    const int tid  = threadIdx.x;
    const int lane = tid & 31;
    const int warpId = tid >> 5;
    const int wm = warpId & 1;
    const int wn = warpId >> 1;
    const int g  = lane >> 2;
    const int tg = lane & 3;
    const int rowBase = blockIdx.y * 128;
    const int colBase = blockIdx.x * 256;

    const __half* BT; const float* bias; float* C; int mode;
    if (multi) {
        const int z = blockIdx.z;
        BT = WTall + (size_t)z * GN * GK;
        bias = (z == 3) ? b3 : (z == 4) ? b4 : nullptr;
        C = Cb + (size_t)z * ((size_t)64 * TSZ * DH);
        mode = (z >= 3) ? 2 : 1;
    } else {
        BT = WTall; bias = nullptr; C = Cb; mode = 0;
    }

    float acc[4][8][4];
#pragma unroll
    for (int i = 0; i < 4; i++)
#pragma unroll
        for (int j = 0; j < 8; j++)
#pragma unroll
            for (int e = 0; e < 4; e++) acc[i][j][e] = 0.f;

    gemm2_fill(A, BT, rowBase, colBase, tid, AsB, BsB, 0);

    const int KT = GK / 64;
    for (int kt = 0; kt < KT; kt++) {
        const int cur = kt & 1;
        asm volatile("cp.async.wait_group 0;");
        __syncthreads();
        if (kt + 1 < KT)
            gemm2_fill(A, BT, rowBase, colBase, tid,
                       AsB + (cur ^ 1) * AS2_EL, BsB + (cur ^ 1) * BS2_EL, kt + 1);

        const __half* As = AsB + cur * AS2_EL;
        const __half* Bs = BsB + cur * BS2_EL;

        unsigned af[2][4][4], bf[2][8][2];
        // preload k-step 0 fragments
#pragma unroll
        for (int mi = 0; mi < 4; mi++) {
            const int m0 = wm * 64 + mi * 16 + g;
            af[0][mi][0] = *(const unsigned*)&As[m0 * AST2 + 2 * tg];
            af[0][mi][1] = *(const unsigned*)&As[(m0 + 8) * AST2 + 2 * tg];
            af[0][mi][2] = *(const unsigned*)&As[m0 * AST2 + 2 * tg + 8];
            af[0][mi][3] = *(const unsigned*)&As[(m0 + 8) * AST2 + 2 * tg + 8];
        }
#pragma unroll
        for (int ni = 0; ni < 8; ni++) {
            const int n0 = wn * 64 + ni * 8 + g;
            bf[0][ni][0] = *(const unsigned*)&Bs[n0 * BST2 + 2 * tg];
            bf[0][ni][1] = *(const unsigned*)&Bs[n0 * BST2 + 2 * tg + 8];
        }

#pragma unroll
        for (int kk = 0; kk < 4; kk++) {          // 4 x k16
            const int cb = kk & 1, nx = cb ^ 1;
            if (kk < 3) {
                const int kb = (kk + 1) * 16;
#pragma unroll
                for (int mi = 0; mi < 4; mi++) {
                    const int m0 = wm * 64 + mi * 16 + g;
                    af[nx][mi][0] = *(const unsigned*)&As[m0 * AST2 + kb + 2 * tg];
                    af[nx][mi][1] = *(const unsigned*)&As[(m0 + 8) * AST2 + kb + 2 * tg];
                    af[nx][mi][2] = *(const unsigned*)&As[m0 * AST2 + kb + 2 * tg + 8];
                    af[nx][mi][3] = *(const unsigned*)&As[(m0 + 8) * AST2 + kb + 2 * tg + 8];
                }
#pragma unroll
                for (int ni = 0; ni < 8; ni++) {
                    const int n0 = wn * 64 + ni * 8 + g;
                    bf[nx][ni][0] = *(const unsigned*)&Bs[n0 * BST2 + kb + 2 * tg];
                    bf[nx][ni][1] = *(const unsigned*)&Bs[n0 * BST2 + kb + 2 * tg + 8];
                }
            }
#pragma unroll
            for (int ni = 0; ni < 8; ni++)
#pragma unroll
                for (int mi = 0; mi < 4; mi++) {
                    asm volatile(
                        "mma.sync.aligned.m16n8k16.row.col.f32.f16.f16.f32 "
                        "{%0,%1,%2,%3}, {%4,%5,%6,%7}, {%8,%9}, {%0,%1,%2,%3};\n"
                        : "+f"(acc[mi][ni][0]), "+f"(acc[mi][ni][1]),
                          "+f"(acc[mi][ni][2]), "+f"(acc[mi][ni][3])
                        : "r"(af[cb][mi][0]), "r"(af[cb][mi][1]),
                          "r"(af[cb][mi][2]), "r"(af[cb][mi][3]),
                          "r"(bf[cb][ni][0]), "r"(bf[cb][ni][1]));
                }
        }
    }

#pragma unroll
    for (int mi = 0; mi < 4; mi++) {
        const int gr0 = rowBase + wm * 64 + mi * 16 + g;
#pragma unroll
        for (int ni = 0; ni < 8; ni++) {
            const int gc = colBase + wn * 64 + ni * 8 + 2 * tg;
#pragma unroll
            for (int half = 0; half < 2; half++) {
                const int gr = gr0 + 8 * half;
                float v0 = acc[mi][ni][2 * half];
                float v1 = acc[mi][ni][2 * half + 1];
                if (mode == 0) {
                    *(float2*)&C[(size_t)gr * GN + gc] = make_float2(v0, v1);
                } else {
                    if (mode == 2) {
                        v0 = 1.f / (1.f + __expf(-(v0 + bias[gc])));
                        v1 = 1.f / (1.f + __expf(-(v1 + bias[gc + 1])));
                    }
                    const int b = gr >> 11, t = gr & 2047;
                    const int h = gc >> 6,  d = gc & 63;
                    *(float2*)&C[((size_t)((b * HN + h) * TSZ + t)) * DH + d] =
                        make_float2(v0, v1);
                }
            }
        }
    }
}

// ---------------------------------------------------------------------------
// Chunked scan, dv-split (round-6 winner; o2d now stored fp16).
// ---------------------------------------------------------------------------
template<int NI>
__device__ __forceinline__ void zacc(float (&acc)[NI][4]) {
#pragma unroll
    for (int i = 0; i < NI; i++)
#pragma unroll
        for (int j = 0; j < 4; j++) acc[i][j] = 0.f;
}

template<int NI, bool TRA, bool TRB, bool CVTB, bool NEGA, int BSTR>
__device__ __forceinline__ void mmk(const float* __restrict__ A,
                                    const float* __restrict__ B,
                                    float (&acc)[NI][4],
                                    int g, int tg, int mb, int nb)
{
#pragma unroll
    for (int k0 = 0; k0 < 64; k0 += 8) {
        unsigned a[4];
        if (!TRA) {
            a[0] = __float_as_uint(A[(mb + g) * TS + k0 + tg]);
            a[1] = __float_as_uint(A[(mb + g + 8) * TS + k0 + tg]);
            a[2] = __float_as_uint(A[(mb + g) * TS + k0 + tg + 4]);
            a[3] = __float_as_uint(A[(mb + g + 8) * TS + k0 + tg + 4]);
        } else {
            a[0] = __float_as_uint(A[(k0 + tg) * TS + mb + g]);
            a[1] = __float_as_uint(A[(k0 + tg) * TS + mb + g + 8]);
            a[2] = __float_as_uint(A[(k0 + tg + 4) * TS + mb + g]);
            a[3] = __float_as_uint(A[(k0 + tg + 4) * TS + mb + g + 8]);
        }
        if (NEGA) {
#pragma unroll
            for (int i = 0; i < 4; i++) a[i] ^= 0x80000000u;
        }
#pragma unroll
        for (int ni = 0; ni < NI; ni++) {
            const int n0 = nb + ni * 8;
            unsigned b0, b1;
            if (!TRB) {
                b0 = __float_as_uint(B[(k0 + tg) * BSTR + n0 + g]);
                b1 = __float_as_uint(B[(k0 + tg + 4) * BSTR + n0 + g]);
            } else {
                b0 = __float_as_uint(B[(n0 + g) * BSTR + k0 + tg]);
                b1 = __float_as_uint(B[(n0 + g) * BSTR + k0 + tg + 4]);
            }
            if (CVTB) { b0 = cvt_tf32_u(b0); b1 = cvt_tf32_u(b1); }
            asm volatile(
                "mma.sync.aligned.m16n8k8.row.col.f32.tf32.tf32.f32 "
                "{%0,%1,%2,%3}, {%4,%5,%6,%7}, {%8,%9}, {%0,%1,%2,%3};\n"
                : "+f"(acc[ni][0]), "+f"(acc[ni][1]),
                  "+f"(acc[ni][2]), "+f"(acc[ni][3])
                : "r"(a[0]), "r"(a[1]), "r"(a[2]), "r"(a[3]),
                  "r"(b0), "r"(b1));
        }
    }
}

template<int NI, int MASK, bool SCALE, int OSTR>
__device__ __forceinline__ void store_tile(float* __restrict__ O,
    const float* __restrict__ scl, float (&acc)[NI][4],
    int g, int tg, int mb, int nb)
{
#pragma unroll
    for (int ni = 0; ni < NI; ni++) {
        const int c0 = nb + ni * 8 + 2 * tg;
#pragma unroll
        for (int hh = 0; hh < 2; hh++) {
            const int r = mb + g + 8 * hh;
#pragma unroll
            for (int e = 0; e < 2; e++) {
                const int c = c0 + e;
                float v = acc[ni][2 * hh + e];
                if (MASK == 1 && c > r)  v = 0.f;
                if (MASK == 2 && c >= r) v = 0.f;
                if (SCALE) v *= scl[r * TS + c];
                O[r * OSTR + c] = f2tf32(v);
            }
        }
    }
}

template<int NI, int KIND, int OSTR>
__device__ __forceinline__ void update_state(float* __restrict__ St,
    const float* __restrict__ rs, float (&acc)[NI][4],
    int g, int tg, int mb, int nb)
{
#pragma unroll
    for (int ni = 0; ni < NI; ni++) {
        const int c0 = nb + ni * 8 + 2 * tg;
#pragma unroll
        for (int hh = 0; hh < 2; hh++) {
            const int r = mb + g + 8 * hh;
            const float rrs = rs[r];
#pragma unroll
            for (int e = 0; e < 2; e++) {
                const int c = c0 + e;
                float s = rrs;
                if (KIND == 0) s *= rs[c];
                St[r * OSTR + c] = s * (St[r * OSTR + c] + acc[ni][2 * hh + e]);
            }
        }
    }
}

__device__ __forceinline__ void load_tile64(float* __restrict__ dst,
    const float* __restrict__ src, int tid)
{
#pragma unroll
    for (int i = 0; i < 4; i++) {
        const int e = (tid + i * 256) * 4;
        const int r = e >> 6, c = e & 63;
        *(float4*)(dst + r * TS + c) = *(const float4*)(src + e);
    }
}

#define SCAN_SMEM_BYTES ((8 * TSF + 4 * HSF) * (int)sizeof(float))

__global__ __launch_bounds__(256) void scan_chunked(
    const float* __restrict__ qp, const float* __restrict__ kp,
    const float* __restrict__ vp, const float* __restrict__ aKp,
    const float* __restrict__ aCp, __half* __restrict__ o2dh)
{
    extern __shared__ float sm[];
    float* S   = sm;
    float* Qh  = S   + TSF;
    float* Kt  = Qh  + TSF;
    float* Qt  = Kt  + TSF;
    float* Kh  = Qt  + TSF;
    float* SCL = Kh  + TSF;
    float* P   = SCL + TSF;
    float* T1  = P   + TSF;
    float* Cst = T1  + TSF;
    float* G   = Cst + HSF;
    float* V   = G   + HSF;
    float* T2  = V   + HSF;
    __shared__ float aKL[64], aCL[64];

    const int bh   = blockIdx.x >> 1;
    const int half = blockIdx.x & 1;
    const int b = bh >> 4, h = bh & 15;
    const size_t base = (size_t)bh * TSZ * DH;
    const int tid  = threadIdx.x;
    const int lane = tid & 31, w = tid >> 5;
    const int g = lane >> 2, tg = lane & 3;
    const int mb   = (w & 3) * 16;
    const int nb64 = (w >> 2) * 32;
    const int nb32 = (w >> 2) * 16;

    for (int i = tid; i < TSF; i += 256) S[i] = 0.f;
    for (int i = tid; i < HSF; i += 256) { Cst[i] = 0.f; G[i] = 0.f; }
    __syncthreads();

    for (int ch = 0; ch < NCHUNK; ch++) {
        const size_t off = base + (size_t)ch * CL * DH;
        load_tile64(Qh,  qp  + off, tid);
        load_tile64(Kt,  kp  + off, tid);
        load_tile64(SCL, aKp + off, tid);
        load_tile64(P,   aCp + off, tid);
#pragma unroll
        for (int i = 0; i < 2; i++) {
            const int e = (tid + i * 256) * 4;
            const int r = e >> 5, c = e & 31;
            *(float4*)(V + r * HS + c) =
                *(const float4*)(vp + off + r * DH + half * 32 + c);
        }
        __syncthreads();

        {
            float* Tt = (tid < 128) ? SCL : P;
            const int col = tid & 63;
            const int seg = (tid >> 6) & 1;
            const int r0 = seg * 32;
            float p = 1.f;
#pragma unroll
            for (int r = 0; r < 32; r++) {
                p *= Tt[(r0 + r) * TS + col];
                Tt[(r0 + r) * TS + col] = p;
            }
            __syncthreads();
            if (seg == 1) {
                const float p0 = Tt[31 * TS + col];
#pragma unroll
                for (int r = 32; r < 64; r++) Tt[r * TS + col] *= p0;
            }
        }
        __syncthreads();

#pragma unroll
        for (int i = 0; i < 16; i++) {
            const int e = tid + i * 256;
            const int r = e >> 6, c = e & 63;
            const int idx = r * TS + c;
            const float ak = SCL[idx], ac = P[idx];
            const float qv = Qh[idx],  kv = Kt[idx];
            if (r == 63) { aKL[c] = ak; aCL[c] = ac; }
            Qh[idx]  = f2tf32(qv * ak);
            Kt[idx]  = f2tf32(kv / ak);
            Qt[idx]  = f2tf32(qv / ac);
            Kh[idx]  = f2tf32(kv * ac);
            SCL[idx] = ak * ac;
        }
#pragma unroll
        for (int i = 0; i < 8; i++) {
            const int e = tid + i * 256;
            const int idx = (e >> 5) * HS + (e & 31);
            V[idx] = f2tf32(V[idx]);
        }
        __syncthreads();

        float acc4[4][4];
        float acc2[2][4];

        zacc(acc4);
        mmk<4, false, true, false, false, TS>(Kh, Qt, acc4, g, tg, mb, nb64);
        store_tile<4, 2, false, TS>(T1, nullptr, acc4, g, tg, mb, nb64);
        zacc(acc4);
        mmk<4, false, true, false, false, TS>(Qh, Kt, acc4, g, tg, mb, nb64);
        store_tile<4, 1, false, TS>(P, nullptr, acc4, g, tg, mb, nb64);
        __syncthreads();

        zacc(acc2);
        mmk<2, false, false, true,  false, HS>(Kh, Cst, acc2, g, tg, mb, nb32);
        mmk<2, false, false, false, false, HS>(T1, V,   acc2, g, tg, mb, nb32);
        store_tile<2, 0, false, HS>(T2, nullptr, acc2, g, tg, mb, nb32);
        zacc(acc4);
        mmk<4, false, false, true,  false, TS>(Qh, S,  acc4, g, tg, mb, nb64);
        mmk<4, false, false, false, false, TS>(P,  Kt, acc4, g, tg, mb, nb64);
        store_tile<4, 0, true, TS>(SCL, SCL, acc4, g, tg, mb, nb64);
        __syncthreads();

        zacc(acc4);
        mmk<4, false, true, false, false, TS>(SCL, Qt, acc4, g, tg, mb, nb64);
        store_tile<4, 1, false, TS>(T1, nullptr, acc4, g, tg, mb, nb64);
        __syncthreads();

        zacc(acc2);
        mmk<2, false, false, true,  false, HS>(SCL, Cst, acc2, g, tg, mb, nb32);
        mmk<2, false, false, false, false, HS>(T1,  V,   acc2, g, tg, mb, nb32);
        mmk<2, false, false, true,  true,  HS>(Qh,  G,   acc2, g, tg, mb, nb32);
        mmk<2, false, false, false, true,  HS>(P,   T2,  acc2, g, tg, mb, nb32);
        {
            const int t0 = ch * CL;
#pragma unroll
            for (int ni = 0; ni < 2; ni++) {
                const int c0 = nb32 + ni * 8 + 2 * tg;
#pragma unroll
                for (int hh = 0; hh < 2; hh++) {
                    const int r = mb + g + 8 * hh;
                    __half2 st = __floats2half2_rn(acc2[ni][2 * hh],
                                                   acc2[ni][2 * hh + 1]);
                    *(__half2*)&o2dh[(size_t)(b * TSZ + t0 + r) * 1024 +
                                     h * DH + half * 32 + c0] = st;
                }
            }
        }
        __syncthreads();

        zacc(acc4);
        mmk<4, true, false, false, false, TS>(Kt, Kt, acc4, g, tg, mb, nb64);
        update_state<4, 0, TS>(S, aKL, acc4, g, tg, mb, nb64);
        zacc(acc2);
        mmk<2, true, false, false, false, HS>(Qt, V, acc2, g, tg, mb, nb32);
        update_state<2, 1, HS>(Cst, aCL, acc2, g, tg, mb, nb32);
        zacc(acc2);
        mmk<2, true, false, false, false, HS>(Kt, T2, acc2, g, tg, mb, nb32);
        update_state<2, 2, HS>(G, aKL, acc2, g, tg, mb, nb32);
        __syncthreads();
    }
}

// ---------------------------------------------------------------------------
extern "C" void kernel_launch(void* const* d_in, const int* in_sizes, int n_in,
                              void* d_out, int out_size)
{
    const float* x   = (const float*)d_in[0];
    const float* Wq  = (const float*)d_in[1];
    const float* Wk  = (const float*)d_in[2];
    const float* Wv  = (const float*)d_in[3];
    const float* WgK = (const float*)d_in[4];
    const float* bgK = (const float*)d_in[5];
    const float* WgC = (const float*)d_in[6];
    const float* bgC = (const float*)d_in[7];
    const float* Wo  = (const float*)d_in[8];
    float* out = (float*)d_out;

    float *proj = nullptr;
    __half *o2dh = nullptr, *xh = nullptr, *wth = nullptr;
    cudaGetSymbolAddress((void**)&proj, g_proj);
    cudaGetSymbolAddress((void**)&o2dh, g_o2dh);
    cudaGetSymbolAddress((void**)&xh,   g_xh);
    cudaGetSymbolAddress((void**)&wth,  g_wth);
    const size_t PS = (size_t)64 * TSZ * DH;

    cudaFuncSetAttribute(gemm_fp16,
                         cudaFuncAttributeMaxDynamicSharedMemorySize,
                         GEMM2_SMEM);
    cudaFuncSetAttribute(scan_chunked,
                         cudaFuncAttributeMaxDynamicSharedMemorySize,
                         SCAN_SMEM_BYTES);

    half_x_kernel<<<(GM * GK) / 2048, 256>>>(x, xh);
    half_wt_kernel<<<dim3(32, 32, 6), 256>>>(Wq, Wk, Wv, WgK, WgC, Wo, wth);

    gemm_fp16<<<dim3(GN / 256, GM / 128, 5), 256, GEMM2_SMEM>>>(
        xh, wth, bgK, bgC, proj, 1);

    scan_chunked<<<128, 256, SCAN_SMEM_BYTES>>>(proj, proj + PS, proj + 2 * PS,
                                                proj + 3 * PS, proj + 4 * PS, o2dh);

    gemm_fp16<<<dim3(GN / 256, GM / 128, 1), 256, GEMM2_SMEM>>>(
        o2dh, wth + (size_t)5 * GN * GK, nullptr, nullptr, out, 0);
}

// round 10
// speedup vs baseline: 3.8284x; 1.2301x over previous
#include <cuda_runtime.h>
#include <cuda_fp16.h>
#include <math.h>
#include <stdint.h>

#define TSZ 2048
#define HN  16
#define DH  64
#define CL  64
#define NCHUNK 32
#define TS  72                  // fp32 staging stride (floats)
#define SH  72                  // half tile stride (halves)

#define GM 8192
#define GN 1024
#define GK 1024

// Scratch
__device__ float  g_proj[5][(size_t)64 * TSZ * DH];   // 5 * 32 MB
__device__ __half g_o2dh[(size_t)GM * GN];            // 16 MB
__device__ __half g_xh[(size_t)GM * GK];              // 16 MB
__device__ __half g_wth[6][(size_t)GN * GK];          // 12 MB  W^T [z][n][k]

// ---------------------------------------------------------------------------
// Prep: fp16(x) and fp16(W^T).
// ---------------------------------------------------------------------------
__global__ __launch_bounds__(256) void half_x_kernel(
    const float* __restrict__ x, __half* __restrict__ xh)
{
    size_t i = ((size_t)blockIdx.x * 256 + threadIdx.x) * 8;
    float4 v0 = *(const float4*)(x + i);
    float4 v1 = *(const float4*)(x + i + 4);
    __half2 h[4];
    h[0] = __floats2half2_rn(v0.x, v0.y);
    h[1] = __floats2half2_rn(v0.z, v0.w);
    h[2] = __floats2half2_rn(v1.x, v1.y);
    h[3] = __floats2half2_rn(v1.z, v1.w);
    *(uint4*)(xh + i) = *(uint4*)h;
}

__global__ __launch_bounds__(256) void half_wt_kernel(
    const float* __restrict__ Wq, const float* __restrict__ Wk,
    const float* __restrict__ Wv, const float* __restrict__ WgK,
    const float* __restrict__ WgC, const float* __restrict__ Wo,
    __half* __restrict__ wth)
{
    __shared__ float tile[32][33];
    const int z = blockIdx.z;
    const float* W = (z == 0) ? Wq : (z == 1) ? Wk : (z == 2) ? Wv
                   : (z == 3) ? WgK : (z == 4) ? WgC : Wo;
    const int n0 = blockIdx.x * 32, k0 = blockIdx.y * 32;
    const int tx = threadIdx.x & 31, ty = threadIdx.x >> 5;
#pragma unroll
    for (int i = 0; i < 4; i++)
        tile[ty + i * 8][tx] = W[(size_t)(k0 + ty + i * 8) * GN + n0 + tx];
    __syncthreads();
    __half* dst = wth + (size_t)z * GN * GK;
#pragma unroll
    for (int i = 0; i < 4; i++)
        dst[(size_t)(n0 + ty + i * 8) * GK + k0 + tx] =
            __float2half_rn(tile[tx][ty + i * 8]);
}

// ---------------------------------------------------------------------------
// FP16 mma GEMM (round-9, unchanged): CTA 128x256, ktile 64, warp 64x64.
// ---------------------------------------------------------------------------
#define AST2 72
#define BST2 72
#define AS2_EL (128 * AST2)
#define BS2_EL (256 * BST2)
#define GEMM2_SMEM ((2 * (AS2_EL + BS2_EL)) * (int)sizeof(__half))

__device__ __forceinline__ void gemm2_fill(const __half* __restrict__ A,
                                           const __half* __restrict__ BT,
                                           int rowBase, int colBase, int tid,
                                           __half* AsD, __half* BsD, int kt)
{
    const int k0 = kt * 64;
#pragma unroll
    for (int i = 0; i < 4; i++) {
        const int id = tid + i * 256;
        const int r = id >> 3, c = (id & 7) * 8;
        const __half* src = A + (size_t)(rowBase + r) * GK + k0 + c;
        unsigned dst = (unsigned)__cvta_generic_to_shared(AsD + r * AST2 + c);
        asm volatile("cp.async.cg.shared.global [%0], [%1], 16;" :: "r"(dst), "l"(src));
    }
#pragma unroll
    for (int i = 0; i < 8; i++) {
        const int id = tid + i * 256;
        const int r = id >> 3, c = (id & 7) * 8;
        const __half* src = BT + (size_t)(colBase + r) * GK + k0 + c;
        unsigned dst = (unsigned)__cvta_generic_to_shared(BsD + r * BST2 + c);
        asm volatile("cp.async.cg.shared.global [%0], [%1], 16;" :: "r"(dst), "l"(src));
    }
    asm volatile("cp.async.commit_group;");
}

__global__ __launch_bounds__(256, 1) void gemm_fp16(
    const __half* __restrict__ A, const __half* __restrict__ WTall,
    const float* __restrict__ b3, const float* __restrict__ b4,
    float* __restrict__ Cb, int multi)
{
    extern __shared__ __half smem[];
    __half* AsB = smem;
    __half* BsB = smem + 2 * AS2_EL;

    const int tid  = threadIdx.x;
    const int lane = tid & 31;
    const int warpId = tid >> 5;
    const int wm = warpId & 1;
    const int wn = warpId >> 1;
    const int g  = lane >> 2;
    const int tg = lane & 3;
    const int rowBase = blockIdx.y * 128;
    const int colBase = blockIdx.x * 256;

    const __half* BT; const float* bias; float* C; int mode;
    if (multi) {
        const int z = blockIdx.z;
        BT = WTall + (size_t)z * GN * GK;
        bias = (z == 3) ? b3 : (z == 4) ? b4 : nullptr;
        C = Cb + (size_t)z * ((size_t)64 * TSZ * DH);
        mode = (z >= 3) ? 2 : 1;
    } else {
        BT = WTall; bias = nullptr; C = Cb; mode = 0;
    }

    float acc[4][8][4];
#pragma unroll
    for (int i = 0; i < 4; i++)
#pragma unroll
        for (int j = 0; j < 8; j++)
#pragma unroll
            for (int e = 0; e < 4; e++) acc[i][j][e] = 0.f;

    gemm2_fill(A, BT, rowBase, colBase, tid, AsB, BsB, 0);

    const int KT = GK / 64;
    for (int kt = 0; kt < KT; kt++) {
        const int cur = kt & 1;
        asm volatile("cp.async.wait_group 0;");
        __syncthreads();
        if (kt + 1 < KT)
            gemm2_fill(A, BT, rowBase, colBase, tid,
                       AsB + (cur ^ 1) * AS2_EL, BsB + (cur ^ 1) * BS2_EL, kt + 1);

        const __half* As = AsB + cur * AS2_EL;
        const __half* Bs = BsB + cur * BS2_EL;

        unsigned af[2][4][4], bf[2][8][2];
#pragma unroll
        for (int mi = 0; mi < 4; mi++) {
            const int m0 = wm * 64 + mi * 16 + g;
            af[0][mi][0] = *(const unsigned*)&As[m0 * AST2 + 2 * tg];
            af[0][mi][1] = *(const unsigned*)&As[(m0 + 8) * AST2 + 2 * tg];
            af[0][mi][2] = *(const unsigned*)&As[m0 * AST2 + 2 * tg + 8];
            af[0][mi][3] = *(const unsigned*)&As[(m0 + 8) * AST2 + 2 * tg + 8];
        }
#pragma unroll
        for (int ni = 0; ni < 8; ni++) {
            const int n0 = wn * 64 + ni * 8 + g;
            bf[0][ni][0] = *(const unsigned*)&Bs[n0 * BST2 + 2 * tg];
            bf[0][ni][1] = *(const unsigned*)&Bs[n0 * BST2 + 2 * tg + 8];
        }

#pragma unroll
        for (int kk = 0; kk < 4; kk++) {
            const int cb = kk & 1, nx = cb ^ 1;
            if (kk < 3) {
                const int kb = (kk + 1) * 16;
#pragma unroll
                for (int mi = 0; mi < 4; mi++) {
                    const int m0 = wm * 64 + mi * 16 + g;
                    af[nx][mi][0] = *(const unsigned*)&As[m0 * AST2 + kb + 2 * tg];
                    af[nx][mi][1] = *(const unsigned*)&As[(m0 + 8) * AST2 + kb + 2 * tg];
                    af[nx][mi][2] = *(const unsigned*)&As[m0 * AST2 + kb + 2 * tg + 8];
                    af[nx][mi][3] = *(const unsigned*)&As[(m0 + 8) * AST2 + kb + 2 * tg + 8];
                }
#pragma unroll
                for (int ni = 0; ni < 8; ni++) {
                    const int n0 = wn * 64 + ni * 8 + g;
                    bf[nx][ni][0] = *(const unsigned*)&Bs[n0 * BST2 + kb + 2 * tg];
                    bf[nx][ni][1] = *(const unsigned*)&Bs[n0 * BST2 + kb + 2 * tg + 8];
                }
            }
#pragma unroll
            for (int ni = 0; ni < 8; ni++)
#pragma unroll
                for (int mi = 0; mi < 4; mi++) {
                    asm volatile(
                        "mma.sync.aligned.m16n8k16.row.col.f32.f16.f16.f32 "
                        "{%0,%1,%2,%3}, {%4,%5,%6,%7}, {%8,%9}, {%0,%1,%2,%3};\n"
                        : "+f"(acc[mi][ni][0]), "+f"(acc[mi][ni][1]),
                          "+f"(acc[mi][ni][2]), "+f"(acc[mi][ni][3])
                        : "r"(af[cb][mi][0]), "r"(af[cb][mi][1]),
                          "r"(af[cb][mi][2]), "r"(af[cb][mi][3]),
                          "r"(bf[cb][ni][0]), "r"(bf[cb][ni][1]));
                }
        }
    }

#pragma unroll
    for (int mi = 0; mi < 4; mi++) {
        const int gr0 = rowBase + wm * 64 + mi * 16 + g;
#pragma unroll
        for (int ni = 0; ni < 8; ni++) {
            const int gc = colBase + wn * 64 + ni * 8 + 2 * tg;
#pragma unroll
            for (int half = 0; half < 2; half++) {
                const int gr = gr0 + 8 * half;
                float v0 = acc[mi][ni][2 * half];
                float v1 = acc[mi][ni][2 * half + 1];
                if (mode == 0) {
                    *(float2*)&C[(size_t)gr * GN + gc] = make_float2(v0, v1);
                } else {
                    if (mode == 2) {
                        v0 = 1.f / (1.f + __expf(-(v0 + bias[gc])));
                        v1 = 1.f / (1.f + __expf(-(v1 + bias[gc + 1])));
                    }
                    const int b = gr >> 11, t = gr & 2047;
                    const int h = gc >> 6,  d = gc & 63;
                    *(float2*)&C[((size_t)((b * HN + h) * TSZ + t)) * DH + d] =
                        make_float2(v0, v1);
                }
            }
        }
    }
}

// ---------------------------------------------------------------------------
// Chunked scan, dv-split, fp16 mma (m16n8k16).
// Convention: mma operand A stored [m][k] stride SH; B stored [n][k] stride SH.
// States: S fp32 [dk][dk'] (symmetric); CstT/GT fp32 TRANSPOSED [dv][dk].
// Half operand tiles regenerated per chunk.
// ---------------------------------------------------------------------------

// byte offsets inside dynamic smem
#define O_QF   0                         // fp32 q staging 64x72
#define O_KF   18432
#define O_AKF  36864                     // aK -> cumprod -> SCL (ak*ac)
#define O_ACF  55296
#define O_SF   73728                     // fp32 S       64x72
#define O_CTF  92160                     // fp32 CstT    32x72
#define O_GTF  101376                    // fp32 GT      32x72
#define HB     110592
#define O_QH   (HB + 0)                  // half, 64x72 each (9216 B)
#define O_KH   (HB + 9216)
#define O_QT   (HB + 18432)
#define O_QTT  (HB + 27648)
#define O_KT   (HB + 36864)
#define O_KTT  (HB + 46080)
#define O_PH   (HB + 55296)
#define O_RS   (HB + 64512)              // R, later Sc2
#define O_UH   (HB + 73728)
#define O_SHH  (HB + 82944)              // half S (symmetric)
#define O_VT   (HB + 92160)              // half 32x72 each (4608 B)
#define O_KCT  (HB + 96768)
#define O_CTH  (HB + 101376)
#define O_GTH  (HB + 105984)
#define SCAN_SMEM_BYTES (HB + 110592)    // 221184 B

template<int NI>
__device__ __forceinline__ void zacc(float (&acc)[NI][4]) {
#pragma unroll
    for (int i = 0; i < NI; i++)
#pragma unroll
        for (int j = 0; j < 4; j++) acc[i][j] = 0.f;
}

// acc(16 x NI*8) += A(16xK=64) @ B(64 x NI*8); A [m][k], B [n][k], stride SH.
template<int NI, bool NEGA>
__device__ __forceinline__ void mmh(const __half* __restrict__ A,
                                    const __half* __restrict__ B,
                                    float (&acc)[NI][4],
                                    int g, int tg, int mb, int nb)
{
#pragma unroll
    for (int kk = 0; kk < 4; kk++) {
        const int kb = kk * 16;
        unsigned a0 = *(const unsigned*)&A[(mb + g) * SH + kb + 2 * tg];
        unsigned a1 = *(const unsigned*)&A[(mb + g + 8) * SH + kb + 2 * tg];
        unsigned a2 = *(const unsigned*)&A[(mb + g) * SH + kb + 2 * tg + 8];
        unsigned a3 = *(const unsigned*)&A[(mb + g + 8) * SH + kb + 2 * tg + 8];
        if (NEGA) {
            a0 ^= 0x80008000u; a1 ^= 0x80008000u;
            a2 ^= 0x80008000u; a3 ^= 0x80008000u;
        }
#pragma unroll
        for (int ni = 0; ni < NI; ni++) {
            const int n0 = nb + ni * 8 + g;
            unsigned b0 = *(const unsigned*)&B[n0 * SH + kb + 2 * tg];
            unsigned b1 = *(const unsigned*)&B[n0 * SH + kb + 2 * tg + 8];
            asm volatile(
                "mma.sync.aligned.m16n8k16.row.col.f32.f16.f16.f32 "
                "{%0,%1,%2,%3}, {%4,%5,%6,%7}, {%8,%9}, {%0,%1,%2,%3};\n"
                : "+f"(acc[ni][0]), "+f"(acc[ni][1]),
                  "+f"(acc[ni][2]), "+f"(acc[ni][3])
                : "r"(a0), "r"(a1), "r"(a2), "r"(a3), "r"(b0), "r"(b1));
        }
    }
}

// Store acc to half tile [r][c]. MASK: 0 none, 1 keep c<=r, 2 keep c<r.
// SCALE: multiply by fp32 scl[r*TS+c].
template<int NI, int MASK, bool SCALE>
__device__ __forceinline__ void storeH(__half* __restrict__ O,
    const float* __restrict__ scl, float (&acc)[NI][4],
    int g, int tg, int mb, int nb)
{
#pragma unroll
    for (int ni = 0; ni < NI; ni++) {
        const int c0 = nb + ni * 8 + 2 * tg;
#pragma unroll
        for (int hh = 0; hh < 2; hh++) {
            const int r = mb + g + 8 * hh;
#pragma unroll
            for (int e = 0; e < 2; e++) {
                const int c = c0 + e;
                float v = acc[ni][2 * hh + e];
                if (MASK == 1 && c > r)  v = 0.f;
                if (MASK == 2 && c >= r) v = 0.f;
                if (SCALE) v *= scl[r * TS + c];
                O[r * SH + c] = __float2half_rn(v);
            }
        }
    }
}

// Store acc TRANSPOSED into half tile: O[c][r].
template<int NI>
__device__ __forceinline__ void storeHT(__half* __restrict__ O,
    float (&acc)[NI][4], int g, int tg, int mb, int nb)
{
#pragma unroll
    for (int ni = 0; ni < NI; ni++) {
        const int c0 = nb + ni * 8 + 2 * tg;
#pragma unroll
        for (int hh = 0; hh < 2; hh++) {
            const int r = mb + g + 8 * hh;
#pragma unroll
            for (int e = 0; e < 2; e++)
                O[(c0 + e) * SH + r] = __float2half_rn(acc[ni][2 * hh + e]);
        }
    }
}

// S update: v = rs[r]*rs[c]*(Sf + acc); write fp32 + half.
template<int NI>
__device__ __forceinline__ void updateS(float* __restrict__ Sf,
    __half* __restrict__ Sh, const float* __restrict__ rs,
    float (&acc)[NI][4], int g, int tg, int mb, int nb)
{
#pragma unroll
    for (int ni = 0; ni < NI; ni++) {
        const int c0 = nb + ni * 8 + 2 * tg;
#pragma unroll
        for (int hh = 0; hh < 2; hh++) {
            const int r = mb + g + 8 * hh;
            const float rr = rs[r];
#pragma unroll
            for (int e = 0; e < 2; e++) {
                const int c = c0 + e;
                float v = rr * rs[c] * (Sf[r * TS + c] + acc[ni][2 * hh + e]);
                Sf[r * TS + c] = v;
                Sh[r * SH + c] = __float2half_rn(v);
            }
        }
    }
}

// transposed-state update: v = rs[c]*(Tf + acc) (scale by COLUMN gate).
template<int NI>
__device__ __forceinline__ void updateT(float* __restrict__ Tf,
    __half* __restrict__ Th, const float* __restrict__ rs,
    float (&acc)[NI][4], int g, int tg, int mb, int nb)
{
#pragma unroll
    for (int ni = 0; ni < NI; ni++) {
        const int c0 = nb + ni * 8 + 2 * tg;
#pragma unroll
        for (int hh = 0; hh < 2; hh++) {
            const int r = mb + g + 8 * hh;
#pragma unroll
            for (int e = 0; e < 2; e++) {
                const int c = c0 + e;
                float v = rs[c] * (Tf[r * TS + c] + acc[ni][2 * hh + e]);
                Tf[r * TS + c] = v;
                Th[r * SH + c] = __float2half_rn(v);
            }
        }
    }
}

__device__ __forceinline__ void load_tile64(float* __restrict__ dst,
    const float* __restrict__ src, int tid)
{
#pragma unroll
    for (int i = 0; i < 4; i++) {
        const int e = (tid + i * 256) * 4;
        const int r = e >> 6, c = e & 63;
        *(float4*)(dst + r * TS + c) = *(const float4*)(src + e);
    }
}

__global__ __launch_bounds__(256) void scan_chunked(
    const float* __restrict__ qp, const float* __restrict__ kp,
    const float* __restrict__ vp, const float* __restrict__ aKp,
    const float* __restrict__ aCp, __half* __restrict__ o2dh)
{
    extern __shared__ char smc[];
    float*  Qf  = (float*)(smc + O_QF);
    float*  Kf  = (float*)(smc + O_KF);
    float*  AKf = (float*)(smc + O_AKF);   // later SCL
    float*  ACf = (float*)(smc + O_ACF);
    float*  Sf  = (float*)(smc + O_SF);
    float*  CTf = (float*)(smc + O_CTF);
    float*  GTf = (float*)(smc + O_GTF);
    __half* Qh  = (__half*)(smc + O_QH);
    __half* Kh  = (__half*)(smc + O_KH);
    __half* Qt  = (__half*)(smc + O_QT);
    __half* QtT = (__half*)(smc + O_QTT);
    __half* Kt  = (__half*)(smc + O_KT);
    __half* KtT = (__half*)(smc + O_KTT);
    __half* Ph  = (__half*)(smc + O_PH);
    __half* RSc = (__half*)(smc + O_RS);
    __half* Uh  = (__half*)(smc + O_UH);
    __half* Sh  = (__half*)(smc + O_SHH);
    __half* VT  = (__half*)(smc + O_VT);
    __half* KCT = (__half*)(smc + O_KCT);
    __half* CTh = (__half*)(smc + O_CTH);
    __half* GTh = (__half*)(smc + O_GTH);
    __shared__ float aKL[64], aCL[64];

    const int bh   = blockIdx.x >> 1;
    const int half = blockIdx.x & 1;
    const int b = bh >> 4, h = bh & 15;
    const size_t base = (size_t)bh * TSZ * DH;
    const int tid  = threadIdx.x;
    const int lane = tid & 31, w = tid >> 5;
    const int g = lane >> 2, tg = lane & 3;
    const int mb4 = (w & 3) * 16, nb4 = (w >> 2) * 32;   // 64x64 tiling
    const int mb2 = (w & 3) * 16, nb2 = (w >> 2) * 16;   // 64x32 tiling
    const int mbF = (w & 1) * 16, nbF = (w >> 1) * 16;   // 32x64 tiling

    // zero states: fp32 [73728,110592), half S [O_SHH,+9216), half CT/GT pair
    for (int i = tid; i < 9216; i += 256) ((uint32_t*)(smc + O_SF))[i] = 0;
    for (int i = tid; i < 2304; i += 256) ((uint32_t*)(smc + O_SHH))[i] = 0;
    for (int i = tid; i < 2304; i += 256) ((uint32_t*)(smc + O_CTH))[i] = 0;
    __syncthreads();

    for (int ch = 0; ch < NCHUNK; ch++) {
        const size_t off = base + (size_t)ch * CL * DH;
        load_tile64(Qf,  qp  + off, tid);
        load_tile64(Kf,  kp  + off, tid);
        load_tile64(AKf, aKp + off, tid);
        load_tile64(ACf, aCp + off, tid);
        // V half-column -> VT (transposed fp16)
#pragma unroll
        for (int i = 0; i < 2; i++) {
            const int id = tid + i * 256;
            const int r = id >> 3, c4 = (id & 7) * 4;    // 64 x 32/4
            float4 v = *(const float4*)(vp + off + r * DH + half * 32 + c4);
            VT[(c4 + 0) * SH + r] = __float2half_rn(v.x);
            VT[(c4 + 1) * SH + r] = __float2half_rn(v.y);
            VT[(c4 + 2) * SH + r] = __float2half_rn(v.z);
            VT[(c4 + 3) * SH + r] = __float2half_rn(v.w);
        }
        __syncthreads();

        // cumulative products down rows of AKf / ACf
        {
            float* Tt = (tid < 128) ? AKf : ACf;
            const int col = tid & 63;
            const int seg = (tid >> 6) & 1;
            const int r0 = seg * 32;
            float p = 1.f;
#pragma unroll
            for (int r = 0; r < 32; r++) {
                p *= Tt[(r0 + r) * TS + col];
                Tt[(r0 + r) * TS + col] = p;
            }
            __syncthreads();
            if (seg == 1) {
                const float p0 = Tt[31 * TS + col];
#pragma unroll
                for (int r = 32; r < 64; r++) Tt[r * TS + col] *= p0;
            }
        }
        __syncthreads();

        // derive fp16 operand tiles (+ SCL fp32 in AKf slot)
#pragma unroll
        for (int i = 0; i < 16; i++) {
            const int e = tid + i * 256;
            const int r = e >> 6, c = e & 63;
            const int idx = r * TS + c;
            const float ak = AKf[idx], ac = ACf[idx];
            const float qv = Qf[idx],  kv = Kf[idx];
            if (r == 63) { aKL[c] = ak; aCL[c] = ac; }
            const float qh = qv * ak, kt = kv / ak;
            const float qt = qv / ac, kh = kv * ac;
            Qh[r * SH + c]  = __float2half_rn(qh);
            Kh[r * SH + c]  = __float2half_rn(kh);
            Qt[r * SH + c]  = __float2half_rn(qt);
            QtT[c * SH + r] = __float2half_rn(qt);
            Kt[r * SH + c]  = __float2half_rn(kt);
            KtT[c * SH + r] = __float2half_rn(kt);
            AKf[idx] = ak * ac;          // SCL
        }
        __syncthreads();

        float acc4[4][4];
        float acc2[2][4];

        // A: R = strict(Kh @ Qt^T) -> RSc ; P = incl(Qh @ Kt^T) -> Ph
        zacc(acc4);
        mmh<4, false>(Kh, Qt, acc4, g, tg, mb4, nb4);
        storeH<4, 2, false>(RSc, nullptr, acc4, g, tg, mb4, nb4);
        zacc(acc4);
        mmh<4, false>(Qh, Kt, acc4, g, tg, mb4, nb4);
        storeH<4, 1, false>(Ph, nullptr, acc4, g, tg, mb4, nb4);
        __syncthreads();

        // B: KC = Kh@C0 + R@V -> KCT (transposed) ;
        //    Uhat = (Qh@S0 + P@Kt)*SCL -> Uh
        zacc(acc2);
        mmh<2, false>(Kh,  CTh, acc2, g, tg, mb2, nb2);
        mmh<2, false>(RSc, VT,  acc2, g, tg, mb2, nb2);
        storeHT<2>(KCT, acc2, g, tg, mb2, nb2);
        zacc(acc4);
        mmh<4, false>(Qh, Sh,  acc4, g, tg, mb4, nb4);
        mmh<4, false>(Ph, KtT, acc4, g, tg, mb4, nb4);
        storeH<4, 0, true>(Uh, AKf, acc4, g, tg, mb4, nb4);
        __syncthreads();

        // D: Sc2 = incl(Uh @ Qt^T) -> RSc (R dead)
        zacc(acc4);
        mmh<4, false>(Uh, Qt, acc4, g, tg, mb4, nb4);
        storeH<4, 1, false>(RSc, nullptr, acc4, g, tg, mb4, nb4);
        __syncthreads();

        // E: O = Uh@C0 + Sc2@V - Qh@G0 - P@KC -> gmem fp16
        zacc(acc2);
        mmh<2, false>(Uh,  CTh, acc2, g, tg, mb2, nb2);
        mmh<2, false>(RSc, VT,  acc2, g, tg, mb2, nb2);
        mmh<2, true >(Qh,  GTh, acc2, g, tg, mb2, nb2);
        mmh<2, true >(Ph,  KCT, acc2, g, tg, mb2, nb2);
        {
            const int t0 = ch * CL;
#pragma unroll
            for (int ni = 0; ni < 2; ni++) {
                const int c0 = nb2 + ni * 8 + 2 * tg;
#pragma unroll
                for (int hh = 0; hh < 2; hh++) {
                    const int r = mb2 + g + 8 * hh;
                    __half2 st = __floats2half2_rn(acc2[ni][2 * hh],
                                                   acc2[ni][2 * hh + 1]);
                    *(__half2*)&o2dh[(size_t)(b * TSZ + t0 + r) * 1024 +
                                     h * DH + half * 32 + c0] = st;
                }
            }
        }
        __syncthreads();

        // F: state updates
        zacc(acc4);
        mmh<4, false>(KtT, KtT, acc4, g, tg, mb4, nb4);       // Kt^T @ Kt
        updateS<4>(Sf, Sh, aKL, acc4, g, tg, mb4, nb4);
        zacc(acc2);
        mmh<2, false>(VT, QtT, acc2, g, tg, mbF, nbF);        // V^T @ Qt
        updateT<2>(CTf, CTh, aCL, acc2, g, tg, mbF, nbF);
        zacc(acc2);
        mmh<2, false>(KCT, KtT, acc2, g, tg, mbF, nbF);       // KC^T @ Kt
        updateT<2>(GTf, GTh, aKL, acc2, g, tg, mbF, nbF);
        __syncthreads();
    }
}

// ---------------------------------------------------------------------------
extern "C" void kernel_launch(void* const* d_in, const int* in_sizes, int n_in,
                              void* d_out, int out_size)
{
    const float* x   = (const float*)d_in[0];
    const float* Wq  = (const float*)d_in[1];
    const float* Wk  = (const float*)d_in[2];
    const float* Wv  = (const float*)d_in[3];
    const float* WgK = (const float*)d_in[4];
    const float* bgK = (const float*)d_in[5];
    const float* WgC = (const float*)d_in[6];
    const float* bgC = (const float*)d_in[7];
    const float* Wo  = (const float*)d_in[8];
    float* out = (float*)d_out;

    float *proj = nullptr;
    __half *o2dh = nullptr, *xh = nullptr, *wth = nullptr;
    cudaGetSymbolAddress((void**)&proj, g_proj);
    cudaGetSymbolAddress((void**)&o2dh, g_o2dh);
    cudaGetSymbolAddress((void**)&xh,   g_xh);
    cudaGetSymbolAddress((void**)&wth,  g_wth);
    const size_t PS = (size_t)64 * TSZ * DH;

    cudaFuncSetAttribute(gemm_fp16,
                         cudaFuncAttributeMaxDynamicSharedMemorySize,
                         GEMM2_SMEM);
    cudaFuncSetAttribute(scan_chunked,
                         cudaFuncAttributeMaxDynamicSharedMemorySize,
                         SCAN_SMEM_BYTES);

    half_x_kernel<<<(GM * GK) / 2048, 256>>>(x, xh);
    half_wt_kernel<<<dim3(32, 32, 6), 256>>>(Wq, Wk, Wv, WgK, WgC, Wo, wth);

    gemm_fp16<<<dim3(GN / 256, GM / 128, 5), 256, GEMM2_SMEM>>>(
        xh, wth, bgK, bgC, proj, 1);

    scan_chunked<<<128, 256, SCAN_SMEM_BYTES>>>(proj, proj + PS, proj + 2 * PS,
                                                proj + 3 * PS, proj + 4 * PS, o2dh);

    gemm_fp16<<<dim3(GN / 256, GM / 128, 1), 256, GEMM2_SMEM>>>(
        o2dh, wth + (size_t)5 * GN * GK, nullptr, nullptr, out, 0);
}

// round 11
// speedup vs baseline: 3.8611x; 1.0086x over previous
#include <cuda_runtime.h>
#include <cuda_fp16.h>
#include <math.h>
#include <stdint.h>

#define TSZ 2048
#define HN  16
#define DH  64
#define CL  64
#define NCHUNK 32
#define TS  72                  // fp32 staging stride (floats)
#define SH  72                  // half tile stride (halves)

#define GM 8192
#define GN 1024
#define GK 1024

// Scratch
__device__ float  g_proj[5][(size_t)64 * TSZ * DH];   // 5 * 32 MB
__device__ __half g_o2dh[(size_t)GM * GN];            // 16 MB
__device__ __half g_xh[(size_t)GM * GK];              // 16 MB
__device__ __half g_wth[6][(size_t)GN * GK];          // 12 MB  W^T [z][n][k]

__device__ __forceinline__ void ldsm_x4(unsigned& r0, unsigned& r1,
                                        unsigned& r2, unsigned& r3,
                                        uint32_t addr) {
    asm volatile("ldmatrix.sync.aligned.m8n8.x4.shared.b16 {%0,%1,%2,%3}, [%4];"
                 : "=r"(r0), "=r"(r1), "=r"(r2), "=r"(r3) : "r"(addr));
}

// ---------------------------------------------------------------------------
// Prep: fp16(x) and fp16(W^T).
// ---------------------------------------------------------------------------
__global__ __launch_bounds__(256) void half_x_kernel(
    const float* __restrict__ x, __half* __restrict__ xh)
{
    size_t i = ((size_t)blockIdx.x * 256 + threadIdx.x) * 8;
    float4 v0 = *(const float4*)(x + i);
    float4 v1 = *(const float4*)(x + i + 4);
    __half2 h[4];
    h[0] = __floats2half2_rn(v0.x, v0.y);
    h[1] = __floats2half2_rn(v0.z, v0.w);
    h[2] = __floats2half2_rn(v1.x, v1.y);
    h[3] = __floats2half2_rn(v1.z, v1.w);
    *(uint4*)(xh + i) = *(uint4*)h;
}

__global__ __launch_bounds__(256) void half_wt_kernel(
    const float* __restrict__ Wq, const float* __restrict__ Wk,
    const float* __restrict__ Wv, const float* __restrict__ WgK,
    const float* __restrict__ WgC, const float* __restrict__ Wo,
    __half* __restrict__ wth)
{
    __shared__ float tile[32][33];
    const int z = blockIdx.z;
    const float* W = (z == 0) ? Wq : (z == 1) ? Wk : (z == 2) ? Wv
                   : (z == 3) ? WgK : (z == 4) ? WgC : Wo;
    const int n0 = blockIdx.x * 32, k0 = blockIdx.y * 32;
    const int tx = threadIdx.x & 31, ty = threadIdx.x >> 5;
#pragma unroll
    for (int i = 0; i < 4; i++)
        tile[ty + i * 8][tx] = W[(size_t)(k0 + ty + i * 8) * GN + n0 + tx];
    __syncthreads();
    __half* dst = wth + (size_t)z * GN * GK;
#pragma unroll
    for (int i = 0; i < 4; i++)
        dst[(size_t)(n0 + ty + i * 8) * GK + k0 + tx] =
            __float2half_rn(tile[tx][ty + i * 8]);
}

// ---------------------------------------------------------------------------
// FP16 mma GEMM with ldmatrix fragments: CTA 128x256, ktile 64, warp 64x64.
// ---------------------------------------------------------------------------
#define AST2 72
#define BST2 72
#define AS2_EL (128 * AST2)
#define BS2_EL (256 * BST2)
#define GEMM2_SMEM ((2 * (AS2_EL + BS2_EL)) * (int)sizeof(__half))

__device__ __forceinline__ void gemm2_fill(const __half* __restrict__ A,
                                           const __half* __restrict__ BT,
                                           int rowBase, int colBase, int tid,
                                           __half* AsD, __half* BsD, int kt)
{
    const int k0 = kt * 64;
#pragma unroll
    for (int i = 0; i < 4; i++) {
        const int id = tid + i * 256;
        const int r = id >> 3, c = (id & 7) * 8;
        const __half* src = A + (size_t)(rowBase + r) * GK + k0 + c;
        unsigned dst = (unsigned)__cvta_generic_to_shared(AsD + r * AST2 + c);
        asm volatile("cp.async.cg.shared.global [%0], [%1], 16;" :: "r"(dst), "l"(src));
    }
#pragma unroll
    for (int i = 0; i < 8; i++) {
        const int id = tid + i * 256;
        const int r = id >> 3, c = (id & 7) * 8;
        const __half* src = BT + (size_t)(colBase + r) * GK + k0 + c;
        unsigned dst = (unsigned)__cvta_generic_to_shared(BsD + r * BST2 + c);
        asm volatile("cp.async.cg.shared.global [%0], [%1], 16;" :: "r"(dst), "l"(src));
    }
    asm volatile("cp.async.commit_group;");
}

__global__ __launch_bounds__(256, 1) void gemm_fp16(
    const __half* __restrict__ A, const __half* __restrict__ WTall,
    const float* __restrict__ b3, const float* __restrict__ b4,
    float* __restrict__ Cb, int multi)
{
    extern __shared__ __half smem[];
    __half* AsB = smem;
    __half* BsB = smem + 2 * AS2_EL;

    const int tid  = threadIdx.x;
    const int lane = tid & 31;
    const int warpId = tid >> 5;
    const int wm = warpId & 1;
    const int wn = warpId >> 1;
    const int g  = lane >> 2;
    const int tg = lane & 3;
    const int rowBase = blockIdx.y * 128;
    const int colBase = blockIdx.x * 256;

    // ldmatrix per-lane offsets (bytes)
    const uint32_t laneAoff =
        (uint32_t)((((lane & 15) * AST2) + ((lane >> 4) << 3)) * 2);
    const int brow = (lane & 7) + ((lane >> 4) << 3);
    const int bko  = ((lane >> 3) & 1) << 3;
    const uint32_t laneBoff = (uint32_t)((brow * BST2 + bko) * 2);

    const __half* BT; const float* bias; float* C; int mode;
    if (multi) {
        const int z = blockIdx.z;
        BT = WTall + (size_t)z * GN * GK;
        bias = (z == 3) ? b3 : (z == 4) ? b4 : nullptr;
        C = Cb + (size_t)z * ((size_t)64 * TSZ * DH);
        mode = (z >= 3) ? 2 : 1;
    } else {
        BT = WTall; bias = nullptr; C = Cb; mode = 0;
    }

    float acc[4][8][4];
#pragma unroll
    for (int i = 0; i < 4; i++)
#pragma unroll
        for (int j = 0; j < 8; j++)
#pragma unroll
            for (int e = 0; e < 4; e++) acc[i][j][e] = 0.f;

    gemm2_fill(A, BT, rowBase, colBase, tid, AsB, BsB, 0);

    const int KT = GK / 64;
    for (int kt = 0; kt < KT; kt++) {
        const int cur = kt & 1;
        asm volatile("cp.async.wait_group 0;");
        __syncthreads();
        if (kt + 1 < KT)
            gemm2_fill(A, BT, rowBase, colBase, tid,
                       AsB + (cur ^ 1) * AS2_EL, BsB + (cur ^ 1) * BS2_EL, kt + 1);

        const __half* As = AsB + cur * AS2_EL;
        const __half* Bs = BsB + cur * BS2_EL;
        const uint32_t asb = (uint32_t)__cvta_generic_to_shared(As)
                           + (uint32_t)(wm * 64 * AST2 * 2) + laneAoff;
        const uint32_t bsb = (uint32_t)__cvta_generic_to_shared(Bs)
                           + (uint32_t)(wn * 64 * BST2 * 2) + laneBoff;

        unsigned af[2][4][4], bf[2][8][2];
        // preload k-step 0 fragments via ldmatrix
#pragma unroll
        for (int mi = 0; mi < 4; mi++)
            ldsm_x4(af[0][mi][0], af[0][mi][1], af[0][mi][2], af[0][mi][3],
                    asb + mi * 16 * AST2 * 2);
#pragma unroll
        for (int j = 0; j < 4; j++)
            ldsm_x4(bf[0][2 * j][0], bf[0][2 * j][1],
                    bf[0][2 * j + 1][0], bf[0][2 * j + 1][1],
                    bsb + j * 16 * BST2 * 2);

#pragma unroll
        for (int kk = 0; kk < 4; kk++) {
            const int cb = kk & 1, nx = cb ^ 1;
            if (kk < 3) {
                const uint32_t kb2 = (kk + 1) * 32;   // bytes
#pragma unroll
                for (int mi = 0; mi < 4; mi++)
                    ldsm_x4(af[nx][mi][0], af[nx][mi][1],
                            af[nx][mi][2], af[nx][mi][3],
                            asb + mi * 16 * AST2 * 2 + kb2);
#pragma unroll
                for (int j = 0; j < 4; j++)
                    ldsm_x4(bf[nx][2 * j][0], bf[nx][2 * j][1],
                            bf[nx][2 * j + 1][0], bf[nx][2 * j + 1][1],
                            bsb + j * 16 * BST2 * 2 + kb2);
            }
#pragma unroll
            for (int ni = 0; ni < 8; ni++)
#pragma unroll
                for (int mi = 0; mi < 4; mi++) {
                    asm volatile(
                        "mma.sync.aligned.m16n8k16.row.col.f32.f16.f16.f32 "
                        "{%0,%1,%2,%3}, {%4,%5,%6,%7}, {%8,%9}, {%0,%1,%2,%3};\n"
                        : "+f"(acc[mi][ni][0]), "+f"(acc[mi][ni][1]),
                          "+f"(acc[mi][ni][2]), "+f"(acc[mi][ni][3])
                        : "r"(af[cb][mi][0]), "r"(af[cb][mi][1]),
                          "r"(af[cb][mi][2]), "r"(af[cb][mi][3]),
                          "r"(bf[cb][ni][0]), "r"(bf[cb][ni][1]));
                }
        }
    }

#pragma unroll
    for (int mi = 0; mi < 4; mi++) {
        const int gr0 = rowBase + wm * 64 + mi * 16 + g;
#pragma unroll
        for (int ni = 0; ni < 8; ni++) {
            const int gc = colBase + wn * 64 + ni * 8 + 2 * tg;
#pragma unroll
            for (int half = 0; half < 2; half++) {
                const int gr = gr0 + 8 * half;
                float v0 = acc[mi][ni][2 * half];
                float v1 = acc[mi][ni][2 * half + 1];
                if (mode == 0) {
                    *(float2*)&C[(size_t)gr * GN + gc] = make_float2(v0, v1);
                } else {
                    if (mode == 2) {
                        v0 = 1.f / (1.f + __expf(-(v0 + bias[gc])));
                        v1 = 1.f / (1.f + __expf(-(v1 + bias[gc + 1])));
                    }
                    const int b = gr >> 11, t = gr & 2047;
                    const int h = gc >> 6,  d = gc & 63;
                    *(float2*)&C[((size_t)((b * HN + h) * TSZ + t)) * DH + d] =
                        make_float2(v0, v1);
                }
            }
        }
    }
}

// ---------------------------------------------------------------------------
// Chunked scan, dv-split, fp16 mma + ldmatrix fragments.
// ---------------------------------------------------------------------------
#define O_QF   0
#define O_KF   18432
#define O_AKF  36864
#define O_ACF  55296
#define O_SF   73728
#define O_CTF  92160
#define O_GTF  101376
#define HB     110592
#define O_QH   (HB + 0)
#define O_KH   (HB + 9216)
#define O_QT   (HB + 18432)
#define O_QTT  (HB + 27648)
#define O_KT   (HB + 36864)
#define O_KTT  (HB + 46080)
#define O_PH   (HB + 55296)
#define O_RS   (HB + 64512)
#define O_UH   (HB + 73728)
#define O_SHH  (HB + 82944)
#define O_VT   (HB + 92160)
#define O_KCT  (HB + 96768)
#define O_CTH  (HB + 101376)
#define O_GTH  (HB + 105984)
#define SCAN_SMEM_BYTES (HB + 110592)

template<int NI>
__device__ __forceinline__ void zacc(float (&acc)[NI][4]) {
#pragma unroll
    for (int i = 0; i < NI; i++)
#pragma unroll
        for (int j = 0; j < 4; j++) acc[i][j] = 0.f;
}

// acc(16 x NI*8) += A(16x64) @ B(64 x NI*8)^T-conv; A [m][k], B [n][k],
// stride SH, fragments via ldmatrix.
template<int NI, bool NEGA>
__device__ __forceinline__ void mmh(const __half* __restrict__ A,
                                    const __half* __restrict__ B,
                                    float (&acc)[NI][4],
                                    int lane, int mb, int nb)
{
    const uint32_t abase = (uint32_t)__cvta_generic_to_shared(
        A + (mb + (lane & 15)) * SH + ((lane >> 4) << 3));
    const int brow = (lane & 7) + ((lane >> 4) << 3);
    const int bko  = ((lane >> 3) & 1) << 3;
    const uint32_t bbase = (uint32_t)__cvta_generic_to_shared(
        B + (nb + brow) * SH + bko);
#pragma unroll
    for (int kk = 0; kk < 4; kk++) {
        const uint32_t kb2 = kk * 32;      // bytes
        unsigned a0, a1, a2, a3;
        ldsm_x4(a0, a1, a2, a3, abase + kb2);
        if (NEGA) {
            a0 ^= 0x80008000u; a1 ^= 0x80008000u;
            a2 ^= 0x80008000u; a3 ^= 0x80008000u;
        }
#pragma unroll
        for (int j = 0; j < NI / 2; j++) {
            unsigned b0, b1, b2, b3;
            ldsm_x4(b0, b1, b2, b3, bbase + (uint32_t)(j * 16 * SH * 2) + kb2);
            asm volatile(
                "mma.sync.aligned.m16n8k16.row.col.f32.f16.f16.f32 "
                "{%0,%1,%2,%3}, {%4,%5,%6,%7}, {%8,%9}, {%0,%1,%2,%3};\n"
                : "+f"(acc[2 * j][0]), "+f"(acc[2 * j][1]),
                  "+f"(acc[2 * j][2]), "+f"(acc[2 * j][3])
                : "r"(a0), "r"(a1), "r"(a2), "r"(a3), "r"(b0), "r"(b1));
            asm volatile(
                "mma.sync.aligned.m16n8k16.row.col.f32.f16.f16.f32 "
                "{%0,%1,%2,%3}, {%4,%5,%6,%7}, {%8,%9}, {%0,%1,%2,%3};\n"
                : "+f"(acc[2 * j + 1][0]), "+f"(acc[2 * j + 1][1]),
                  "+f"(acc[2 * j + 1][2]), "+f"(acc[2 * j + 1][3])
                : "r"(a0), "r"(a1), "r"(a2), "r"(a3), "r"(b2), "r"(b3));
        }
    }
}

template<int NI, int MASK, bool SCALE>
__device__ __forceinline__ void storeH(__half* __restrict__ O,
    const float* __restrict__ scl, float (&acc)[NI][4],
    int g, int tg, int mb, int nb)
{
#pragma unroll
    for (int ni = 0; ni < NI; ni++) {
        const int c0 = nb + ni * 8 + 2 * tg;
#pragma unroll
        for (int hh = 0; hh < 2; hh++) {
            const int r = mb + g + 8 * hh;
#pragma unroll
            for (int e = 0; e < 2; e++) {
                const int c = c0 + e;
                float v = acc[ni][2 * hh + e];
                if (MASK == 1 && c > r)  v = 0.f;
                if (MASK == 2 && c >= r) v = 0.f;
                if (SCALE) v *= scl[r * TS + c];
                O[r * SH + c] = __float2half_rn(v);
            }
        }
    }
}

template<int NI>
__device__ __forceinline__ void storeHT(__half* __restrict__ O,
    float (&acc)[NI][4], int g, int tg, int mb, int nb)
{
#pragma unroll
    for (int ni = 0; ni < NI; ni++) {
        const int c0 = nb + ni * 8 + 2 * tg;
#pragma unroll
        for (int hh = 0; hh < 2; hh++) {
            const int r = mb + g + 8 * hh;
#pragma unroll
            for (int e = 0; e < 2; e++)
                O[(c0 + e) * SH + r] = __float2half_rn(acc[ni][2 * hh + e]);
        }
    }
}

template<int NI>
__device__ __forceinline__ void updateS(float* __restrict__ Sf,
    __half* __restrict__ Sh, const float* __restrict__ rs,
    float (&acc)[NI][4], int g, int tg, int mb, int nb)
{
#pragma unroll
    for (int ni = 0; ni < NI; ni++) {
        const int c0 = nb + ni * 8 + 2 * tg;
#pragma unroll
        for (int hh = 0; hh < 2; hh++) {
            const int r = mb + g + 8 * hh;
            const float rr = rs[r];
#pragma unroll
            for (int e = 0; e < 2; e++) {
                const int c = c0 + e;
                float v = rr * rs[c] * (Sf[r * TS + c] + acc[ni][2 * hh + e]);
                Sf[r * TS + c] = v;
                Sh[r * SH + c] = __float2half_rn(v);
            }
        }
    }
}

template<int NI>
__device__ __forceinline__ void updateT(float* __restrict__ Tf,
    __half* __restrict__ Th, const float* __restrict__ rs,
    float (&acc)[NI][4], int g, int tg, int mb, int nb)
{
#pragma unroll
    for (int ni = 0; ni < NI; ni++) {
        const int c0 = nb + ni * 8 + 2 * tg;
#pragma unroll
        for (int hh = 0; hh < 2; hh++) {
            const int r = mb + g + 8 * hh;
#pragma unroll
            for (int e = 0; e < 2; e++) {
                const int c = c0 + e;
                float v = rs[c] * (Tf[r * TS + c] + acc[ni][2 * hh + e]);
                Tf[r * TS + c] = v;
                Th[r * SH + c] = __float2half_rn(v);
            }
        }
    }
}

__device__ __forceinline__ void load_tile64(float* __restrict__ dst,
    const float* __restrict__ src, int tid)
{
#pragma unroll
    for (int i = 0; i < 4; i++) {
        const int e = (tid + i * 256) * 4;
        const int r = e >> 6, c = e & 63;
        *(float4*)(dst + r * TS + c) = *(const float4*)(src + e);
    }
}

__global__ __launch_bounds__(256) void scan_chunked(
    const float* __restrict__ qp, const float* __restrict__ kp,
    const float* __restrict__ vp, const float* __restrict__ aKp,
    const float* __restrict__ aCp, __half* __restrict__ o2dh)
{
    extern __shared__ char smc[];
    float*  Qf  = (float*)(smc + O_QF);
    float*  Kf  = (float*)(smc + O_KF);
    float*  AKf = (float*)(smc + O_AKF);
    float*  ACf = (float*)(smc + O_ACF);
    float*  Sf  = (float*)(smc + O_SF);
    float*  CTf = (float*)(smc + O_CTF);
    float*  GTf = (float*)(smc + O_GTF);
    __half* Qh  = (__half*)(smc + O_QH);
    __half* Kh  = (__half*)(smc + O_KH);
    __half* Qt  = (__half*)(smc + O_QT);
    __half* QtT = (__half*)(smc + O_QTT);
    __half* Kt  = (__half*)(smc + O_KT);
    __half* KtT = (__half*)(smc + O_KTT);
    __half* Ph  = (__half*)(smc + O_PH);
    __half* RSc = (__half*)(smc + O_RS);
    __half* Uh  = (__half*)(smc + O_UH);
    __half* Sh  = (__half*)(smc + O_SHH);
    __half* VT  = (__half*)(smc + O_VT);
    __half* KCT = (__half*)(smc + O_KCT);
    __half* CTh = (__half*)(smc + O_CTH);
    __half* GTh = (__half*)(smc + O_GTH);
    __shared__ float aKL[64], aCL[64];

    const int bh   = blockIdx.x >> 1;
    const int half = blockIdx.x & 1;
    const int b = bh >> 4, h = bh & 15;
    const size_t base = (size_t)bh * TSZ * DH;
    const int tid  = threadIdx.x;
    const int lane = tid & 31, w = tid >> 5;
    const int g = lane >> 2, tg = lane & 3;
    const int mb4 = (w & 3) * 16, nb4 = (w >> 2) * 32;   // 64x64 tiling
    const int mb2 = (w & 3) * 16, nb2 = (w >> 2) * 16;   // 64x32 tiling
    const int mbF = (w & 1) * 16, nbF = (w >> 1) * 16;   // 32x64 tiling

    for (int i = tid; i < 9216; i += 256) ((uint32_t*)(smc + O_SF))[i] = 0;
    for (int i = tid; i < 2304; i += 256) ((uint32_t*)(smc + O_SHH))[i] = 0;
    for (int i = tid; i < 2304; i += 256) ((uint32_t*)(smc + O_CTH))[i] = 0;
    __syncthreads();

    for (int ch = 0; ch < NCHUNK; ch++) {
        const size_t off = base + (size_t)ch * CL * DH;
        load_tile64(Qf,  qp  + off, tid);
        load_tile64(Kf,  kp  + off, tid);
        load_tile64(AKf, aKp + off, tid);
        load_tile64(ACf, aCp + off, tid);
#pragma unroll
        for (int i = 0; i < 2; i++) {
            const int id = tid + i * 256;
            const int r = id >> 3, c4 = (id & 7) * 4;
            float4 v = *(const float4*)(vp + off + r * DH + half * 32 + c4);
            VT[(c4 + 0) * SH + r] = __float2half_rn(v.x);
            VT[(c4 + 1) * SH + r] = __float2half_rn(v.y);
            VT[(c4 + 2) * SH + r] = __float2half_rn(v.z);
            VT[(c4 + 3) * SH + r] = __float2half_rn(v.w);
        }
        __syncthreads();

        {
            float* Tt = (tid < 128) ? AKf : ACf;
            const int col = tid & 63;
            const int seg = (tid >> 6) & 1;
            const int r0 = seg * 32;
            float p = 1.f;
#pragma unroll
            for (int r = 0; r < 32; r++) {
                p *= Tt[(r0 + r) * TS + col];
                Tt[(r0 + r) * TS + col] = p;
            }
            __syncthreads();
            if (seg == 1) {
                const float p0 = Tt[31 * TS + col];
#pragma unroll
                for (int r = 32; r < 64; r++) Tt[r * TS + col] *= p0;
            }
        }
        __syncthreads();

#pragma unroll
        for (int i = 0; i < 16; i++) {
            const int e = tid + i * 256;
            const int r = e >> 6, c = e & 63;
            const int idx = r * TS + c;
            const float ak = AKf[idx], ac = ACf[idx];
            const float qv = Qf[idx],  kv = Kf[idx];
            if (r == 63) { aKL[c] = ak; aCL[c] = ac; }
            const float qh = qv * ak, kt = kv / ak;
            const float qt = qv / ac, kh = kv * ac;
            Qh[r * SH + c]  = __float2half_rn(qh);
            Kh[r * SH + c]  = __float2half_rn(kh);
            Qt[r * SH + c]  = __float2half_rn(qt);
            QtT[c * SH + r] = __float2half_rn(qt);
            Kt[r * SH + c]  = __float2half_rn(kt);
            KtT[c * SH + r] = __float2half_rn(kt);
            AKf[idx] = ak * ac;          // SCL
        }
        __syncthreads();

        float acc4[4][4];
        float acc2[2][4];

        // A: R = strict(Kh @ Qt^T) -> RSc ; P = incl(Qh @ Kt^T) -> Ph
        zacc(acc4);
        mmh<4, false>(Kh, Qt, acc4, lane, mb4, nb4);
        storeH<4, 2, false>(RSc, nullptr, acc4, g, tg, mb4, nb4);
        zacc(acc4);
        mmh<4, false>(Qh, Kt, acc4, lane, mb4, nb4);
        storeH<4, 1, false>(Ph, nullptr, acc4, g, tg, mb4, nb4);
        __syncthreads();

        // B: KC = Kh@C0 + R@V -> KCT (transposed) ;
        //    Uhat = (Qh@S0 + P@Kt)*SCL -> Uh
        zacc(acc2);
        mmh<2, false>(Kh,  CTh, acc2, lane, mb2, nb2);
        mmh<2, false>(RSc, VT,  acc2, lane, mb2, nb2);
        storeHT<2>(KCT, acc2, g, tg, mb2, nb2);
        zacc(acc4);
        mmh<4, false>(Qh, Sh,  acc4, lane, mb4, nb4);
        mmh<4, false>(Ph, KtT, acc4, lane, mb4, nb4);
        storeH<4, 0, true>(Uh, AKf, acc4, g, tg, mb4, nb4);
        __syncthreads();

        // D: Sc2 = incl(Uh @ Qt^T) -> RSc
        zacc(acc4);
        mmh<4, false>(Uh, Qt, acc4, lane, mb4, nb4);
        storeH<4, 1, false>(RSc, nullptr, acc4, g, tg, mb4, nb4);
        __syncthreads();

        // E: O = Uh@C0 + Sc2@V - Qh@G0 - P@KC -> gmem fp16
        zacc(acc2);
        mmh<2, false>(Uh,  CTh, acc2, lane, mb2, nb2);
        mmh<2, false>(RSc, VT,  acc2, lane, mb2, nb2);
        mmh<2, true >(Qh,  GTh, acc2, lane, mb2, nb2);
        mmh<2, true >(Ph,  KCT, acc2, lane, mb2, nb2);
        {
            const int t0 = ch * CL;
#pragma unroll
            for (int ni = 0; ni < 2; ni++) {
                const int c0 = nb2 + ni * 8 + 2 * tg;
#pragma unroll
                for (int hh = 0; hh < 2; hh++) {
                    const int r = mb2 + g + 8 * hh;
                    __half2 st = __floats2half2_rn(acc2[ni][2 * hh],
                                                   acc2[ni][2 * hh + 1]);
                    *(__half2*)&o2dh[(size_t)(b * TSZ + t0 + r) * 1024 +
                                     h * DH + half * 32 + c0] = st;
                }
            }
        }
        __syncthreads();

        // F: state updates
        zacc(acc4);
        mmh<4, false>(KtT, KtT, acc4, lane, mb4, nb4);        // Kt^T @ Kt
        updateS<4>(Sf, Sh, aKL, acc4, g, tg, mb4, nb4);
        zacc(acc2);
        mmh<2, false>(VT, QtT, acc2, lane, mbF, nbF);         // V^T @ Qt
        updateT<2>(CTf, CTh, aCL, acc2, g, tg, mbF, nbF);
        zacc(acc2);
        mmh<2, false>(KCT, KtT, acc2, lane, mbF, nbF);        // KC^T @ Kt
        updateT<2>(GTf, GTh, aKL, acc2, g, tg, mbF, nbF);
        __syncthreads();
    }
}

// ---------------------------------------------------------------------------
extern "C" void kernel_launch(void* const* d_in, const int* in_sizes, int n_in,
                              void* d_out, int out_size)
{
    const float* x   = (const float*)d_in[0];
    const float* Wq  = (const float*)d_in[1];
    const float* Wk  = (const float*)d_in[2];
    const float* Wv  = (const float*)d_in[3];
    const float* WgK = (const float*)d_in[4];
    const float* bgK = (const float*)d_in[5];
    const float* WgC = (const float*)d_in[6];
    const float* bgC = (const float*)d_in[7];
    const float* Wo  = (const float*)d_in[8];
    float* out = (float*)d_out;

    float *proj = nullptr;
    __half *o2dh = nullptr, *xh = nullptr, *wth = nullptr;
    cudaGetSymbolAddress((void**)&proj, g_proj);
    cudaGetSymbolAddress((void**)&o2dh, g_o2dh);
    cudaGetSymbolAddress((void**)&xh,   g_xh);
    cudaGetSymbolAddress((void**)&wth,  g_wth);
    const size_t PS = (size_t)64 * TSZ * DH;

    cudaFuncSetAttribute(gemm_fp16,
                         cudaFuncAttributeMaxDynamicSharedMemorySize,
                         GEMM2_SMEM);
    cudaFuncSetAttribute(scan_chunked,
                         cudaFuncAttributeMaxDynamicSharedMemorySize,
                         SCAN_SMEM_BYTES);

    half_x_kernel<<<(GM * GK) / 2048, 256>>>(x, xh);
    half_wt_kernel<<<dim3(32, 32, 6), 256>>>(Wq, Wk, Wv, WgK, WgC, Wo, wth);

    gemm_fp16<<<dim3(GN / 256, GM / 128, 5), 256, GEMM2_SMEM>>>(
        xh, wth, bgK, bgC, proj, 1);

    scan_chunked<<<128, 256, SCAN_SMEM_BYTES>>>(proj, proj + PS, proj + 2 * PS,
                                                proj + 3 * PS, proj + 4 * PS, o2dh);

    gemm_fp16<<<dim3(GN / 256, GM / 128, 1), 256, GEMM2_SMEM>>>(
        o2dh, wth + (size_t)5 * GN * GK, nullptr, nullptr, out, 0);
}

// round 12
// speedup vs baseline: 4.0188x; 1.0408x over previous
#include <cuda_runtime.h>
#include <cuda_fp16.h>
#include <math.h>
#include <stdint.h>

#define TSZ 2048
#define HN  16
#define DH  64
#define CL  64
#define NCHUNK 32
#define TS  72                  // fp32 staging stride (floats)
#define SH  72                  // half tile stride (halves)

#define GM 8192
#define GN 1024
#define GK 1024

// Scratch
__device__ float  g_proj[5][(size_t)64 * TSZ * DH];   // 5 * 32 MB
__device__ __half g_o2dh[(size_t)GM * GN];            // 16 MB
__device__ __half g_xh[(size_t)GM * GK];              // 16 MB
__device__ __half g_wth[6][(size_t)GN * GK];          // 12 MB  W^T [z][n][k]

__device__ __forceinline__ void ldsm_x4(unsigned& r0, unsigned& r1,
                                        unsigned& r2, unsigned& r3,
                                        uint32_t addr) {
    asm volatile("ldmatrix.sync.aligned.m8n8.x4.shared.b16 {%0,%1,%2,%3}, [%4];"
                 : "=r"(r0), "=r"(r1), "=r"(r2), "=r"(r3) : "r"(addr));
}
__device__ __forceinline__ void ldsm_x2(unsigned& r0, unsigned& r1,
                                        uint32_t addr) {
    asm volatile("ldmatrix.sync.aligned.m8n8.x2.shared.b16 {%0,%1}, [%2];"
                 : "=r"(r0), "=r"(r1) : "r"(addr));
}

// ---------------------------------------------------------------------------
// Prep: fp16(x) and fp16(W^T).
// ---------------------------------------------------------------------------
__global__ __launch_bounds__(256) void half_x_kernel(
    const float* __restrict__ x, __half* __restrict__ xh)
{
    size_t i = ((size_t)blockIdx.x * 256 + threadIdx.x) * 8;
    float4 v0 = *(const float4*)(x + i);
    float4 v1 = *(const float4*)(x + i + 4);
    __half2 h[4];
    h[0] = __floats2half2_rn(v0.x, v0.y);
    h[1] = __floats2half2_rn(v0.z, v0.w);
    h[2] = __floats2half2_rn(v1.x, v1.y);
    h[3] = __floats2half2_rn(v1.z, v1.w);
    *(uint4*)(xh + i) = *(uint4*)h;
}

__global__ __launch_bounds__(256) void half_wt_kernel(
    const float* __restrict__ Wq, const float* __restrict__ Wk,
    const float* __restrict__ Wv, const float* __restrict__ WgK,
    const float* __restrict__ WgC, const float* __restrict__ Wo,
    __half* __restrict__ wth)
{
    __shared__ float tile[32][33];
    const int z = blockIdx.z;
    const float* W = (z == 0) ? Wq : (z == 1) ? Wk : (z == 2) ? Wv
                   : (z == 3) ? WgK : (z == 4) ? WgC : Wo;
    const int n0 = blockIdx.x * 32, k0 = blockIdx.y * 32;
    const int tx = threadIdx.x & 31, ty = threadIdx.x >> 5;
#pragma unroll
    for (int i = 0; i < 4; i++)
        tile[ty + i * 8][tx] = W[(size_t)(k0 + ty + i * 8) * GN + n0 + tx];
    __syncthreads();
    __half* dst = wth + (size_t)z * GN * GK;
#pragma unroll
    for (int i = 0; i < 4; i++)
        dst[(size_t)(n0 + ty + i * 8) * GK + k0 + tx] =
            __float2half_rn(tile[tx][ty + i * 8]);
}

// ---------------------------------------------------------------------------
// FP16 mma GEMM with ldmatrix fragments (round-11, unchanged).
// ---------------------------------------------------------------------------
#define AST2 72
#define BST2 72
#define AS2_EL (128 * AST2)
#define BS2_EL (256 * BST2)
#define GEMM2_SMEM ((2 * (AS2_EL + BS2_EL)) * (int)sizeof(__half))

__device__ __forceinline__ void gemm2_fill(const __half* __restrict__ A,
                                           const __half* __restrict__ BT,
                                           int rowBase, int colBase, int tid,
                                           __half* AsD, __half* BsD, int kt)
{
    const int k0 = kt * 64;
#pragma unroll
    for (int i = 0; i < 4; i++) {
        const int id = tid + i * 256;
        const int r = id >> 3, c = (id & 7) * 8;
        const __half* src = A + (size_t)(rowBase + r) * GK + k0 + c;
        unsigned dst = (unsigned)__cvta_generic_to_shared(AsD + r * AST2 + c);
        asm volatile("cp.async.cg.shared.global [%0], [%1], 16;" :: "r"(dst), "l"(src));
    }
#pragma unroll
    for (int i = 0; i < 8; i++) {
        const int id = tid + i * 256;
        const int r = id >> 3, c = (id & 7) * 8;
        const __half* src = BT + (size_t)(colBase + r) * GK + k0 + c;
        unsigned dst = (unsigned)__cvta_generic_to_shared(BsD + r * BST2 + c);
        asm volatile("cp.async.cg.shared.global [%0], [%1], 16;" :: "r"(dst), "l"(src));
    }
    asm volatile("cp.async.commit_group;");
}

__global__ __launch_bounds__(256, 1) void gemm_fp16(
    const __half* __restrict__ A, const __half* __restrict__ WTall,
    const float* __restrict__ b3, const float* __restrict__ b4,
    float* __restrict__ Cb, int multi)
{
    extern __shared__ __half smem[];
    __half* AsB = smem;
    __half* BsB = smem + 2 * AS2_EL;

    const int tid  = threadIdx.x;
    const int lane = tid & 31;
    const int warpId = tid >> 5;
    const int wm = warpId & 1;
    const int wn = warpId >> 1;
    const int g  = lane >> 2;
    const int tg = lane & 3;
    const int rowBase = blockIdx.y * 128;
    const int colBase = blockIdx.x * 256;

    const uint32_t laneAoff =
        (uint32_t)((((lane & 15) * AST2) + ((lane >> 4) << 3)) * 2);
    const int brow = (lane & 7) + ((lane >> 4) << 3);
    const int bko  = ((lane >> 3) & 1) << 3;
    const uint32_t laneBoff = (uint32_t)((brow * BST2 + bko) * 2);

    const __half* BT; const float* bias; float* C; int mode;
    if (multi) {
        const int z = blockIdx.z;
        BT = WTall + (size_t)z * GN * GK;
        bias = (z == 3) ? b3 : (z == 4) ? b4 : nullptr;
        C = Cb + (size_t)z * ((size_t)64 * TSZ * DH);
        mode = (z >= 3) ? 2 : 1;
    } else {
        BT = WTall; bias = nullptr; C = Cb; mode = 0;
    }

    float acc[4][8][4];
#pragma unroll
    for (int i = 0; i < 4; i++)
#pragma unroll
        for (int j = 0; j < 8; j++)
#pragma unroll
            for (int e = 0; e < 4; e++) acc[i][j][e] = 0.f;

    gemm2_fill(A, BT, rowBase, colBase, tid, AsB, BsB, 0);

    const int KT = GK / 64;
    for (int kt = 0; kt < KT; kt++) {
        const int cur = kt & 1;
        asm volatile("cp.async.wait_group 0;");
        __syncthreads();
        if (kt + 1 < KT)
            gemm2_fill(A, BT, rowBase, colBase, tid,
                       AsB + (cur ^ 1) * AS2_EL, BsB + (cur ^ 1) * BS2_EL, kt + 1);

        const __half* As = AsB + cur * AS2_EL;
        const __half* Bs = BsB + cur * BS2_EL;
        const uint32_t asb = (uint32_t)__cvta_generic_to_shared(As)
                           + (uint32_t)(wm * 64 * AST2 * 2) + laneAoff;
        const uint32_t bsb = (uint32_t)__cvta_generic_to_shared(Bs)
                           + (uint32_t)(wn * 64 * BST2 * 2) + laneBoff;

        unsigned af[2][4][4], bf[2][8][2];
#pragma unroll
        for (int mi = 0; mi < 4; mi++)
            ldsm_x4(af[0][mi][0], af[0][mi][1], af[0][mi][2], af[0][mi][3],
                    asb + mi * 16 * AST2 * 2);
#pragma unroll
        for (int j = 0; j < 4; j++)
            ldsm_x4(bf[0][2 * j][0], bf[0][2 * j][1],
                    bf[0][2 * j + 1][0], bf[0][2 * j + 1][1],
                    bsb + j * 16 * BST2 * 2);

#pragma unroll
        for (int kk = 0; kk < 4; kk++) {
            const int cb = kk & 1, nx = cb ^ 1;
            if (kk < 3) {
                const uint32_t kb2 = (kk + 1) * 32;
#pragma unroll
                for (int mi = 0; mi < 4; mi++)
                    ldsm_x4(af[nx][mi][0], af[nx][mi][1],
                            af[nx][mi][2], af[nx][mi][3],
                            asb + mi * 16 * AST2 * 2 + kb2);
#pragma unroll
                for (int j = 0; j < 4; j++)
                    ldsm_x4(bf[nx][2 * j][0], bf[nx][2 * j][1],
                            bf[nx][2 * j + 1][0], bf[nx][2 * j + 1][1],
                            bsb + j * 16 * BST2 * 2 + kb2);
            }
#pragma unroll
            for (int ni = 0; ni < 8; ni++)
#pragma unroll
                for (int mi = 0; mi < 4; mi++) {
                    asm volatile(
                        "mma.sync.aligned.m16n8k16.row.col.f32.f16.f16.f32 "
                        "{%0,%1,%2,%3}, {%4,%5,%6,%7}, {%8,%9}, {%0,%1,%2,%3};\n"
                        : "+f"(acc[mi][ni][0]), "+f"(acc[mi][ni][1]),
                          "+f"(acc[mi][ni][2]), "+f"(acc[mi][ni][3])
                        : "r"(af[cb][mi][0]), "r"(af[cb][mi][1]),
                          "r"(af[cb][mi][2]), "r"(af[cb][mi][3]),
                          "r"(bf[cb][ni][0]), "r"(bf[cb][ni][1]));
                }
        }
    }

#pragma unroll
    for (int mi = 0; mi < 4; mi++) {
        const int gr0 = rowBase + wm * 64 + mi * 16 + g;
#pragma unroll
        for (int ni = 0; ni < 8; ni++) {
            const int gc = colBase + wn * 64 + ni * 8 + 2 * tg;
#pragma unroll
            for (int half = 0; half < 2; half++) {
                const int gr = gr0 + 8 * half;
                float v0 = acc[mi][ni][2 * half];
                float v1 = acc[mi][ni][2 * half + 1];
                if (mode == 0) {
                    *(float2*)&C[(size_t)gr * GN + gc] = make_float2(v0, v1);
                } else {
                    if (mode == 2) {
                        v0 = 1.f / (1.f + __expf(-(v0 + bias[gc])));
                        v1 = 1.f / (1.f + __expf(-(v1 + bias[gc + 1])));
                    }
                    const int b = gr >> 11, t = gr & 2047;
                    const int h = gc >> 6,  d = gc & 63;
                    *(float2*)&C[((size_t)((b * HN + h) * TSZ + t)) * DH + d] =
                        make_float2(v0, v1);
                }
            }
        }
    }
}

// ---------------------------------------------------------------------------
// Chunked scan, dv-split, fp16 mma + ldmatrix, 512 threads,
// warp-group task parallelism (wg0 / wg1 run independent matmuls per phase).
// ---------------------------------------------------------------------------
#define O_QF   0
#define O_KF   18432
#define O_AKF  36864
#define O_ACF  55296
#define O_SF   73728
#define O_CTF  92160
#define O_GTF  101376
#define HB     110592
#define O_QH   (HB + 0)
#define O_KH   (HB + 9216)
#define O_QT   (HB + 18432)
#define O_QTT  (HB + 27648)
#define O_KT   (HB + 36864)
#define O_KTT  (HB + 46080)
#define O_PH   (HB + 55296)
#define O_RS   (HB + 64512)
#define O_UH   (HB + 73728)
#define O_SHH  (HB + 82944)
#define O_VT   (HB + 92160)
#define O_KCT  (HB + 96768)
#define O_CTH  (HB + 101376)
#define O_GTH  (HB + 105984)
#define SCAN_SMEM_BYTES (HB + 110592)

template<int NI>
__device__ __forceinline__ void zacc(float (&acc)[NI][4]) {
#pragma unroll
    for (int i = 0; i < NI; i++)
#pragma unroll
        for (int j = 0; j < 4; j++) acc[i][j] = 0.f;
}

// acc(16 x NI*8) += A(16x64) @ B(64 x NI*8); A [m][k], B [n][k], stride SH.
template<int NI, bool NEGA>
__device__ __forceinline__ void mmh(const __half* __restrict__ A,
                                    const __half* __restrict__ B,
                                    float (&acc)[NI][4],
                                    int lane, int mb, int nb)
{
    const uint32_t abase = (uint32_t)__cvta_generic_to_shared(
        A + (mb + (lane & 15)) * SH + ((lane >> 4) << 3));
    const int brow = (lane & 7) + ((lane >> 4) << 3);
    const int bko  = ((lane >> 3) & 1) << 3;
    const uint32_t bbase = (uint32_t)__cvta_generic_to_shared(
        B + (nb + brow) * SH + bko);
#pragma unroll
    for (int kk = 0; kk < 4; kk++) {
        const uint32_t kb2 = kk * 32;
        unsigned a0, a1, a2, a3;
        ldsm_x4(a0, a1, a2, a3, abase + kb2);
        if (NEGA) {
            a0 ^= 0x80008000u; a1 ^= 0x80008000u;
            a2 ^= 0x80008000u; a3 ^= 0x80008000u;
        }
#pragma unroll
        for (int j = 0; j < NI / 2; j++) {
            unsigned b0, b1, b2, b3;
            ldsm_x4(b0, b1, b2, b3, bbase + (uint32_t)(j * 16 * SH * 2) + kb2);
            asm volatile(
                "mma.sync.aligned.m16n8k16.row.col.f32.f16.f16.f32 "
                "{%0,%1,%2,%3}, {%4,%5,%6,%7}, {%8,%9}, {%0,%1,%2,%3};\n"
                : "+f"(acc[2 * j][0]), "+f"(acc[2 * j][1]),
                  "+f"(acc[2 * j][2]), "+f"(acc[2 * j][3])
                : "r"(a0), "r"(a1), "r"(a2), "r"(a3), "r"(b0), "r"(b1));
            asm volatile(
                "mma.sync.aligned.m16n8k16.row.col.f32.f16.f16.f32 "
                "{%0,%1,%2,%3}, {%4,%5,%6,%7}, {%8,%9}, {%0,%1,%2,%3};\n"
                : "+f"(acc[2 * j + 1][0]), "+f"(acc[2 * j + 1][1]),
                  "+f"(acc[2 * j + 1][2]), "+f"(acc[2 * j + 1][3])
                : "r"(a0), "r"(a1), "r"(a2), "r"(a3), "r"(b2), "r"(b3));
        }
    }
}

// 16x8 output tile variant (NI=1): A via ldsm.x4, B via ldsm.x2.
template<bool NEGA>
__device__ __forceinline__ void mmh1(const __half* __restrict__ A,
                                     const __half* __restrict__ B,
                                     float (&acc)[4],
                                     int lane, int mb, int nb)
{
    const uint32_t abase = (uint32_t)__cvta_generic_to_shared(
        A + (mb + (lane & 15)) * SH + ((lane >> 4) << 3));
    const uint32_t bbase = (uint32_t)__cvta_generic_to_shared(
        B + (nb + (lane & 7)) * SH + (((lane >> 3) & 1) << 3));
#pragma unroll
    for (int kk = 0; kk < 4; kk++) {
        const uint32_t kb2 = kk * 32;
        unsigned a0, a1, a2, a3;
        ldsm_x4(a0, a1, a2, a3, abase + kb2);
        if (NEGA) {
            a0 ^= 0x80008000u; a1 ^= 0x80008000u;
            a2 ^= 0x80008000u; a3 ^= 0x80008000u;
        }
        unsigned b0, b1;
        ldsm_x2(b0, b1, bbase + kb2);
        asm volatile(
            "mma.sync.aligned.m16n8k16.row.col.f32.f16.f16.f32 "
            "{%0,%1,%2,%3}, {%4,%5,%6,%7}, {%8,%9}, {%0,%1,%2,%3};\n"
            : "+f"(acc[0]), "+f"(acc[1]), "+f"(acc[2]), "+f"(acc[3])
            : "r"(a0), "r"(a1), "r"(a2), "r"(a3), "r"(b0), "r"(b1));
    }
}

template<int NI, int MASK, bool SCALE>
__device__ __forceinline__ void storeH(__half* __restrict__ O,
    const float* __restrict__ scl, float (&acc)[NI][4],
    int g, int tg, int mb, int nb)
{
#pragma unroll
    for (int ni = 0; ni < NI; ni++) {
        const int c0 = nb + ni * 8 + 2 * tg;
#pragma unroll
        for (int hh = 0; hh < 2; hh++) {
            const int r = mb + g + 8 * hh;
#pragma unroll
            for (int e = 0; e < 2; e++) {
                const int c = c0 + e;
                float v = acc[ni][2 * hh + e];
                if (MASK == 1 && c > r)  v = 0.f;
                if (MASK == 2 && c >= r) v = 0.f;
                if (SCALE) v *= scl[r * TS + c];
                O[r * SH + c] = __float2half_rn(v);
            }
        }
    }
}

template<int NI>
__device__ __forceinline__ void storeHT(__half* __restrict__ O,
    float (&acc)[NI][4], int g, int tg, int mb, int nb)
{
#pragma unroll
    for (int ni = 0; ni < NI; ni++) {
        const int c0 = nb + ni * 8 + 2 * tg;
#pragma unroll
        for (int hh = 0; hh < 2; hh++) {
            const int r = mb + g + 8 * hh;
#pragma unroll
            for (int e = 0; e < 2; e++)
                O[(c0 + e) * SH + r] = __float2half_rn(acc[ni][2 * hh + e]);
        }
    }
}

template<int NI>
__device__ __forceinline__ void updateS(float* __restrict__ Sf,
    __half* __restrict__ Sh, const float* __restrict__ rs,
    float (&acc)[NI][4], int g, int tg, int mb, int nb)
{
#pragma unroll
    for (int ni = 0; ni < NI; ni++) {
        const int c0 = nb + ni * 8 + 2 * tg;
#pragma unroll
        for (int hh = 0; hh < 2; hh++) {
            const int r = mb + g + 8 * hh;
            const float rr = rs[r];
#pragma unroll
            for (int e = 0; e < 2; e++) {
                const int c = c0 + e;
                float v = rr * rs[c] * (Sf[r * TS + c] + acc[ni][2 * hh + e]);
                Sf[r * TS + c] = v;
                Sh[r * SH + c] = __float2half_rn(v);
            }
        }
    }
}

template<int NI>
__device__ __forceinline__ void updateT(float* __restrict__ Tf,
    __half* __restrict__ Th, const float* __restrict__ rs,
    float (&acc)[NI][4], int g, int tg, int mb, int nb)
{
#pragma unroll
    for (int ni = 0; ni < NI; ni++) {
        const int c0 = nb + ni * 8 + 2 * tg;
#pragma unroll
        for (int hh = 0; hh < 2; hh++) {
            const int r = mb + g + 8 * hh;
#pragma unroll
            for (int e = 0; e < 2; e++) {
                const int c = c0 + e;
                float v = rs[c] * (Tf[r * TS + c] + acc[ni][2 * hh + e]);
                Tf[r * TS + c] = v;
                Th[r * SH + c] = __float2half_rn(v);
            }
        }
    }
}

__device__ __forceinline__ void load_tile64_512(float* __restrict__ dst,
    const float* __restrict__ src, int tid)
{
#pragma unroll
    for (int i = 0; i < 2; i++) {
        const int e = (tid + i * 512) * 4;
        const int r = e >> 6, c = e & 63;
        *(float4*)(dst + r * TS + c) = *(const float4*)(src + e);
    }
}

__global__ __launch_bounds__(512) void scan_chunked(
    const float* __restrict__ qp, const float* __restrict__ kp,
    const float* __restrict__ vp, const float* __restrict__ aKp,
    const float* __restrict__ aCp, __half* __restrict__ o2dh)
{
    extern __shared__ char smc[];
    float*  Qf  = (float*)(smc + O_QF);
    float*  Kf  = (float*)(smc + O_KF);
    float*  AKf = (float*)(smc + O_AKF);
    float*  ACf = (float*)(smc + O_ACF);
    float*  Sf  = (float*)(smc + O_SF);
    float*  CTf = (float*)(smc + O_CTF);
    float*  GTf = (float*)(smc + O_GTF);
    __half* Qh  = (__half*)(smc + O_QH);
    __half* Kh  = (__half*)(smc + O_KH);
    __half* Qt  = (__half*)(smc + O_QT);
    __half* QtT = (__half*)(smc + O_QTT);
    __half* Kt  = (__half*)(smc + O_KT);
    __half* KtT = (__half*)(smc + O_KTT);
    __half* Ph  = (__half*)(smc + O_PH);
    __half* RSc = (__half*)(smc + O_RS);
    __half* Uh  = (__half*)(smc + O_UH);
    __half* Sh  = (__half*)(smc + O_SHH);
    __half* VT  = (__half*)(smc + O_VT);
    __half* KCT = (__half*)(smc + O_KCT);
    __half* CTh = (__half*)(smc + O_CTH);
    __half* GTh = (__half*)(smc + O_GTH);
    __shared__ float aKL[64], aCL[64];

    const int bh   = blockIdx.x >> 1;
    const int half = blockIdx.x & 1;
    const int b = bh >> 4, h = bh & 15;
    const size_t base = (size_t)bh * TSZ * DH;
    const int tid  = threadIdx.x;
    const int lane = tid & 31, w = tid >> 5;          // w 0..15
    const int wg = w >> 3, w8 = w & 7;
    const int g = lane >> 2, tg = lane & 3;
    const int mb4 = (w8 & 3) * 16, nb4 = (w8 >> 2) * 32;  // 64x64, 8 warps
    const int mb2 = (w8 & 3) * 16, nb2 = (w8 >> 2) * 16;  // 64x32, 8 warps
    const int mbF = (w8 & 1) * 16, nbF = (w8 >> 1) * 16;  // 32x64, 8 warps
    const int mbO = (w & 3) * 16,  nbO = (w >> 2) * 8;    // 64x32, 16 warps

    for (int i = tid; i < 9216; i += 512) ((uint32_t*)(smc + O_SF))[i] = 0;
    for (int i = tid; i < 2304; i += 512) ((uint32_t*)(smc + O_SHH))[i] = 0;
    for (int i = tid; i < 2304; i += 512) ((uint32_t*)(smc + O_CTH))[i] = 0;
    __syncthreads();

    for (int ch = 0; ch < NCHUNK; ch++) {
        const size_t off = base + (size_t)ch * CL * DH;
        load_tile64_512(Qf,  qp  + off, tid);
        load_tile64_512(Kf,  kp  + off, tid);
        load_tile64_512(AKf, aKp + off, tid);
        load_tile64_512(ACf, aCp + off, tid);
        {   // V half-column -> VT (transposed fp16); 512 threads x 4 floats
            const int r = tid >> 3, c4 = (tid & 7) * 4;
            float4 v = *(const float4*)(vp + off + r * DH + half * 32 + c4);
            VT[(c4 + 0) * SH + r] = __float2half_rn(v.x);
            VT[(c4 + 1) * SH + r] = __float2half_rn(v.y);
            VT[(c4 + 2) * SH + r] = __float2half_rn(v.z);
            VT[(c4 + 3) * SH + r] = __float2half_rn(v.w);
        }
        __syncthreads();

        // cumulative products: 2 tensors x 4 segments of 16 rows x 64 cols
        {
            float* Tt = (tid < 256) ? AKf : ACf;
            const int col = tid & 63;
            const int seg = (tid >> 6) & 3;
            const int r0 = seg * 16;
            float p = 1.f;
#pragma unroll
            for (int r = 0; r < 16; r++) {
                p *= Tt[(r0 + r) * TS + col];
                Tt[(r0 + r) * TS + col] = p;
            }
            __syncthreads();
            float pref = 1.f;
#pragma unroll
            for (int s = 0; s < 3; s++)
                if (s < seg) pref *= Tt[(s * 16 + 15) * TS + col];
            __syncthreads();
            if (seg > 0) {
#pragma unroll
                for (int r = 0; r < 16; r++) Tt[(r0 + r) * TS + col] *= pref;
            }
        }
        __syncthreads();

        // derive fp16 operand tiles (+ SCL fp32 in AKf slot)
#pragma unroll
        for (int i = 0; i < 8; i++) {
            const int e = tid + i * 512;
            const int r = e >> 6, c = e & 63;
            const int idx = r * TS + c;
            const float ak = AKf[idx], ac = ACf[idx];
            const float qv = Qf[idx],  kv = Kf[idx];
            if (r == 63) { aKL[c] = ak; aCL[c] = ac; }
            const float qh = qv * ak, kt = kv / ak;
            const float qt = qv / ac, kh = kv * ac;
            Qh[r * SH + c]  = __float2half_rn(qh);
            Kh[r * SH + c]  = __float2half_rn(kh);
            Qt[r * SH + c]  = __float2half_rn(qt);
            QtT[c * SH + r] = __float2half_rn(qt);
            Kt[r * SH + c]  = __float2half_rn(kt);
            KtT[c * SH + r] = __float2half_rn(kt);
            AKf[idx] = ak * ac;          // SCL
        }
        __syncthreads();

        float acc4[4][4];
        float acc2[2][4];

        // Phase A: wg0: R = strict(Kh @ Qt^T) -> RSc ;
        //          wg1: P = incl(Qh @ Kt^T)  -> Ph
        if (wg == 0) {
            zacc(acc4);
            mmh<4, false>(Kh, Qt, acc4, lane, mb4, nb4);
            storeH<4, 2, false>(RSc, nullptr, acc4, g, tg, mb4, nb4);
        } else {
            zacc(acc4);
            mmh<4, false>(Qh, Kt, acc4, lane, mb4, nb4);
            storeH<4, 1, false>(Ph, nullptr, acc4, g, tg, mb4, nb4);
        }
        __syncthreads();

        // Phase B: wg0: KC = Kh@C0 + R@V -> KCT (transposed) ;
        //          wg1: Uhat = (Qh@S0 + P@Kt)*SCL -> Uh
        if (wg == 0) {
            zacc(acc2);
            mmh<2, false>(Kh,  CTh, acc2, lane, mb2, nb2);
            mmh<2, false>(RSc, VT,  acc2, lane, mb2, nb2);
            storeHT<2>(KCT, acc2, g, tg, mb2, nb2);
        } else {
            zacc(acc4);
            mmh<4, false>(Qh, Sh,  acc4, lane, mb4, nb4);
            mmh<4, false>(Ph, KtT, acc4, lane, mb4, nb4);
            storeH<4, 0, true>(Uh, AKf, acc4, g, tg, mb4, nb4);
        }
        __syncthreads();

        // Phase C: wg0: Sc2 = incl(Uh @ Qt^T) -> RSc ;
        //          wg1: S state update (Kt^T @ Kt, updateS)
        if (wg == 0) {
            zacc(acc4);
            mmh<4, false>(Uh, Qt, acc4, lane, mb4, nb4);
            storeH<4, 1, false>(RSc, nullptr, acc4, g, tg, mb4, nb4);
        } else {
            zacc(acc4);
            mmh<4, false>(KtT, KtT, acc4, lane, mb4, nb4);
            updateS<4>(Sf, Sh, aKL, acc4, g, tg, mb4, nb4);
        }
        __syncthreads();

        // Phase E: all 16 warps: O = Uh@C0 + Sc2@V - Qh@G0 - P@KC -> gmem
        {
            float accO[4] = {0.f, 0.f, 0.f, 0.f};
            mmh1<false>(Uh,  CTh, accO, lane, mbO, nbO);
            mmh1<false>(RSc, VT,  accO, lane, mbO, nbO);
            mmh1<true >(Qh,  GTh, accO, lane, mbO, nbO);
            mmh1<true >(Ph,  KCT, accO, lane, mbO, nbO);
            const int t0 = ch * CL;
            const int c0 = nbO + 2 * tg;
#pragma unroll
            for (int hh = 0; hh < 2; hh++) {
                const int r = mbO + g + 8 * hh;
                __half2 st = __floats2half2_rn(accO[2 * hh], accO[2 * hh + 1]);
                *(__half2*)&o2dh[(size_t)(b * TSZ + t0 + r) * 1024 +
                                 h * DH + half * 32 + c0] = st;
            }
        }
        __syncthreads();

        // Phase F: wg0: C state update (V^T@Qt) ; wg1: G state update (KC^T@Kt)
        if (wg == 0) {
            zacc(acc2);
            mmh<2, false>(VT, QtT, acc2, lane, mbF, nbF);
            updateT<2>(CTf, CTh, aCL, acc2, g, tg, mbF, nbF);
        } else {
            zacc(acc2);
            mmh<2, false>(KCT, KtT, acc2, lane, mbF, nbF);
            updateT<2>(GTf, GTh, aKL, acc2, g, tg, mbF, nbF);
        }
        __syncthreads();
    }
}

// ---------------------------------------------------------------------------
extern "C" void kernel_launch(void* const* d_in, const int* in_sizes, int n_in,
                              void* d_out, int out_size)
{
    const float* x   = (const float*)d_in[0];
    const float* Wq  = (const float*)d_in[1];
    const float* Wk  = (const float*)d_in[2];
    const float* Wv  = (const float*)d_in[3];
    const float* WgK = (const float*)d_in[4];
    const float* bgK = (const float*)d_in[5];
    const float* WgC = (const float*)d_in[6];
    const float* bgC = (const float*)d_in[7];
    const float* Wo  = (const float*)d_in[8];
    float* out = (float*)d_out;

    float *proj = nullptr;
    __half *o2dh = nullptr, *xh = nullptr, *wth = nullptr;
    cudaGetSymbolAddress((void**)&proj, g_proj);
    cudaGetSymbolAddress((void**)&o2dh, g_o2dh);
    cudaGetSymbolAddress((void**)&xh,   g_xh);
    cudaGetSymbolAddress((void**)&wth,  g_wth);
    const size_t PS = (size_t)64 * TSZ * DH;

    cudaFuncSetAttribute(gemm_fp16,
                         cudaFuncAttributeMaxDynamicSharedMemorySize,
                         GEMM2_SMEM);
    cudaFuncSetAttribute(scan_chunked,
                         cudaFuncAttributeMaxDynamicSharedMemorySize,
                         SCAN_SMEM_BYTES);

    half_x_kernel<<<(GM * GK) / 2048, 256>>>(x, xh);
    half_wt_kernel<<<dim3(32, 32, 6), 256>>>(Wq, Wk, Wv, WgK, WgC, Wo, wth);

    gemm_fp16<<<dim3(GN / 256, GM / 128, 5), 256, GEMM2_SMEM>>>(
        xh, wth, bgK, bgC, proj, 1);

    scan_chunked<<<128, 512, SCAN_SMEM_BYTES>>>(proj, proj + PS, proj + 2 * PS,
                                                proj + 3 * PS, proj + 4 * PS, o2dh);

    gemm_fp16<<<dim3(GN / 256, GM / 128, 1), 256, GEMM2_SMEM>>>(
        o2dh, wth + (size_t)5 * GN * GK, nullptr, nullptr, out, 0);
}

// round 13
// speedup vs baseline: 4.4302x; 1.1024x over previous
#include <cuda_runtime.h>
#include <cuda_fp16.h>
#include <math.h>
#include <stdint.h>

#define TSZ 2048
#define HN  16
#define DH  64
#define CL  64
#define NCHUNK 32
#define TS  72                  // fp32 staging stride (floats)
#define SH  72                  // half tile stride (halves)

#define GM 8192
#define GN 1024
#define GK 1024

// Scratch
__device__ float  g_proj[5][(size_t)64 * TSZ * DH];   // 5 * 32 MB
__device__ __half g_o2dh[(size_t)GM * GN];            // 16 MB
__device__ __half g_xh[(size_t)GM * GK];              // 16 MB
__device__ __half g_wth[6][(size_t)GN * GK];          // 12 MB  W^T [z][n][k]

__device__ __forceinline__ void ldsm_x4(unsigned& r0, unsigned& r1,
                                        unsigned& r2, unsigned& r3,
                                        uint32_t addr) {
    asm volatile("ldmatrix.sync.aligned.m8n8.x4.shared.b16 {%0,%1,%2,%3}, [%4];"
                 : "=r"(r0), "=r"(r1), "=r"(r2), "=r"(r3) : "r"(addr));
}
__device__ __forceinline__ void ldsm_x2(unsigned& r0, unsigned& r1,
                                        uint32_t addr) {
    asm volatile("ldmatrix.sync.aligned.m8n8.x2.shared.b16 {%0,%1}, [%2];"
                 : "=r"(r0), "=r"(r1) : "r"(addr));
}

// ---------------------------------------------------------------------------
// Prep: fp16(x) and fp16(W^T).
// ---------------------------------------------------------------------------
__global__ __launch_bounds__(256) void half_x_kernel(
    const float* __restrict__ x, __half* __restrict__ xh)
{
    size_t i = ((size_t)blockIdx.x * 256 + threadIdx.x) * 8;
    float4 v0 = *(const float4*)(x + i);
    float4 v1 = *(const float4*)(x + i + 4);
    __half2 h[4];
    h[0] = __floats2half2_rn(v0.x, v0.y);
    h[1] = __floats2half2_rn(v0.z, v0.w);
    h[2] = __floats2half2_rn(v1.x, v1.y);
    h[3] = __floats2half2_rn(v1.z, v1.w);
    *(uint4*)(xh + i) = *(uint4*)h;
}

__global__ __launch_bounds__(256) void half_wt_kernel(
    const float* __restrict__ Wq, const float* __restrict__ Wk,
    const float* __restrict__ Wv, const float* __restrict__ WgK,
    const float* __restrict__ WgC, const float* __restrict__ Wo,
    __half* __restrict__ wth)
{
    __shared__ float tile[32][33];
    const int z = blockIdx.z;
    const float* W = (z == 0) ? Wq : (z == 1) ? Wk : (z == 2) ? Wv
                   : (z == 3) ? WgK : (z == 4) ? WgC : Wo;
    const int n0 = blockIdx.x * 32, k0 = blockIdx.y * 32;
    const int tx = threadIdx.x & 31, ty = threadIdx.x >> 5;
#pragma unroll
    for (int i = 0; i < 4; i++)
        tile[ty + i * 8][tx] = W[(size_t)(k0 + ty + i * 8) * GN + n0 + tx];
    __syncthreads();
    __half* dst = wth + (size_t)z * GN * GK;
#pragma unroll
    for (int i = 0; i < 4; i++)
        dst[(size_t)(n0 + ty + i * 8) * GK + k0 + tx] =
            __float2half_rn(tile[tx][ty + i * 8]);
}

// ---------------------------------------------------------------------------
// FP16 mma GEMM, 512 threads (16 warps = 2m x 8n, warp tile 64x32).
// CTA 128x256, ktile 64 halves, cp.async double-buffered smem, ldmatrix
// fragments (single-buffered; 16 warps hide the latency).
// ---------------------------------------------------------------------------
#define AST2 72
#define BST2 72
#define AS2_EL (128 * AST2)
#define BS2_EL (256 * BST2)
#define GEMM2_SMEM ((2 * (AS2_EL + BS2_EL)) * (int)sizeof(__half))

__device__ __forceinline__ void gemm2_fill(const __half* __restrict__ A,
                                           const __half* __restrict__ BT,
                                           int rowBase, int colBase, int tid,
                                           __half* AsD, __half* BsD, int kt)
{
    const int k0 = kt * 64;
#pragma unroll
    for (int i = 0; i < 2; i++) {
        const int id = tid + i * 512;
        const int r = id >> 3, c = (id & 7) * 8;
        const __half* src = A + (size_t)(rowBase + r) * GK + k0 + c;
        unsigned dst = (unsigned)__cvta_generic_to_shared(AsD + r * AST2 + c);
        asm volatile("cp.async.cg.shared.global [%0], [%1], 16;" :: "r"(dst), "l"(src));
    }
#pragma unroll
    for (int i = 0; i < 4; i++) {
        const int id = tid + i * 512;
        const int r = id >> 3, c = (id & 7) * 8;
        const __half* src = BT + (size_t)(colBase + r) * GK + k0 + c;
        unsigned dst = (unsigned)__cvta_generic_to_shared(BsD + r * BST2 + c);
        asm volatile("cp.async.cg.shared.global [%0], [%1], 16;" :: "r"(dst), "l"(src));
    }
    asm volatile("cp.async.commit_group;");
}

__global__ __launch_bounds__(512, 1) void gemm_fp16(
    const __half* __restrict__ A, const __half* __restrict__ WTall,
    const float* __restrict__ b3, const float* __restrict__ b4,
    float* __restrict__ Cb, int multi)
{
    extern __shared__ __half smem[];
    __half* AsB = smem;
    __half* BsB = smem + 2 * AS2_EL;

    const int tid  = threadIdx.x;
    const int lane = tid & 31;
    const int warpId = tid >> 5;       // 0..15
    const int wm = warpId & 1;
    const int wn = warpId >> 1;        // 0..7
    const int g  = lane >> 2;
    const int tg = lane & 3;
    const int rowBase = blockIdx.y * 128;
    const int colBase = blockIdx.x * 256;

    const uint32_t laneAoff =
        (uint32_t)((((lane & 15) * AST2) + ((lane >> 4) << 3)) * 2);
    const int brow = (lane & 7) + ((lane >> 4) << 3);
    const int bko  = ((lane >> 3) & 1) << 3;
    const uint32_t laneBoff = (uint32_t)((brow * BST2 + bko) * 2);

    const __half* BT; const float* bias; float* C; int mode;
    if (multi) {
        const int z = blockIdx.z;
        BT = WTall + (size_t)z * GN * GK;
        bias = (z == 3) ? b3 : (z == 4) ? b4 : nullptr;
        C = Cb + (size_t)z * ((size_t)64 * TSZ * DH);
        mode = (z >= 3) ? 2 : 1;
    } else {
        BT = WTall; bias = nullptr; C = Cb; mode = 0;
    }

    float acc[4][4][4];
#pragma unroll
    for (int i = 0; i < 4; i++)
#pragma unroll
        for (int j = 0; j < 4; j++)
#pragma unroll
            for (int e = 0; e < 4; e++) acc[i][j][e] = 0.f;

    gemm2_fill(A, BT, rowBase, colBase, tid, AsB, BsB, 0);

    const int KT = GK / 64;
    for (int kt = 0; kt < KT; kt++) {
        const int cur = kt & 1;
        asm volatile("cp.async.wait_group 0;");
        __syncthreads();
        if (kt + 1 < KT)
            gemm2_fill(A, BT, rowBase, colBase, tid,
                       AsB + (cur ^ 1) * AS2_EL, BsB + (cur ^ 1) * BS2_EL, kt + 1);

        const __half* As = AsB + cur * AS2_EL;
        const __half* Bs = BsB + cur * BS2_EL;
        const uint32_t asb = (uint32_t)__cvta_generic_to_shared(As)
                           + (uint32_t)(wm * 64 * AST2 * 2) + laneAoff;
        const uint32_t bsb = (uint32_t)__cvta_generic_to_shared(Bs)
                           + (uint32_t)(wn * 32 * BST2 * 2) + laneBoff;

#pragma unroll
        for (int kk = 0; kk < 4; kk++) {
            const uint32_t kb2 = kk * 32;   // bytes
            unsigned af[4][4], bf[4][2];
#pragma unroll
            for (int mi = 0; mi < 4; mi++)
                ldsm_x4(af[mi][0], af[mi][1], af[mi][2], af[mi][3],
                        asb + mi * 16 * AST2 * 2 + kb2);
#pragma unroll
            for (int j = 0; j < 2; j++)
                ldsm_x4(bf[2 * j][0], bf[2 * j][1],
                        bf[2 * j + 1][0], bf[2 * j + 1][1],
                        bsb + j * 16 * BST2 * 2 + kb2);
#pragma unroll
            for (int ni = 0; ni < 4; ni++)
#pragma unroll
                for (int mi = 0; mi < 4; mi++) {
                    asm volatile(
                        "mma.sync.aligned.m16n8k16.row.col.f32.f16.f16.f32 "
                        "{%0,%1,%2,%3}, {%4,%5,%6,%7}, {%8,%9}, {%0,%1,%2,%3};\n"
                        : "+f"(acc[mi][ni][0]), "+f"(acc[mi][ni][1]),
                          "+f"(acc[mi][ni][2]), "+f"(acc[mi][ni][3])
                        : "r"(af[mi][0]), "r"(af[mi][1]),
                          "r"(af[mi][2]), "r"(af[mi][3]),
                          "r"(bf[ni][0]), "r"(bf[ni][1]));
                }
        }
    }

#pragma unroll
    for (int mi = 0; mi < 4; mi++) {
        const int gr0 = rowBase + wm * 64 + mi * 16 + g;
#pragma unroll
        for (int ni = 0; ni < 4; ni++) {
            const int gc = colBase + wn * 32 + ni * 8 + 2 * tg;
#pragma unroll
            for (int half = 0; half < 2; half++) {
                const int gr = gr0 + 8 * half;
                float v0 = acc[mi][ni][2 * half];
                float v1 = acc[mi][ni][2 * half + 1];
                if (mode == 0) {
                    *(float2*)&C[(size_t)gr * GN + gc] = make_float2(v0, v1);
                } else {
                    if (mode == 2) {
                        v0 = 1.f / (1.f + __expf(-(v0 + bias[gc])));
                        v1 = 1.f / (1.f + __expf(-(v1 + bias[gc + 1])));
                    }
                    const int b = gr >> 11, t = gr & 2047;
                    const int h = gc >> 6,  d = gc & 63;
                    *(float2*)&C[((size_t)((b * HN + h) * TSZ + t)) * DH + d] =
                        make_float2(v0, v1);
                }
            }
        }
    }
}

// ---------------------------------------------------------------------------
// Chunked scan, dv-split, fp16 mma + ldmatrix, 512 threads,
// warp-group task parallelism (round-12 version, unchanged).
// ---------------------------------------------------------------------------
#define O_QF   0
#define O_KF   18432
#define O_AKF  36864
#define O_ACF  55296
#define O_SF   73728
#define O_CTF  92160
#define O_GTF  101376
#define HB     110592
#define O_QH   (HB + 0)
#define O_KH   (HB + 9216)
#define O_QT   (HB + 18432)
#define O_QTT  (HB + 27648)
#define O_KT   (HB + 36864)
#define O_KTT  (HB + 46080)
#define O_PH   (HB + 55296)
#define O_RS   (HB + 64512)
#define O_UH   (HB + 73728)
#define O_SHH  (HB + 82944)
#define O_VT   (HB + 92160)
#define O_KCT  (HB + 96768)
#define O_CTH  (HB + 101376)
#define O_GTH  (HB + 105984)
#define SCAN_SMEM_BYTES (HB + 110592)

template<int NI>
__device__ __forceinline__ void zacc(float (&acc)[NI][4]) {
#pragma unroll
    for (int i = 0; i < NI; i++)
#pragma unroll
        for (int j = 0; j < 4; j++) acc[i][j] = 0.f;
}

template<int NI, bool NEGA>
__device__ __forceinline__ void mmh(const __half* __restrict__ A,
                                    const __half* __restrict__ B,
                                    float (&acc)[NI][4],
                                    int lane, int mb, int nb)
{
    const uint32_t abase = (uint32_t)__cvta_generic_to_shared(
        A + (mb + (lane & 15)) * SH + ((lane >> 4) << 3));
    const int brow = (lane & 7) + ((lane >> 4) << 3);
    const int bko  = ((lane >> 3) & 1) << 3;
    const uint32_t bbase = (uint32_t)__cvta_generic_to_shared(
        B + (nb + brow) * SH + bko);
#pragma unroll
    for (int kk = 0; kk < 4; kk++) {
        const uint32_t kb2 = kk * 32;
        unsigned a0, a1, a2, a3;
        ldsm_x4(a0, a1, a2, a3, abase + kb2);
        if (NEGA) {
            a0 ^= 0x80008000u; a1 ^= 0x80008000u;
            a2 ^= 0x80008000u; a3 ^= 0x80008000u;
        }
#pragma unroll
        for (int j = 0; j < NI / 2; j++) {
            unsigned b0, b1, b2, b3;
            ldsm_x4(b0, b1, b2, b3, bbase + (uint32_t)(j * 16 * SH * 2) + kb2);
            asm volatile(
                "mma.sync.aligned.m16n8k16.row.col.f32.f16.f16.f32 "
                "{%0,%1,%2,%3}, {%4,%5,%6,%7}, {%8,%9}, {%0,%1,%2,%3};\n"
                : "+f"(acc[2 * j][0]), "+f"(acc[2 * j][1]),
                  "+f"(acc[2 * j][2]), "+f"(acc[2 * j][3])
                : "r"(a0), "r"(a1), "r"(a2), "r"(a3), "r"(b0), "r"(b1));
            asm volatile(
                "mma.sync.aligned.m16n8k16.row.col.f32.f16.f16.f32 "
                "{%0,%1,%2,%3}, {%4,%5,%6,%7}, {%8,%9}, {%0,%1,%2,%3};\n"
                : "+f"(acc[2 * j + 1][0]), "+f"(acc[2 * j + 1][1]),
                  "+f"(acc[2 * j + 1][2]), "+f"(acc[2 * j + 1][3])
                : "r"(a0), "r"(a1), "r"(a2), "r"(a3), "r"(b2), "r"(b3));
        }
    }
}

template<bool NEGA>
__device__ __forceinline__ void mmh1(const __half* __restrict__ A,
                                     const __half* __restrict__ B,
                                     float (&acc)[4],
                                     int lane, int mb, int nb)
{
    const uint32_t abase = (uint32_t)__cvta_generic_to_shared(
        A + (mb + (lane & 15)) * SH + ((lane >> 4) << 3));
    const uint32_t bbase = (uint32_t)__cvta_generic_to_shared(
        B + (nb + (lane & 7)) * SH + (((lane >> 3) & 1) << 3));
#pragma unroll
    for (int kk = 0; kk < 4; kk++) {
        const uint32_t kb2 = kk * 32;
        unsigned a0, a1, a2, a3;
        ldsm_x4(a0, a1, a2, a3, abase + kb2);
        if (NEGA) {
            a0 ^= 0x80008000u; a1 ^= 0x80008000u;
            a2 ^= 0x80008000u; a3 ^= 0x80008000u;
        }
        unsigned b0, b1;
        ldsm_x2(b0, b1, bbase + kb2);
        asm volatile(
            "mma.sync.aligned.m16n8k16.row.col.f32.f16.f16.f32 "
            "{%0,%1,%2,%3}, {%4,%5,%6,%7}, {%8,%9}, {%0,%1,%2,%3};\n"
            : "+f"(acc[0]), "+f"(acc[1]), "+f"(acc[2]), "+f"(acc[3])
            : "r"(a0), "r"(a1), "r"(a2), "r"(a3), "r"(b0), "r"(b1));
    }
}

template<int NI, int MASK, bool SCALE>
__device__ __forceinline__ void storeH(__half* __restrict__ O,
    const float* __restrict__ scl, float (&acc)[NI][4],
    int g, int tg, int mb, int nb)
{
#pragma unroll
    for (int ni = 0; ni < NI; ni++) {
        const int c0 = nb + ni * 8 + 2 * tg;
#pragma unroll
        for (int hh = 0; hh < 2; hh++) {
            const int r = mb + g + 8 * hh;
#pragma unroll
            for (int e = 0; e < 2; e++) {
                const int c = c0 + e;
                float v = acc[ni][2 * hh + e];
                if (MASK == 1 && c > r)  v = 0.f;
                if (MASK == 2 && c >= r) v = 0.f;
                if (SCALE) v *= scl[r * TS + c];
                O[r * SH + c] = __float2half_rn(v);
            }
        }
    }
}

template<int NI>
__device__ __forceinline__ void storeHT(__half* __restrict__ O,
    float (&acc)[NI][4], int g, int tg, int mb, int nb)
{
#pragma unroll
    for (int ni = 0; ni < NI; ni++) {
        const int c0 = nb + ni * 8 + 2 * tg;
#pragma unroll
        for (int hh = 0; hh < 2; hh++) {
            const int r = mb + g + 8 * hh;
#pragma unroll
            for (int e = 0; e < 2; e++)
                O[(c0 + e) * SH + r] = __float2half_rn(acc[ni][2 * hh + e]);
        }
    }
}

template<int NI>
__device__ __forceinline__ void updateS(float* __restrict__ Sf,
    __half* __restrict__ Sh, const float* __restrict__ rs,
    float (&acc)[NI][4], int g, int tg, int mb, int nb)
{
#pragma unroll
    for (int ni = 0; ni < NI; ni++) {
        const int c0 = nb + ni * 8 + 2 * tg;
#pragma unroll
        for (int hh = 0; hh < 2; hh++) {
            const int r = mb + g + 8 * hh;
            const float rr = rs[r];
#pragma unroll
            for (int e = 0; e < 2; e++) {
                const int c = c0 + e;
                float v = rr * rs[c] * (Sf[r * TS + c] + acc[ni][2 * hh + e]);
                Sf[r * TS + c] = v;
                Sh[r * SH + c] = __float2half_rn(v);
            }
        }
    }
}

template<int NI>
__device__ __forceinline__ void updateT(float* __restrict__ Tf,
    __half* __restrict__ Th, const float* __restrict__ rs,
    float (&acc)[NI][4], int g, int tg, int mb, int nb)
{
#pragma unroll
    for (int ni = 0; ni < NI; ni++) {
        const int c0 = nb + ni * 8 + 2 * tg;
#pragma unroll
        for (int hh = 0; hh < 2; hh++) {
            const int r = mb + g + 8 * hh;
#pragma unroll
            for (int e = 0; e < 2; e++) {
                const int c = c0 + e;
                float v = rs[c] * (Tf[r * TS + c] + acc[ni][2 * hh + e]);
                Tf[r * TS + c] = v;
                Th[r * SH + c] = __float2half_rn(v);
            }
        }
    }
}

__device__ __forceinline__ void load_tile64_512(float* __restrict__ dst,
    const float* __restrict__ src, int tid)
{
#pragma unroll
    for (int i = 0; i < 2; i++) {
        const int e = (tid + i * 512) * 4;
        const int r = e >> 6, c = e & 63;
        *(float4*)(dst + r * TS + c) = *(const float4*)(src + e);
    }
}

__global__ __launch_bounds__(512) void scan_chunked(
    const float* __restrict__ qp, const float* __restrict__ kp,
    const float* __restrict__ vp, const float* __restrict__ aKp,
    const float* __restrict__ aCp, __half* __restrict__ o2dh)
{
    extern __shared__ char smc[];
    float*  Qf  = (float*)(smc + O_QF);
    float*  Kf  = (float*)(smc + O_KF);
    float*  AKf = (float*)(smc + O_AKF);
    float*  ACf = (float*)(smc + O_ACF);
    float*  Sf  = (float*)(smc + O_SF);
    float*  CTf = (float*)(smc + O_CTF);
    float*  GTf = (float*)(smc + O_GTF);
    __half* Qh  = (__half*)(smc + O_QH);
    __half* Kh  = (__half*)(smc + O_KH);
    __half* Qt  = (__half*)(smc + O_QT);
    __half* QtT = (__half*)(smc + O_QTT);
    __half* Kt  = (__half*)(smc + O_KT);
    __half* KtT = (__half*)(smc + O_KTT);
    __half* Ph  = (__half*)(smc + O_PH);
    __half* RSc = (__half*)(smc + O_RS);
    __half* Uh  = (__half*)(smc + O_UH);
    __half* Sh  = (__half*)(smc + O_SHH);
    __half* VT  = (__half*)(smc + O_VT);
    __half* KCT = (__half*)(smc + O_KCT);
    __half* CTh = (__half*)(smc + O_CTH);
    __half* GTh = (__half*)(smc + O_GTH);
    __shared__ float aKL[64], aCL[64];

    const int bh   = blockIdx.x >> 1;
    const int half = blockIdx.x & 1;
    const int b = bh >> 4, h = bh & 15;
    const size_t base = (size_t)bh * TSZ * DH;
    const int tid  = threadIdx.x;
    const int lane = tid & 31, w = tid >> 5;
    const int wg = w >> 3, w8 = w & 7;
    const int g = lane >> 2, tg = lane & 3;
    const int mb4 = (w8 & 3) * 16, nb4 = (w8 >> 2) * 32;
    const int mb2 = (w8 & 3) * 16, nb2 = (w8 >> 2) * 16;
    const int mbF = (w8 & 1) * 16, nbF = (w8 >> 1) * 16;
    const int mbO = (w & 3) * 16,  nbO = (w >> 2) * 8;

    for (int i = tid; i < 9216; i += 512) ((uint32_t*)(smc + O_SF))[i] = 0;
    for (int i = tid; i < 2304; i += 512) ((uint32_t*)(smc + O_SHH))[i] = 0;
    for (int i = tid; i < 2304; i += 512) ((uint32_t*)(smc + O_CTH))[i] = 0;
    __syncthreads();

    for (int ch = 0; ch < NCHUNK; ch++) {
        const size_t off = base + (size_t)ch * CL * DH;
        load_tile64_512(Qf,  qp  + off, tid);
        load_tile64_512(Kf,  kp  + off, tid);
        load_tile64_512(AKf, aKp + off, tid);
        load_tile64_512(ACf, aCp + off, tid);
        {
            const int r = tid >> 3, c4 = (tid & 7) * 4;
            float4 v = *(const float4*)(vp + off + r * DH + half * 32 + c4);
            VT[(c4 + 0) * SH + r] = __float2half_rn(v.x);
            VT[(c4 + 1) * SH + r] = __float2half_rn(v.y);
            VT[(c4 + 2) * SH + r] = __float2half_rn(v.z);
            VT[(c4 + 3) * SH + r] = __float2half_rn(v.w);
        }
        __syncthreads();

        {
            float* Tt = (tid < 256) ? AKf : ACf;
            const int col = tid & 63;
            const int seg = (tid >> 6) & 3;
            const int r0 = seg * 16;
            float p = 1.f;
#pragma unroll
            for (int r = 0; r < 16; r++) {
                p *= Tt[(r0 + r) * TS + col];
                Tt[(r0 + r) * TS + col] = p;
            }
            __syncthreads();
            float pref = 1.f;
#pragma unroll
            for (int s = 0; s < 3; s++)
                if (s < seg) pref *= Tt[(s * 16 + 15) * TS + col];
            __syncthreads();
            if (seg > 0) {
#pragma unroll
                for (int r = 0; r < 16; r++) Tt[(r0 + r) * TS + col] *= pref;
            }
        }
        __syncthreads();

#pragma unroll
        for (int i = 0; i < 8; i++) {
            const int e = tid + i * 512;
            const int r = e >> 6, c = e & 63;
            const int idx = r * TS + c;
            const float ak = AKf[idx], ac = ACf[idx];
            const float qv = Qf[idx],  kv = Kf[idx];
            if (r == 63) { aKL[c] = ak; aCL[c] = ac; }
            const float qh = qv * ak, kt = kv / ak;
            const float qt = qv / ac, kh = kv * ac;
            Qh[r * SH + c]  = __float2half_rn(qh);
            Kh[r * SH + c]  = __float2half_rn(kh);
            Qt[r * SH + c]  = __float2half_rn(qt);
            QtT[c * SH + r] = __float2half_rn(qt);
            Kt[r * SH + c]  = __float2half_rn(kt);
            KtT[c * SH + r] = __float2half_rn(kt);
            AKf[idx] = ak * ac;          // SCL
        }
        __syncthreads();

        float acc4[4][4];
        float acc2[2][4];

        if (wg == 0) {
            zacc(acc4);
            mmh<4, false>(Kh, Qt, acc4, lane, mb4, nb4);
            storeH<4, 2, false>(RSc, nullptr, acc4, g, tg, mb4, nb4);
        } else {
            zacc(acc4);
            mmh<4, false>(Qh, Kt, acc4, lane, mb4, nb4);
            storeH<4, 1, false>(Ph, nullptr, acc4, g, tg, mb4, nb4);
        }
        __syncthreads();

        if (wg == 0) {
            zacc(acc2);
            mmh<2, false>(Kh,  CTh, acc2, lane, mb2, nb2);
            mmh<2, false>(RSc, VT,  acc2, lane, mb2, nb2);
            storeHT<2>(KCT, acc2, g, tg, mb2, nb2);
        } else {
            zacc(acc4);
            mmh<4, false>(Qh, Sh,  acc4, lane, mb4, nb4);
            mmh<4, false>(Ph, KtT, acc4, lane, mb4, nb4);
            storeH<4, 0, true>(Uh, AKf, acc4, g, tg, mb4, nb4);
        }
        __syncthreads();

        if (wg == 0) {
            zacc(acc4);
            mmh<4, false>(Uh, Qt, acc4, lane, mb4, nb4);
            storeH<4, 1, false>(RSc, nullptr, acc4, g, tg, mb4, nb4);
        } else {
            zacc(acc4);
            mmh<4, false>(KtT, KtT, acc4, lane, mb4, nb4);
            updateS<4>(Sf, Sh, aKL, acc4, g, tg, mb4, nb4);
        }
        __syncthreads();

        {
            float accO[4] = {0.f, 0.f, 0.f, 0.f};
            mmh1<false>(Uh,  CTh, accO, lane, mbO, nbO);
            mmh1<false>(RSc, VT,  accO, lane, mbO, nbO);
            mmh1<true >(Qh,  GTh, accO, lane, mbO, nbO);
            mmh1<true >(Ph,  KCT, accO, lane, mbO, nbO);
            const int t0 = ch * CL;
            const int c0 = nbO + 2 * tg;
#pragma unroll
            for (int hh = 0; hh < 2; hh++) {
                const int r = mbO + g + 8 * hh;
                __half2 st = __floats2half2_rn(accO[2 * hh], accO[2 * hh + 1]);
                *(__half2*)&o2dh[(size_t)(b * TSZ + t0 + r) * 1024 +
                                 h * DH + half * 32 + c0] = st;
            }
        }
        __syncthreads();

        if (wg == 0) {
            zacc(acc2);
            mmh<2, false>(VT, QtT, acc2, lane, mbF, nbF);
            updateT<2>(CTf, CTh, aCL, acc2, g, tg, mbF, nbF);
        } else {
            zacc(acc2);
            mmh<2, false>(KCT, KtT, acc2, lane, mbF, nbF);
            updateT<2>(GTf, GTh, aKL, acc2, g, tg, mbF, nbF);
        }
        __syncthreads();
    }
}

// ---------------------------------------------------------------------------
extern "C" void kernel_launch(void* const* d_in, const int* in_sizes, int n_in,
                              void* d_out, int out_size)
{
    const float* x   = (const float*)d_in[0];
    const float* Wq  = (const float*)d_in[1];
    const float* Wk  = (const float*)d_in[2];
    const float* Wv  = (const float*)d_in[3];
    const float* WgK = (const float*)d_in[4];
    const float* bgK = (const float*)d_in[5];
    const float* WgC = (const float*)d_in[6];
    const float* bgC = (const float*)d_in[7];
    const float* Wo  = (const float*)d_in[8];
    float* out = (float*)d_out;

    float *proj = nullptr;
    __half *o2dh = nullptr, *xh = nullptr, *wth = nullptr;
    cudaGetSymbolAddress((void**)&proj, g_proj);
    cudaGetSymbolAddress((void**)&o2dh, g_o2dh);
    cudaGetSymbolAddress((void**)&xh,   g_xh);
    cudaGetSymbolAddress((void**)&wth,  g_wth);
    const size_t PS = (size_t)64 * TSZ * DH;

    cudaFuncSetAttribute(gemm_fp16,
                         cudaFuncAttributeMaxDynamicSharedMemorySize,
                         GEMM2_SMEM);
    cudaFuncSetAttribute(scan_chunked,
                         cudaFuncAttributeMaxDynamicSharedMemorySize,
                         SCAN_SMEM_BYTES);

    half_x_kernel<<<(GM * GK) / 2048, 256>>>(x, xh);
    half_wt_kernel<<<dim3(32, 32, 6), 256>>>(Wq, Wk, Wv, WgK, WgC, Wo, wth);

    gemm_fp16<<<dim3(GN / 256, GM / 128, 5), 512, GEMM2_SMEM>>>(
        xh, wth, bgK, bgC, proj, 1);

    scan_chunked<<<128, 512, SCAN_SMEM_BYTES>>>(proj, proj + PS, proj + 2 * PS,
                                                proj + 3 * PS, proj + 4 * PS, o2dh);

    gemm_fp16<<<dim3(GN / 256, GM / 128, 1), 512, GEMM2_SMEM>>>(
        o2dh, wth + (size_t)5 * GN * GK, nullptr, nullptr, out, 0);
}

// round 14
// speedup vs baseline: 4.4883x; 1.0131x over previous
#include <cuda_runtime.h>
#include <cuda_fp16.h>
#include <math.h>
#include <stdint.h>

#define TSZ 2048
#define HN  16
#define DH  64
#define CL  64
#define NCHUNK 32
#define TS  72                  // fp32 staging stride (floats)
#define SH  72                  // half tile stride (halves)

#define GM 8192
#define GN 1024
#define GK 1024

// Scratch
__device__ float  g_proj[5][(size_t)64 * TSZ * DH];   // 5 * 32 MB
__device__ __half g_o2dh[(size_t)GM * GN];            // 16 MB
__device__ __half g_xh[(size_t)GM * GK];              // 16 MB
__device__ __half g_wth[6][(size_t)GN * GK];          // 12 MB  W^T [z][n][k]

__device__ __forceinline__ void ldsm_x4(unsigned& r0, unsigned& r1,
                                        unsigned& r2, unsigned& r3,
                                        uint32_t addr) {
    asm volatile("ldmatrix.sync.aligned.m8n8.x4.shared.b16 {%0,%1,%2,%3}, [%4];"
                 : "=r"(r0), "=r"(r1), "=r"(r2), "=r"(r3) : "r"(addr));
}
__device__ __forceinline__ void ldsm_x2(unsigned& r0, unsigned& r1,
                                        uint32_t addr) {
    asm volatile("ldmatrix.sync.aligned.m8n8.x2.shared.b16 {%0,%1}, [%2];"
                 : "=r"(r0), "=r"(r1) : "r"(addr));
}

// ---------------------------------------------------------------------------
// Prep: fp16(x) and fp16(W^T).
// ---------------------------------------------------------------------------
__global__ __launch_bounds__(256) void half_x_kernel(
    const float* __restrict__ x, __half* __restrict__ xh)
{
    size_t i = ((size_t)blockIdx.x * 256 + threadIdx.x) * 8;
    float4 v0 = *(const float4*)(x + i);
    float4 v1 = *(const float4*)(x + i + 4);
    __half2 h[4];
    h[0] = __floats2half2_rn(v0.x, v0.y);
    h[1] = __floats2half2_rn(v0.z, v0.w);
    h[2] = __floats2half2_rn(v1.x, v1.y);
    h[3] = __floats2half2_rn(v1.z, v1.w);
    *(uint4*)(xh + i) = *(uint4*)h;
}

__global__ __launch_bounds__(256) void half_wt_kernel(
    const float* __restrict__ Wq, const float* __restrict__ Wk,
    const float* __restrict__ Wv, const float* __restrict__ WgK,
    const float* __restrict__ WgC, const float* __restrict__ Wo,
    __half* __restrict__ wth)
{
    __shared__ float tile[32][33];
    const int z = blockIdx.z;
    const float* W = (z == 0) ? Wq : (z == 1) ? Wk : (z == 2) ? Wv
                   : (z == 3) ? WgK : (z == 4) ? WgC : Wo;
    const int n0 = blockIdx.x * 32, k0 = blockIdx.y * 32;
    const int tx = threadIdx.x & 31, ty = threadIdx.x >> 5;
#pragma unroll
    for (int i = 0; i < 4; i++)
        tile[ty + i * 8][tx] = W[(size_t)(k0 + ty + i * 8) * GN + n0 + tx];
    __syncthreads();
    __half* dst = wth + (size_t)z * GN * GK;
#pragma unroll
    for (int i = 0; i < 4; i++)
        dst[(size_t)(n0 + ty + i * 8) * GK + k0 + tx] =
            __float2half_rn(tile[tx][ty + i * 8]);
}

// ---------------------------------------------------------------------------
// FP16 mma GEMM, 512 threads (16 warps = 2m x 8n, warp tile 64x32).
// cp.async double-buffered smem; A-fragments double-buffered across k16 steps.
// ---------------------------------------------------------------------------
#define AST2 72
#define BST2 72
#define AS2_EL (128 * AST2)
#define BS2_EL (256 * BST2)
#define GEMM2_SMEM ((2 * (AS2_EL + BS2_EL)) * (int)sizeof(__half))

__device__ __forceinline__ void gemm2_fill(const __half* __restrict__ A,
                                           const __half* __restrict__ BT,
                                           int rowBase, int colBase, int tid,
                                           __half* AsD, __half* BsD, int kt)
{
    const int k0 = kt * 64;
#pragma unroll
    for (int i = 0; i < 2; i++) {
        const int id = tid + i * 512;
        const int r = id >> 3, c = (id & 7) * 8;
        const __half* src = A + (size_t)(rowBase + r) * GK + k0 + c;
        unsigned dst = (unsigned)__cvta_generic_to_shared(AsD + r * AST2 + c);
        asm volatile("cp.async.cg.shared.global [%0], [%1], 16;" :: "r"(dst), "l"(src));
    }
#pragma unroll
    for (int i = 0; i < 4; i++) {
        const int id = tid + i * 512;
        const int r = id >> 3, c = (id & 7) * 8;
        const __half* src = BT + (size_t)(colBase + r) * GK + k0 + c;
        unsigned dst = (unsigned)__cvta_generic_to_shared(BsD + r * BST2 + c);
        asm volatile("cp.async.cg.shared.global [%0], [%1], 16;" :: "r"(dst), "l"(src));
    }
    asm volatile("cp.async.commit_group;");
}

__global__ __launch_bounds__(512, 1) void gemm_fp16(
    const __half* __restrict__ A, const __half* __restrict__ WTall,
    const float* __restrict__ b3, const float* __restrict__ b4,
    float* __restrict__ Cb, int multi)
{
    extern __shared__ __half smem[];
    __half* AsB = smem;
    __half* BsB = smem + 2 * AS2_EL;

    const int tid  = threadIdx.x;
    const int lane = tid & 31;
    const int warpId = tid >> 5;       // 0..15
    const int wm = warpId & 1;
    const int wn = warpId >> 1;        // 0..7
    const int g  = lane >> 2;
    const int tg = lane & 3;
    const int rowBase = blockIdx.y * 128;
    const int colBase = blockIdx.x * 256;

    const uint32_t laneAoff =
        (uint32_t)((((lane & 15) * AST2) + ((lane >> 4) << 3)) * 2);
    const int brow = (lane & 7) + ((lane >> 4) << 3);
    const int bko  = ((lane >> 3) & 1) << 3;
    const uint32_t laneBoff = (uint32_t)((brow * BST2 + bko) * 2);

    const __half* BT; const float* bias; float* C; int mode;
    if (multi) {
        const int z = blockIdx.z;
        BT = WTall + (size_t)z * GN * GK;
        bias = (z == 3) ? b3 : (z == 4) ? b4 : nullptr;
        C = Cb + (size_t)z * ((size_t)64 * TSZ * DH);
        mode = (z >= 3) ? 2 : 1;
    } else {
        BT = WTall; bias = nullptr; C = Cb; mode = 0;
    }

    float acc[4][4][4];
#pragma unroll
    for (int i = 0; i < 4; i++)
#pragma unroll
        for (int j = 0; j < 4; j++)
#pragma unroll
            for (int e = 0; e < 4; e++) acc[i][j][e] = 0.f;

    gemm2_fill(A, BT, rowBase, colBase, tid, AsB, BsB, 0);

    const int KT = GK / 64;
    for (int kt = 0; kt < KT; kt++) {
        const int cur = kt & 1;
        asm volatile("cp.async.wait_group 0;");
        __syncthreads();
        if (kt + 1 < KT)
            gemm2_fill(A, BT, rowBase, colBase, tid,
                       AsB + (cur ^ 1) * AS2_EL, BsB + (cur ^ 1) * BS2_EL, kt + 1);

        const __half* As = AsB + cur * AS2_EL;
        const __half* Bs = BsB + cur * BS2_EL;
        const uint32_t asb = (uint32_t)__cvta_generic_to_shared(As)
                           + (uint32_t)(wm * 64 * AST2 * 2) + laneAoff;
        const uint32_t bsb = (uint32_t)__cvta_generic_to_shared(Bs)
                           + (uint32_t)(wn * 32 * BST2 * 2) + laneBoff;

        unsigned af[2][4][4];
        // preload kk=0 A-fragments
#pragma unroll
        for (int mi = 0; mi < 4; mi++)
            ldsm_x4(af[0][mi][0], af[0][mi][1], af[0][mi][2], af[0][mi][3],
                    asb + mi * 16 * AST2 * 2);

#pragma unroll
        for (int kk = 0; kk < 4; kk++) {
            const int cb = kk & 1, nx = cb ^ 1;
            if (kk < 3) {
                const uint32_t kb2 = (kk + 1) * 32;
#pragma unroll
                for (int mi = 0; mi < 4; mi++)
                    ldsm_x4(af[nx][mi][0], af[nx][mi][1],
                            af[nx][mi][2], af[nx][mi][3],
                            asb + mi * 16 * AST2 * 2 + kb2);
            }
            unsigned bf[4][2];
#pragma unroll
            for (int j = 0; j < 2; j++)
                ldsm_x4(bf[2 * j][0], bf[2 * j][1],
                        bf[2 * j + 1][0], bf[2 * j + 1][1],
                        bsb + j * 16 * BST2 * 2 + kk * 32);
#pragma unroll
            for (int ni = 0; ni < 4; ni++)
#pragma unroll
                for (int mi = 0; mi < 4; mi++) {
                    asm volatile(
                        "mma.sync.aligned.m16n8k16.row.col.f32.f16.f16.f32 "
                        "{%0,%1,%2,%3}, {%4,%5,%6,%7}, {%8,%9}, {%0,%1,%2,%3};\n"
                        : "+f"(acc[mi][ni][0]), "+f"(acc[mi][ni][1]),
                          "+f"(acc[mi][ni][2]), "+f"(acc[mi][ni][3])
                        : "r"(af[cb][mi][0]), "r"(af[cb][mi][1]),
                          "r"(af[cb][mi][2]), "r"(af[cb][mi][3]),
                          "r"(bf[ni][0]), "r"(bf[ni][1]));
                }
        }
    }

#pragma unroll
    for (int mi = 0; mi < 4; mi++) {
        const int gr0 = rowBase + wm * 64 + mi * 16 + g;
#pragma unroll
        for (int ni = 0; ni < 4; ni++) {
            const int gc = colBase + wn * 32 + ni * 8 + 2 * tg;
#pragma unroll
            for (int half = 0; half < 2; half++) {
                const int gr = gr0 + 8 * half;
                float v0 = acc[mi][ni][2 * half];
                float v1 = acc[mi][ni][2 * half + 1];
                if (mode == 0) {
                    *(float2*)&C[(size_t)gr * GN + gc] = make_float2(v0, v1);
                } else {
                    if (mode == 2) {
                        v0 = 1.f / (1.f + __expf(-(v0 + bias[gc])));
                        v1 = 1.f / (1.f + __expf(-(v1 + bias[gc + 1])));
                    }
                    const int b = gr >> 11, t = gr & 2047;
                    const int h = gc >> 6,  d = gc & 63;
                    *(float2*)&C[((size_t)((b * HN + h) * TSZ + t)) * DH + d] =
                        make_float2(v0, v1);
                }
            }
        }
    }
}

// ---------------------------------------------------------------------------
// Chunked scan, dv-split, fp16 mma + ldmatrix, 512 threads, warp-group task
// parallelism + cp.async input prefetch + vectorized epilogues.
// ---------------------------------------------------------------------------
#define O_QF   0
#define O_KF   18432
#define O_AKF  36864
#define O_ACF  55296
#define O_SF   73728
#define O_CTF  92160
#define O_GTF  101376
#define HB     110592
#define O_QH   (HB + 0)
#define O_KH   (HB + 9216)
#define O_QT   (HB + 18432)
#define O_QTT  (HB + 27648)
#define O_KT   (HB + 36864)
#define O_KTT  (HB + 46080)
#define O_PH   (HB + 55296)
#define O_RS   (HB + 64512)
#define O_UH   (HB + 73728)
#define O_SHH  (HB + 82944)
#define O_VT   (HB + 92160)
#define O_KCT  (HB + 96768)
#define O_CTH  (HB + 101376)
#define O_GTH  (HB + 105984)
#define SCAN_SMEM_BYTES (HB + 110592)

template<int NI>
__device__ __forceinline__ void zacc(float (&acc)[NI][4]) {
#pragma unroll
    for (int i = 0; i < NI; i++)
#pragma unroll
        for (int j = 0; j < 4; j++) acc[i][j] = 0.f;
}

template<int NI, bool NEGA>
__device__ __forceinline__ void mmh(const __half* __restrict__ A,
                                    const __half* __restrict__ B,
                                    float (&acc)[NI][4],
                                    int lane, int mb, int nb)
{
    const uint32_t abase = (uint32_t)__cvta_generic_to_shared(
        A + (mb + (lane & 15)) * SH + ((lane >> 4) << 3));
    const int brow = (lane & 7) + ((lane >> 4) << 3);
    const int bko  = ((lane >> 3) & 1) << 3;
    const uint32_t bbase = (uint32_t)__cvta_generic_to_shared(
        B + (nb + brow) * SH + bko);
#pragma unroll
    for (int kk = 0; kk < 4; kk++) {
        const uint32_t kb2 = kk * 32;
        unsigned a0, a1, a2, a3;
        ldsm_x4(a0, a1, a2, a3, abase + kb2);
        if (NEGA) {
            a0 ^= 0x80008000u; a1 ^= 0x80008000u;
            a2 ^= 0x80008000u; a3 ^= 0x80008000u;
        }
#pragma unroll
        for (int j = 0; j < NI / 2; j++) {
            unsigned b0, b1, b2, b3;
            ldsm_x4(b0, b1, b2, b3, bbase + (uint32_t)(j * 16 * SH * 2) + kb2);
            asm volatile(
                "mma.sync.aligned.m16n8k16.row.col.f32.f16.f16.f32 "
                "{%0,%1,%2,%3}, {%4,%5,%6,%7}, {%8,%9}, {%0,%1,%2,%3};\n"
                : "+f"(acc[2 * j][0]), "+f"(acc[2 * j][1]),
                  "+f"(acc[2 * j][2]), "+f"(acc[2 * j][3])
                : "r"(a0), "r"(a1), "r"(a2), "r"(a3), "r"(b0), "r"(b1));
            asm volatile(
                "mma.sync.aligned.m16n8k16.row.col.f32.f16.f16.f32 "
                "{%0,%1,%2,%3}, {%4,%5,%6,%7}, {%8,%9}, {%0,%1,%2,%3};\n"
                : "+f"(acc[2 * j + 1][0]), "+f"(acc[2 * j + 1][1]),
                  "+f"(acc[2 * j + 1][2]), "+f"(acc[2 * j + 1][3])
                : "r"(a0), "r"(a1), "r"(a2), "r"(a3), "r"(b2), "r"(b3));
        }
    }
}

template<bool NEGA>
__device__ __forceinline__ void mmh1(const __half* __restrict__ A,
                                     const __half* __restrict__ B,
                                     float (&acc)[4],
                                     int lane, int mb, int nb)
{
    const uint32_t abase = (uint32_t)__cvta_generic_to_shared(
        A + (mb + (lane & 15)) * SH + ((lane >> 4) << 3));
    const uint32_t bbase = (uint32_t)__cvta_generic_to_shared(
        B + (nb + (lane & 7)) * SH + (((lane >> 3) & 1) << 3));
#pragma unroll
    for (int kk = 0; kk < 4; kk++) {
        const uint32_t kb2 = kk * 32;
        unsigned a0, a1, a2, a3;
        ldsm_x4(a0, a1, a2, a3, abase + kb2);
        if (NEGA) {
            a0 ^= 0x80008000u; a1 ^= 0x80008000u;
            a2 ^= 0x80008000u; a3 ^= 0x80008000u;
        }
        unsigned b0, b1;
        ldsm_x2(b0, b1, bbase + kb2);
        asm volatile(
            "mma.sync.aligned.m16n8k16.row.col.f32.f16.f16.f32 "
            "{%0,%1,%2,%3}, {%4,%5,%6,%7}, {%8,%9}, {%0,%1,%2,%3};\n"
            : "+f"(acc[0]), "+f"(acc[1]), "+f"(acc[2]), "+f"(acc[3])
            : "r"(a0), "r"(a1), "r"(a2), "r"(a3), "r"(b0), "r"(b1));
    }
}

template<int NI, int MASK, bool SCALE>
__device__ __forceinline__ void storeH(__half* __restrict__ O,
    const float* __restrict__ scl, float (&acc)[NI][4],
    int g, int tg, int mb, int nb)
{
#pragma unroll
    for (int ni = 0; ni < NI; ni++) {
        const int c0 = nb + ni * 8 + 2 * tg;
#pragma unroll
        for (int hh = 0; hh < 2; hh++) {
            const int r = mb + g + 8 * hh;
            float v0 = acc[ni][2 * hh];
            float v1 = acc[ni][2 * hh + 1];
            if (MASK == 1) { if (c0 > r) v0 = 0.f; if (c0 + 1 > r) v1 = 0.f; }
            if (MASK == 2) { if (c0 >= r) v0 = 0.f; if (c0 + 1 >= r) v1 = 0.f; }
            if (SCALE) { v0 *= scl[r * TS + c0]; v1 *= scl[r * TS + c0 + 1]; }
            *(__half2*)&O[r * SH + c0] = __floats2half2_rn(v0, v1);
        }
    }
}

template<int NI>
__device__ __forceinline__ void storeHT(__half* __restrict__ O,
    float (&acc)[NI][4], int g, int tg, int mb, int nb)
{
#pragma unroll
    for (int ni = 0; ni < NI; ni++) {
        const int c0 = nb + ni * 8 + 2 * tg;
#pragma unroll
        for (int hh = 0; hh < 2; hh++) {
            const int r = mb + g + 8 * hh;
#pragma unroll
            for (int e = 0; e < 2; e++)
                O[(c0 + e) * SH + r] = __float2half_rn(acc[ni][2 * hh + e]);
        }
    }
}

template<int NI>
__device__ __forceinline__ void updateS(float* __restrict__ Sf,
    __half* __restrict__ Sh, const float* __restrict__ rs,
    float (&acc)[NI][4], int g, int tg, int mb, int nb)
{
#pragma unroll
    for (int ni = 0; ni < NI; ni++) {
        const int c0 = nb + ni * 8 + 2 * tg;
#pragma unroll
        for (int hh = 0; hh < 2; hh++) {
            const int r = mb + g + 8 * hh;
            const float rr = rs[r];
            float v0 = rr * rs[c0]     * (Sf[r * TS + c0]     + acc[ni][2 * hh]);
            float v1 = rr * rs[c0 + 1] * (Sf[r * TS + c0 + 1] + acc[ni][2 * hh + 1]);
            *(float2*)&Sf[r * TS + c0] = make_float2(v0, v1);
            *(__half2*)&Sh[r * SH + c0] = __floats2half2_rn(v0, v1);
        }
    }
}

template<int NI>
__device__ __forceinline__ void updateT(float* __restrict__ Tf,
    __half* __restrict__ Th, const float* __restrict__ rs,
    float (&acc)[NI][4], int g, int tg, int mb, int nb)
{
#pragma unroll
    for (int ni = 0; ni < NI; ni++) {
        const int c0 = nb + ni * 8 + 2 * tg;
#pragma unroll
        for (int hh = 0; hh < 2; hh++) {
            const int r = mb + g + 8 * hh;
            float v0 = rs[c0]     * (Tf[r * TS + c0]     + acc[ni][2 * hh]);
            float v1 = rs[c0 + 1] * (Tf[r * TS + c0 + 1] + acc[ni][2 * hh + 1]);
            *(float2*)&Tf[r * TS + c0] = make_float2(v0, v1);
            *(__half2*)&Th[r * SH + c0] = __floats2half2_rn(v0, v1);
        }
    }
}

// cp.async prefetch of the next chunk's 4 fp32 input tiles into staging.
// Staging tiles are consecutive at byte offsets tile*18432; chunk source data
// is contiguous (4096 floats per tile).
__device__ __forceinline__ void scan_prefetch(
    const float* __restrict__ q, const float* __restrict__ k,
    const float* __restrict__ aK, const float* __restrict__ aC,
    uint32_t smbase, int tid, size_t off)
{
#pragma unroll
    for (int i = 0; i < 8; i++) {
        const int id = tid + i * 512;
        const int tile = id >> 10, loc = id & 1023;
        const int r = loc >> 4, c4 = (loc & 15) * 4;
        const float* src = (tile == 0) ? q : (tile == 1) ? k
                         : (tile == 2) ? aK : aC;
        src += off + (size_t)loc * 4;
        uint32_t dst = smbase + (uint32_t)(tile * 18432 + (r * TS + c4) * 4);
        asm volatile("cp.async.cg.shared.global [%0], [%1], 16;" :: "r"(dst), "l"(src));
    }
    asm volatile("cp.async.commit_group;");
}

__global__ __launch_bounds__(512) void scan_chunked(
    const float* __restrict__ qp, const float* __restrict__ kp,
    const float* __restrict__ vp, const float* __restrict__ aKp,
    const float* __restrict__ aCp, __half* __restrict__ o2dh)
{
    extern __shared__ char smc[];
    float*  Qf  = (float*)(smc + O_QF);
    float*  Kf  = (float*)(smc + O_KF);
    float*  AKf = (float*)(smc + O_AKF);
    float*  ACf = (float*)(smc + O_ACF);
    float*  Sf  = (float*)(smc + O_SF);
    float*  CTf = (float*)(smc + O_CTF);
    float*  GTf = (float*)(smc + O_GTF);
    __half* Qh  = (__half*)(smc + O_QH);
    __half* Kh  = (__half*)(smc + O_KH);
    __half* Qt  = (__half*)(smc + O_QT);
    __half* QtT = (__half*)(smc + O_QTT);
    __half* Kt  = (__half*)(smc + O_KT);
    __half* KtT = (__half*)(smc + O_KTT);
    __half* Ph  = (__half*)(smc + O_PH);
    __half* RSc = (__half*)(smc + O_RS);
    __half* Uh  = (__half*)(smc + O_UH);
    __half* Sh  = (__half*)(smc + O_SHH);
    __half* VT  = (__half*)(smc + O_VT);
    __half* KCT = (__half*)(smc + O_KCT);
    __half* CTh = (__half*)(smc + O_CTH);
    __half* GTh = (__half*)(smc + O_GTH);
    __shared__ float aKL[64], aCL[64];

    const int bh   = blockIdx.x >> 1;
    const int half = blockIdx.x & 1;
    const int b = bh >> 4, h = bh & 15;
    const size_t base = (size_t)bh * TSZ * DH;
    const int tid  = threadIdx.x;
    const int lane = tid & 31, w = tid >> 5;
    const int wg = w >> 3, w8 = w & 7;
    const int g = lane >> 2, tg = lane & 3;
    const int mb4 = (w8 & 3) * 16, nb4 = (w8 >> 2) * 32;
    const int mb2 = (w8 & 3) * 16, nb2 = (w8 >> 2) * 16;
    const int mbF = (w8 & 1) * 16, nbF = (w8 >> 1) * 16;
    const int mbO = (w & 3) * 16,  nbO = (w >> 2) * 8;
    const uint32_t smbase = (uint32_t)__cvta_generic_to_shared(smc);

    for (int i = tid; i < 9216; i += 512) ((uint32_t*)(smc + O_SF))[i] = 0;
    for (int i = tid; i < 2304; i += 512) ((uint32_t*)(smc + O_SHH))[i] = 0;
    for (int i = tid; i < 2304; i += 512) ((uint32_t*)(smc + O_CTH))[i] = 0;

    // prefetch chunk 0
    scan_prefetch(qp, kp, aKp, aCp, smbase, tid, base);
    __syncthreads();

    for (int ch = 0; ch < NCHUNK; ch++) {
        const size_t off = base + (size_t)ch * CL * DH;
        {   // V half-column -> VT (transposed fp16)
            const int r = tid >> 3, c4 = (tid & 7) * 4;
            float4 v = *(const float4*)(vp + off + r * DH + half * 32 + c4);
            VT[(c4 + 0) * SH + r] = __float2half_rn(v.x);
            VT[(c4 + 1) * SH + r] = __float2half_rn(v.y);
            VT[(c4 + 2) * SH + r] = __float2half_rn(v.z);
            VT[(c4 + 3) * SH + r] = __float2half_rn(v.w);
        }
        asm volatile("cp.async.wait_group 0;");
        __syncthreads();

        {   // cumulative products: 2 tensors x 4 segments of 16 rows
            float* Tt = (tid < 256) ? AKf : ACf;
            const int col = tid & 63;
            const int seg = (tid >> 6) & 3;
            const int r0 = seg * 16;
            float p = 1.f;
#pragma unroll
            for (int r = 0; r < 16; r++) {
                p *= Tt[(r0 + r) * TS + col];
                Tt[(r0 + r) * TS + col] = p;
            }
            __syncthreads();
            float pref = 1.f;
#pragma unroll
            for (int s = 0; s < 3; s++)
                if (s < seg) pref *= Tt[(s * 16 + 15) * TS + col];
            __syncthreads();
            if (seg > 0) {
#pragma unroll
                for (int r = 0; r < 16; r++) Tt[(r0 + r) * TS + col] *= pref;
            }
        }
        __syncthreads();

        // derive fp16 operand tiles (+ SCL fp32 in AKf slot)
#pragma unroll
        for (int i = 0; i < 8; i++) {
            const int e = tid + i * 512;
            const int r = e >> 6, c = e & 63;
            const int idx = r * TS + c;
            const float ak = AKf[idx], ac = ACf[idx];
            const float qv = Qf[idx],  kv = Kf[idx];
            if (r == 63) { aKL[c] = ak; aCL[c] = ac; }
            const float qh = qv * ak, kt = kv / ak;
            const float qt = qv / ac, kh = kv * ac;
            Qh[r * SH + c]  = __float2half_rn(qh);
            Kh[r * SH + c]  = __float2half_rn(kh);
            Qt[r * SH + c]  = __float2half_rn(qt);
            QtT[c * SH + r] = __float2half_rn(qt);
            Kt[r * SH + c]  = __float2half_rn(kt);
            KtT[c * SH + r] = __float2half_rn(kt);
            AKf[idx] = ak * ac;          // SCL
        }
        __syncthreads();

        float acc4[4][4];
        float acc2[2][4];

        // Phase A: wg0: R = strict(Kh@Qt^T) -> RSc ; wg1: P = incl(Qh@Kt^T) -> Ph
        if (wg == 0) {
            zacc(acc4);
            mmh<4, false>(Kh, Qt, acc4, lane, mb4, nb4);
            storeH<4, 2, false>(RSc, nullptr, acc4, g, tg, mb4, nb4);
        } else {
            zacc(acc4);
            mmh<4, false>(Qh, Kt, acc4, lane, mb4, nb4);
            storeH<4, 1, false>(Ph, nullptr, acc4, g, tg, mb4, nb4);
        }
        __syncthreads();

        // Phase B: wg0: KC = Kh@C0 + R@V -> KCT ; wg1: Uhat -> Uh
        if (wg == 0) {
            zacc(acc2);
            mmh<2, false>(Kh,  CTh, acc2, lane, mb2, nb2);
            mmh<2, false>(RSc, VT,  acc2, lane, mb2, nb2);
            storeHT<2>(KCT, acc2, g, tg, mb2, nb2);
        } else {
            zacc(acc4);
            mmh<4, false>(Qh, Sh,  acc4, lane, mb4, nb4);
            mmh<4, false>(Ph, KtT, acc4, lane, mb4, nb4);
            storeH<4, 0, true>(Uh, AKf, acc4, g, tg, mb4, nb4);
        }
        __syncthreads();

        // staging tiles now dead: prefetch next chunk's inputs
        {
            int chn = ch + 1; if (chn > NCHUNK - 1) chn = NCHUNK - 1;
            scan_prefetch(qp, kp, aKp, aCp, smbase, tid,
                          base + (size_t)chn * CL * DH);
        }

        // Phase C: wg0: Sc2 = incl(Uh@Qt^T) -> RSc ; wg1: S state update
        if (wg == 0) {
            zacc(acc4);
            mmh<4, false>(Uh, Qt, acc4, lane, mb4, nb4);
            storeH<4, 1, false>(RSc, nullptr, acc4, g, tg, mb4, nb4);
        } else {
            zacc(acc4);
            mmh<4, false>(KtT, KtT, acc4, lane, mb4, nb4);
            updateS<4>(Sf, Sh, aKL, acc4, g, tg, mb4, nb4);
        }
        __syncthreads();

        // Phase E: all 16 warps: O = Uh@C0 + Sc2@V - Qh@G0 - P@KC -> gmem
        {
            float accO[4] = {0.f, 0.f, 0.f, 0.f};
            mmh1<false>(Uh,  CTh, accO, lane, mbO, nbO);
            mmh1<false>(RSc, VT,  accO, lane, mbO, nbO);
            mmh1<true >(Qh,  GTh, accO, lane, mbO, nbO);
            mmh1<true >(Ph,  KCT, accO, lane, mbO, nbO);
            const int t0 = ch * CL;
            const int c0 = nbO + 2 * tg;
#pragma unroll
            for (int hh = 0; hh < 2; hh++) {
                const int r = mbO + g + 8 * hh;
                __half2 st = __floats2half2_rn(accO[2 * hh], accO[2 * hh + 1]);
                *(__half2*)&o2dh[(size_t)(b * TSZ + t0 + r) * 1024 +
                                 h * DH + half * 32 + c0] = st;
            }
        }
        __syncthreads();

        // Phase F: wg0: C state update ; wg1: G state update
        if (wg == 0) {
            zacc(acc2);
            mmh<2, false>(VT, QtT, acc2, lane, mbF, nbF);
            updateT<2>(CTf, CTh, aCL, acc2, g, tg, mbF, nbF);
        } else {
            zacc(acc2);
            mmh<2, false>(KCT, KtT, acc2, lane, mbF, nbF);
            updateT<2>(GTf, GTh, aKL, acc2, g, tg, mbF, nbF);
        }
        __syncthreads();
    }
}

// ---------------------------------------------------------------------------
extern "C" void kernel_launch(void* const* d_in, const int* in_sizes, int n_in,
                              void* d_out, int out_size)
{
    const float* x   = (const float*)d_in[0];
    const float* Wq  = (const float*)d_in[1];
    const float* Wk  = (const float*)d_in[2];
    const float* Wv  = (const float*)d_in[3];
    const float* WgK = (const float*)d_in[4];
    const float* bgK = (const float*)d_in[5];
    const float* WgC = (const float*)d_in[6];
    const float* bgC = (const float*)d_in[7];
    const float* Wo  = (const float*)d_in[8];
    float* out = (float*)d_out;

    float *proj = nullptr;
    __half *o2dh = nullptr, *xh = nullptr, *wth = nullptr;
    cudaGetSymbolAddress((void**)&proj, g_proj);
    cudaGetSymbolAddress((void**)&o2dh, g_o2dh);
    cudaGetSymbolAddress((void**)&xh,   g_xh);
    cudaGetSymbolAddress((void**)&wth,  g_wth);
    const size_t PS = (size_t)64 * TSZ * DH;

    cudaFuncSetAttribute(gemm_fp16,
                         cudaFuncAttributeMaxDynamicSharedMemorySize,
                         GEMM2_SMEM);
    cudaFuncSetAttribute(scan_chunked,
                         cudaFuncAttributeMaxDynamicSharedMemorySize,
                         SCAN_SMEM_BYTES);

    half_x_kernel<<<(GM * GK) / 2048, 256>>>(x, xh);
    half_wt_kernel<<<dim3(32, 32, 6), 256>>>(Wq, Wk, Wv, WgK, WgC, Wo, wth);

    gemm_fp16<<<dim3(GN / 256, GM / 128, 5), 512, GEMM2_SMEM>>>(
        xh, wth, bgK, bgC, proj, 1);

    scan_chunked<<<128, 512, SCAN_SMEM_BYTES>>>(proj, proj + PS, proj + 2 * PS,
                                                proj + 3 * PS, proj + 4 * PS, o2dh);

    gemm_fp16<<<dim3(GN / 256, GM / 128, 1), 512, GEMM2_SMEM>>>(
        o2dh, wth + (size_t)5 * GN * GK, nullptr, nullptr, out, 0);
}

// round 15
// speedup vs baseline: 4.7547x; 1.0593x over previous
#include <cuda_runtime.h>
#include <cuda_fp16.h>
#include <math.h>
#include <stdint.h>

#define TSZ 2048
#define HN  16
#define DH  64
#define CL  64
#define NCHUNK 32
#define TS  72                  // fp32 staging stride (floats)
#define SH  72                  // half tile stride (halves)

#define GM 8192
#define GN 1024
#define GK 1024

// Scratch
__device__ __half g_projh[3][(size_t)64 * TSZ * DH];  // q,k,v fp16: 48 MB
__device__ float  g_projf[2][(size_t)64 * TSZ * DH];  // aK,aC fp32: 64 MB
__device__ __half g_o2dh[(size_t)GM * GN];            // 16 MB
__device__ __half g_xh[(size_t)GM * GK];              // 16 MB
__device__ __half g_wth[6][(size_t)GN * GK];          // 12 MB  W^T [z][n][k]

__device__ __forceinline__ void ldsm_x4(unsigned& r0, unsigned& r1,
                                        unsigned& r2, unsigned& r3,
                                        uint32_t addr) {
    asm volatile("ldmatrix.sync.aligned.m8n8.x4.shared.b16 {%0,%1,%2,%3}, [%4];"
                 : "=r"(r0), "=r"(r1), "=r"(r2), "=r"(r3) : "r"(addr));
}
__device__ __forceinline__ void ldsm_x2(unsigned& r0, unsigned& r1,
                                        uint32_t addr) {
    asm volatile("ldmatrix.sync.aligned.m8n8.x2.shared.b16 {%0,%1}, [%2];"
                 : "=r"(r0), "=r"(r1) : "r"(addr));
}

// ---------------------------------------------------------------------------
// Prep: fp16(x) and fp16(W^T).
// ---------------------------------------------------------------------------
__global__ __launch_bounds__(256) void half_x_kernel(
    const float* __restrict__ x, __half* __restrict__ xh)
{
    size_t i = ((size_t)blockIdx.x * 256 + threadIdx.x) * 8;
    float4 v0 = *(const float4*)(x + i);
    float4 v1 = *(const float4*)(x + i + 4);
    __half2 h[4];
    h[0] = __floats2half2_rn(v0.x, v0.y);
    h[1] = __floats2half2_rn(v0.z, v0.w);
    h[2] = __floats2half2_rn(v1.x, v1.y);
    h[3] = __floats2half2_rn(v1.z, v1.w);
    *(uint4*)(xh + i) = *(uint4*)h;
}

__global__ __launch_bounds__(256) void half_wt_kernel(
    const float* __restrict__ Wq, const float* __restrict__ Wk,
    const float* __restrict__ Wv, const float* __restrict__ WgK,
    const float* __restrict__ WgC, const float* __restrict__ Wo,
    __half* __restrict__ wth)
{
    __shared__ float tile[32][33];
    const int z = blockIdx.z;
    const float* W = (z == 0) ? Wq : (z == 1) ? Wk : (z == 2) ? Wv
                   : (z == 3) ? WgK : (z == 4) ? WgC : Wo;
    const int n0 = blockIdx.x * 32, k0 = blockIdx.y * 32;
    const int tx = threadIdx.x & 31, ty = threadIdx.x >> 5;
#pragma unroll
    for (int i = 0; i < 4; i++)
        tile[ty + i * 8][tx] = W[(size_t)(k0 + ty + i * 8) * GN + n0 + tx];
    __syncthreads();
    __half* dst = wth + (size_t)z * GN * GK;
#pragma unroll
    for (int i = 0; i < 4; i++)
        dst[(size_t)(n0 + ty + i * 8) * GK + k0 + tx] =
            __float2half_rn(tile[tx][ty + i * 8]);
}

// ---------------------------------------------------------------------------
// FP16 mma GEMM, 512 threads (16 warps = 2m x 8n, warp tile 64x32).
// Round-13 inner loop (no frag double-buffering).
// mode: 0 plain fp32 row-major; 1 permuted fp16 (q/k/v); 2 permuted fp32
// sigmoid (gates).
// ---------------------------------------------------------------------------
#define AST2 72
#define BST2 72
#define AS2_EL (128 * AST2)
#define BS2_EL (256 * BST2)
#define GEMM2_SMEM ((2 * (AS2_EL + BS2_EL)) * (int)sizeof(__half))

__device__ __forceinline__ void gemm2_fill(const __half* __restrict__ A,
                                           const __half* __restrict__ BT,
                                           int rowBase, int colBase, int tid,
                                           __half* AsD, __half* BsD, int kt)
{
    const int k0 = kt * 64;
#pragma unroll
    for (int i = 0; i < 2; i++) {
        const int id = tid + i * 512;
        const int r = id >> 3, c = (id & 7) * 8;
        const __half* src = A + (size_t)(rowBase + r) * GK + k0 + c;
        unsigned dst = (unsigned)__cvta_generic_to_shared(AsD + r * AST2 + c);
        asm volatile("cp.async.cg.shared.global [%0], [%1], 16;" :: "r"(dst), "l"(src));
    }
#pragma unroll
    for (int i = 0; i < 4; i++) {
        const int id = tid + i * 512;
        const int r = id >> 3, c = (id & 7) * 8;
        const __half* src = BT + (size_t)(colBase + r) * GK + k0 + c;
        unsigned dst = (unsigned)__cvta_generic_to_shared(BsD + r * BST2 + c);
        asm volatile("cp.async.cg.shared.global [%0], [%1], 16;" :: "r"(dst), "l"(src));
    }
    asm volatile("cp.async.commit_group;");
}

__global__ __launch_bounds__(512, 1) void gemm_fp16(
    const __half* __restrict__ A, const __half* __restrict__ WTall,
    const float* __restrict__ b3, const float* __restrict__ b4,
    float* __restrict__ Cf, __half* __restrict__ Chb, int multi)
{
    extern __shared__ __half smem[];
    __half* AsB = smem;
    __half* BsB = smem + 2 * AS2_EL;

    const int tid  = threadIdx.x;
    const int lane = tid & 31;
    const int warpId = tid >> 5;
    const int wm = warpId & 1;
    const int wn = warpId >> 1;
    const int g  = lane >> 2;
    const int tg = lane & 3;
    const int rowBase = blockIdx.y * 128;
    const int colBase = blockIdx.x * 256;

    const uint32_t laneAoff =
        (uint32_t)((((lane & 15) * AST2) + ((lane >> 4) << 3)) * 2);
    const int brow = (lane & 7) + ((lane >> 4) << 3);
    const int bko  = ((lane >> 3) & 1) << 3;
    const uint32_t laneBoff = (uint32_t)((brow * BST2 + bko) * 2);

    const size_t PS = (size_t)64 * TSZ * DH;
    const __half* BT; const float* bias; float* C; __half* Ch; int mode;
    if (multi) {
        const int z = blockIdx.z;
        BT = WTall + (size_t)z * GN * GK;
        if (z < 3) {
            Ch = Chb + (size_t)z * PS; C = nullptr; bias = nullptr; mode = 1;
        } else {
            C = Cf + (size_t)(z - 3) * PS; Ch = nullptr;
            bias = (z == 3) ? b3 : b4; mode = 2;
        }
    } else {
        BT = WTall; bias = nullptr; C = Cf; Ch = nullptr; mode = 0;
    }

    float acc[4][4][4];
#pragma unroll
    for (int i = 0; i < 4; i++)
#pragma unroll
        for (int j = 0; j < 4; j++)
#pragma unroll
            for (int e = 0; e < 4; e++) acc[i][j][e] = 0.f;

    gemm2_fill(A, BT, rowBase, colBase, tid, AsB, BsB, 0);

    const int KT = GK / 64;
    for (int kt = 0; kt < KT; kt++) {
        const int cur = kt & 1;
        asm volatile("cp.async.wait_group 0;");
        __syncthreads();
        if (kt + 1 < KT)
            gemm2_fill(A, BT, rowBase, colBase, tid,
                       AsB + (cur ^ 1) * AS2_EL, BsB + (cur ^ 1) * BS2_EL, kt + 1);

        const __half* As = AsB + cur * AS2_EL;
        const __half* Bs = BsB + cur * BS2_EL;
        const uint32_t asb = (uint32_t)__cvta_generic_to_shared(As)
                           + (uint32_t)(wm * 64 * AST2 * 2) + laneAoff;
        const uint32_t bsb = (uint32_t)__cvta_generic_to_shared(Bs)
                           + (uint32_t)(wn * 32 * BST2 * 2) + laneBoff;

#pragma unroll
        for (int kk = 0; kk < 4; kk++) {
            const uint32_t kb2 = kk * 32;   // bytes
            unsigned af[4][4], bf[4][2];
#pragma unroll
            for (int mi = 0; mi < 4; mi++)
                ldsm_x4(af[mi][0], af[mi][1], af[mi][2], af[mi][3],
                        asb + mi * 16 * AST2 * 2 + kb2);
#pragma unroll
            for (int j = 0; j < 2; j++)
                ldsm_x4(bf[2 * j][0], bf[2 * j][1],
                        bf[2 * j + 1][0], bf[2 * j + 1][1],
                        bsb + j * 16 * BST2 * 2 + kb2);
#pragma unroll
            for (int ni = 0; ni < 4; ni++)
#pragma unroll
                for (int mi = 0; mi < 4; mi++) {
                    asm volatile(
                        "mma.sync.aligned.m16n8k16.row.col.f32.f16.f16.f32 "
                        "{%0,%1,%2,%3}, {%4,%5,%6,%7}, {%8,%9}, {%0,%1,%2,%3};\n"
                        : "+f"(acc[mi][ni][0]), "+f"(acc[mi][ni][1]),
                          "+f"(acc[mi][ni][2]), "+f"(acc[mi][ni][3])
                        : "r"(af[mi][0]), "r"(af[mi][1]),
                          "r"(af[mi][2]), "r"(af[mi][3]),
                          "r"(bf[ni][0]), "r"(bf[ni][1]));
                }
        }
    }

#pragma unroll
    for (int mi = 0; mi < 4; mi++) {
        const int gr0 = rowBase + wm * 64 + mi * 16 + g;
#pragma unroll
        for (int ni = 0; ni < 4; ni++) {
            const int gc = colBase + wn * 32 + ni * 8 + 2 * tg;
#pragma unroll
            for (int half = 0; half < 2; half++) {
                const int gr = gr0 + 8 * half;
                float v0 = acc[mi][ni][2 * half];
                float v1 = acc[mi][ni][2 * half + 1];
                if (mode == 0) {
                    *(float2*)&C[(size_t)gr * GN + gc] = make_float2(v0, v1);
                } else {
                    const int b = gr >> 11, t = gr & 2047;
                    const int h = gc >> 6,  d = gc & 63;
                    const size_t idx =
                        ((size_t)((b * HN + h) * TSZ + t)) * DH + d;
                    if (mode == 1) {
                        *(__half2*)&Ch[idx] = __floats2half2_rn(v0, v1);
                    } else {
                        v0 = 1.f / (1.f + __expf(-(v0 + bias[gc])));
                        v1 = 1.f / (1.f + __expf(-(v1 + bias[gc + 1])));
                        *(float2*)&C[idx] = make_float2(v0, v1);
                    }
                }
            }
        }
    }
}

// ---------------------------------------------------------------------------
// Chunked scan, dv-split, fp16 mma + ldmatrix, 512 threads, warp-group task
// parallelism + cp.async input prefetch (q/k now fp16 sources) + vectorized
// epilogues.
// ---------------------------------------------------------------------------
#define O_QS   0                         // half q staging 64x72 (9216 B)
#define O_KS   9216                      // half k staging
#define O_AKF  36864
#define O_ACF  55296
#define O_SF   73728
#define O_CTF  92160
#define O_GTF  101376
#define HB     110592
#define O_QH   (HB + 0)
#define O_KH   (HB + 9216)
#define O_QT   (HB + 18432)
#define O_QTT  (HB + 27648)
#define O_KT   (HB + 36864)
#define O_KTT  (HB + 46080)
#define O_PH   (HB + 55296)
#define O_RS   (HB + 64512)
#define O_UH   (HB + 73728)
#define O_SHH  (HB + 82944)
#define O_VT   (HB + 92160)
#define O_KCT  (HB + 96768)
#define O_CTH  (HB + 101376)
#define O_GTH  (HB + 105984)
#define SCAN_SMEM_BYTES (HB + 110592)

template<int NI>
__device__ __forceinline__ void zacc(float (&acc)[NI][4]) {
#pragma unroll
    for (int i = 0; i < NI; i++)
#pragma unroll
        for (int j = 0; j < 4; j++) acc[i][j] = 0.f;
}

template<int NI, bool NEGA>
__device__ __forceinline__ void mmh(const __half* __restrict__ A,
                                    const __half* __restrict__ B,
                                    float (&acc)[NI][4],
                                    int lane, int mb, int nb)
{
    const uint32_t abase = (uint32_t)__cvta_generic_to_shared(
        A + (mb + (lane & 15)) * SH + ((lane >> 4) << 3));
    const int brow = (lane & 7) + ((lane >> 4) << 3);
    const int bko  = ((lane >> 3) & 1) << 3;
    const uint32_t bbase = (uint32_t)__cvta_generic_to_shared(
        B + (nb + brow) * SH + bko);
#pragma unroll
    for (int kk = 0; kk < 4; kk++) {
        const uint32_t kb2 = kk * 32;
        unsigned a0, a1, a2, a3;
        ldsm_x4(a0, a1, a2, a3, abase + kb2);
        if (NEGA) {
            a0 ^= 0x80008000u; a1 ^= 0x80008000u;
            a2 ^= 0x80008000u; a3 ^= 0x80008000u;
        }
#pragma unroll
        for (int j = 0; j < NI / 2; j++) {
            unsigned b0, b1, b2, b3;
            ldsm_x4(b0, b1, b2, b3, bbase + (uint32_t)(j * 16 * SH * 2) + kb2);
            asm volatile(
                "mma.sync.aligned.m16n8k16.row.col.f32.f16.f16.f32 "
                "{%0,%1,%2,%3}, {%4,%5,%6,%7}, {%8,%9}, {%0,%1,%2,%3};\n"
                : "+f"(acc[2 * j][0]), "+f"(acc[2 * j][1]),
                  "+f"(acc[2 * j][2]), "+f"(acc[2 * j][3])
                : "r"(a0), "r"(a1), "r"(a2), "r"(a3), "r"(b0), "r"(b1));
            asm volatile(
                "mma.sync.aligned.m16n8k16.row.col.f32.f16.f16.f32 "
                "{%0,%1,%2,%3}, {%4,%5,%6,%7}, {%8,%9}, {%0,%1,%2,%3};\n"
                : "+f"(acc[2 * j + 1][0]), "+f"(acc[2 * j + 1][1]),
                  "+f"(acc[2 * j + 1][2]), "+f"(acc[2 * j + 1][3])
                : "r"(a0), "r"(a1), "r"(a2), "r"(a3), "r"(b2), "r"(b3));
        }
    }
}

template<bool NEGA>
__device__ __forceinline__ void mmh1(const __half* __restrict__ A,
                                     const __half* __restrict__ B,
                                     float (&acc)[4],
                                     int lane, int mb, int nb)
{
    const uint32_t abase = (uint32_t)__cvta_generic_to_shared(
        A + (mb + (lane & 15)) * SH + ((lane >> 4) << 3));
    const uint32_t bbase = (uint32_t)__cvta_generic_to_shared(
        B + (nb + (lane & 7)) * SH + (((lane >> 3) & 1) << 3));
#pragma unroll
    for (int kk = 0; kk < 4; kk++) {
        const uint32_t kb2 = kk * 32;
        unsigned a0, a1, a2, a3;
        ldsm_x4(a0, a1, a2, a3, abase + kb2);
        if (NEGA) {
            a0 ^= 0x80008000u; a1 ^= 0x80008000u;
            a2 ^= 0x80008000u; a3 ^= 0x80008000u;
        }
        unsigned b0, b1;
        ldsm_x2(b0, b1, bbase + kb2);
        asm volatile(
            "mma.sync.aligned.m16n8k16.row.col.f32.f16.f16.f32 "
            "{%0,%1,%2,%3}, {%4,%5,%6,%7}, {%8,%9}, {%0,%1,%2,%3};\n"
            : "+f"(acc[0]), "+f"(acc[1]), "+f"(acc[2]), "+f"(acc[3])
            : "r"(a0), "r"(a1), "r"(a2), "r"(a3), "r"(b0), "r"(b1));
    }
}

template<int NI, int MASK, bool SCALE>
__device__ __forceinline__ void storeH(__half* __restrict__ O,
    const float* __restrict__ scl, float (&acc)[NI][4],
    int g, int tg, int mb, int nb)
{
#pragma unroll
    for (int ni = 0; ni < NI; ni++) {
        const int c0 = nb + ni * 8 + 2 * tg;
#pragma unroll
        for (int hh = 0; hh < 2; hh++) {
            const int r = mb + g + 8 * hh;
            float v0 = acc[ni][2 * hh];
            float v1 = acc[ni][2 * hh + 1];
            if (MASK == 1) { if (c0 > r) v0 = 0.f; if (c0 + 1 > r) v1 = 0.f; }
            if (MASK == 2) { if (c0 >= r) v0 = 0.f; if (c0 + 1 >= r) v1 = 0.f; }
            if (SCALE) { v0 *= scl[r * TS + c0]; v1 *= scl[r * TS + c0 + 1]; }
            *(__half2*)&O[r * SH + c0] = __floats2half2_rn(v0, v1);
        }
    }
}

template<int NI>
__device__ __forceinline__ void storeHT(__half* __restrict__ O,
    float (&acc)[NI][4], int g, int tg, int mb, int nb)
{
#pragma unroll
    for (int ni = 0; ni < NI; ni++) {
        const int c0 = nb + ni * 8 + 2 * tg;
#pragma unroll
        for (int hh = 0; hh < 2; hh++) {
            const int r = mb + g + 8 * hh;
#pragma unroll
            for (int e = 0; e < 2; e++)
                O[(c0 + e) * SH + r] = __float2half_rn(acc[ni][2 * hh + e]);
        }
    }
}

template<int NI>
__device__ __forceinline__ void updateS(float* __restrict__ Sf,
    __half* __restrict__ Sh, const float* __restrict__ rs,
    float (&acc)[NI][4], int g, int tg, int mb, int nb)
{
#pragma unroll
    for (int ni = 0; ni < NI; ni++) {
        const int c0 = nb + ni * 8 + 2 * tg;
#pragma unroll
        for (int hh = 0; hh < 2; hh++) {
            const int r = mb + g + 8 * hh;
            const float rr = rs[r];
            float v0 = rr * rs[c0]     * (Sf[r * TS + c0]     + acc[ni][2 * hh]);
            float v1 = rr * rs[c0 + 1] * (Sf[r * TS + c0 + 1] + acc[ni][2 * hh + 1]);
            *(float2*)&Sf[r * TS + c0] = make_float2(v0, v1);
            *(__half2*)&Sh[r * SH + c0] = __floats2half2_rn(v0, v1);
        }
    }
}

template<int NI>
__device__ __forceinline__ void updateT(float* __restrict__ Tf,
    __half* __restrict__ Th, const float* __restrict__ rs,
    float (&acc)[NI][4], int g, int tg, int mb, int nb)
{
#pragma unroll
    for (int ni = 0; ni < NI; ni++) {
        const int c0 = nb + ni * 8 + 2 * tg;
#pragma unroll
        for (int hh = 0; hh < 2; hh++) {
            const int r = mb + g + 8 * hh;
            float v0 = rs[c0]     * (Tf[r * TS + c0]     + acc[ni][2 * hh]);
            float v1 = rs[c0 + 1] * (Tf[r * TS + c0 + 1] + acc[ni][2 * hh + 1]);
            *(float2*)&Tf[r * TS + c0] = make_float2(v0, v1);
            *(__half2*)&Th[r * SH + c0] = __floats2half2_rn(v0, v1);
        }
    }
}

// cp.async prefetch: q,k fp16 tiles (512 x 16B each) + aK,aC fp32 tiles
// (1024 x 16B each) = 3072 chunks, 6 per thread.
__device__ __forceinline__ void scan_prefetch(
    const __half* __restrict__ q, const __half* __restrict__ k,
    const float* __restrict__ aK, const float* __restrict__ aC,
    uint32_t smbase, int tid, size_t off)
{
#pragma unroll
    for (int i = 0; i < 6; i++) {
        const int id = tid + i * 512;
        uint32_t dst;
        const void* src;
        if (id < 1024) {                 // q (0..511), k (512..1023) fp16
            const int t8 = id >> 9, loc = id & 511;
            const int r = loc >> 3, c8 = (loc & 7) * 8;
            const __half* s = (t8 == 0) ? q : k;
            src = s + off + (size_t)loc * 8;
            dst = smbase + (uint32_t)(t8 * 9216 + (r * SH + c8) * 2);
        } else {                         // aK, aC fp32
            const int t4 = (id - 1024) >> 10, loc = (id - 1024) & 1023;
            const int r = loc >> 4, c4 = (loc & 15) * 4;
            const float* s = (t4 == 0) ? aK : aC;
            src = s + off + (size_t)loc * 4;
            dst = smbase + (uint32_t)(O_AKF + t4 * 18432 + (r * TS + c4) * 4);
        }
        asm volatile("cp.async.cg.shared.global [%0], [%1], 16;" :: "r"(dst), "l"(src));
    }
    asm volatile("cp.async.commit_group;");
}

__global__ __launch_bounds__(512) void scan_chunked(
    const __half* __restrict__ qp, const __half* __restrict__ kp,
    const __half* __restrict__ vp, const float* __restrict__ aKp,
    const float* __restrict__ aCp, __half* __restrict__ o2dh)
{
    extern __shared__ char smc[];
    __half* QS  = (__half*)(smc + O_QS);
    __half* KS  = (__half*)(smc + O_KS);
    float*  AKf = (float*)(smc + O_AKF);
    float*  ACf = (float*)(smc + O_ACF);
    float*  Sf  = (float*)(smc + O_SF);
    float*  CTf = (float*)(smc + O_CTF);
    float*  GTf = (float*)(smc + O_GTF);
    __half* Qh  = (__half*)(smc + O_QH);
    __half* Kh  = (__half*)(smc + O_KH);
    __half* Qt  = (__half*)(smc + O_QT);
    __half* QtT = (__half*)(smc + O_QTT);
    __half* Kt  = (__half*)(smc + O_KT);
    __half* KtT = (__half*)(smc + O_KTT);
    __half* Ph  = (__half*)(smc + O_PH);
    __half* RSc = (__half*)(smc + O_RS);
    __half* Uh  = (__half*)(smc + O_UH);
    __half* Sh  = (__half*)(smc + O_SHH);
    __half* VT  = (__half*)(smc + O_VT);
    __half* KCT = (__half*)(smc + O_KCT);
    __half* CTh = (__half*)(smc + O_CTH);
    __half* GTh = (__half*)(smc + O_GTH);
    __shared__ float aKL[64], aCL[64];

    const int bh   = blockIdx.x >> 1;
    const int half = blockIdx.x & 1;
    const int b = bh >> 4, h = bh & 15;
    const size_t base = (size_t)bh * TSZ * DH;
    const int tid  = threadIdx.x;
    const int lane = tid & 31, w = tid >> 5;
    const int wg = w >> 3, w8 = w & 7;
    const int g = lane >> 2, tg = lane & 3;
    const int mb4 = (w8 & 3) * 16, nb4 = (w8 >> 2) * 32;
    const int mb2 = (w8 & 3) * 16, nb2 = (w8 >> 2) * 16;
    const int mbF = (w8 & 1) * 16, nbF = (w8 >> 1) * 16;
    const int mbO = (w & 3) * 16,  nbO = (w >> 2) * 8;
    const uint32_t smbase = (uint32_t)__cvta_generic_to_shared(smc);

    for (int i = tid; i < 9216; i += 512) ((uint32_t*)(smc + O_SF))[i] = 0;
    for (int i = tid; i < 2304; i += 512) ((uint32_t*)(smc + O_SHH))[i] = 0;
    for (int i = tid; i < 2304; i += 512) ((uint32_t*)(smc + O_CTH))[i] = 0;

    scan_prefetch(qp, kp, aKp, aCp, smbase, tid, base);
    __syncthreads();

    for (int ch = 0; ch < NCHUNK; ch++) {
        const size_t off = base + (size_t)ch * CL * DH;
        {   // V (fp16 source) half-column -> VT transposed
            const int r = tid >> 3, c4 = (tid & 7) * 4;
            __half2 hv[2];
            *(uint2*)hv = *(const uint2*)(vp + off + r * DH + half * 32 + c4);
            VT[(c4 + 0) * SH + r] = __low2half(hv[0]);
            VT[(c4 + 1) * SH + r] = __high2half(hv[0]);
            VT[(c4 + 2) * SH + r] = __low2half(hv[1]);
            VT[(c4 + 3) * SH + r] = __high2half(hv[1]);
        }
        asm volatile("cp.async.wait_group 0;");
        __syncthreads();

        {   // cumulative products: 2 tensors x 4 segments of 16 rows
            float* Tt = (tid < 256) ? AKf : ACf;
            const int col = tid & 63;
            const int seg = (tid >> 6) & 3;
            const int r0 = seg * 16;
            float p = 1.f;
#pragma unroll
            for (int r = 0; r < 16; r++) {
                p *= Tt[(r0 + r) * TS + col];
                Tt[(r0 + r) * TS + col] = p;
            }
            __syncthreads();
            float pref = 1.f;
#pragma unroll
            for (int s = 0; s < 3; s++)
                if (s < seg) pref *= Tt[(s * 16 + 15) * TS + col];
            __syncthreads();
            if (seg > 0) {
#pragma unroll
                for (int r = 0; r < 16; r++) Tt[(r0 + r) * TS + col] *= pref;
            }
        }
        __syncthreads();

        // derive fp16 operand tiles (+ SCL fp32 in AKf slot)
#pragma unroll
        for (int i = 0; i < 8; i++) {
            const int e = tid + i * 512;
            const int r = e >> 6, c = e & 63;
            const int idx = r * TS + c;
            const float ak = AKf[idx], ac = ACf[idx];
            const float qv = __half2float(QS[r * SH + c]);
            const float kv = __half2float(KS[r * SH + c]);
            if (r == 63) { aKL[c] = ak; aCL[c] = ac; }
            const float qh = qv * ak, kt = kv / ak;
            const float qt = qv / ac, kh = kv * ac;
            Qh[r * SH + c]  = __float2half_rn(qh);
            Kh[r * SH + c]  = __float2half_rn(kh);
            Qt[r * SH + c]  = __float2half_rn(qt);
            QtT[c * SH + r] = __float2half_rn(qt);
            Kt[r * SH + c]  = __float2half_rn(kt);
            KtT[c * SH + r] = __float2half_rn(kt);
            AKf[idx] = ak * ac;          // SCL
        }
        __syncthreads();

        float acc4[4][4];
        float acc2[2][4];

        // Phase A
        if (wg == 0) {
            zacc(acc4);
            mmh<4, false>(Kh, Qt, acc4, lane, mb4, nb4);
            storeH<4, 2, false>(RSc, nullptr, acc4, g, tg, mb4, nb4);
        } else {
            zacc(acc4);
            mmh<4, false>(Qh, Kt, acc4, lane, mb4, nb4);
            storeH<4, 1, false>(Ph, nullptr, acc4, g, tg, mb4, nb4);
        }
        __syncthreads();

        // Phase B
        if (wg == 0) {
            zacc(acc2);
            mmh<2, false>(Kh,  CTh, acc2, lane, mb2, nb2);
            mmh<2, false>(RSc, VT,  acc2, lane, mb2, nb2);
            storeHT<2>(KCT, acc2, g, tg, mb2, nb2);
        } else {
            zacc(acc4);
            mmh<4, false>(Qh, Sh,  acc4, lane, mb4, nb4);
            mmh<4, false>(Ph, KtT, acc4, lane, mb4, nb4);
            storeH<4, 0, true>(Uh, AKf, acc4, g, tg, mb4, nb4);
        }
        __syncthreads();

        // staging dead: prefetch next chunk
        {
            int chn = ch + 1; if (chn > NCHUNK - 1) chn = NCHUNK - 1;
            scan_prefetch(qp, kp, aKp, aCp, smbase, tid,
                          base + (size_t)chn * CL * DH);
        }

        // Phase C
        if (wg == 0) {
            zacc(acc4);
            mmh<4, false>(Uh, Qt, acc4, lane, mb4, nb4);
            storeH<4, 1, false>(RSc, nullptr, acc4, g, tg, mb4, nb4);
        } else {
            zacc(acc4);
            mmh<4, false>(KtT, KtT, acc4, lane, mb4, nb4);
            updateS<4>(Sf, Sh, aKL, acc4, g, tg, mb4, nb4);
        }
        __syncthreads();

        // Phase E
        {
            float accO[4] = {0.f, 0.f, 0.f, 0.f};
            mmh1<false>(Uh,  CTh, accO, lane, mbO, nbO);
            mmh1<false>(RSc, VT,  accO, lane, mbO, nbO);
            mmh1<true >(Qh,  GTh, accO, lane, mbO, nbO);
            mmh1<true >(Ph,  KCT, accO, lane, mbO, nbO);
            const int t0 = ch * CL;
            const int c0 = nbO + 2 * tg;
#pragma unroll
            for (int hh = 0; hh < 2; hh++) {
                const int r = mbO + g + 8 * hh;
                __half2 st = __floats2half2_rn(accO[2 * hh], accO[2 * hh + 1]);
                *(__half2*)&o2dh[(size_t)(b * TSZ + t0 + r) * 1024 +
                                 h * DH + half * 32 + c0] = st;
            }
        }
        __syncthreads();

        // Phase F
        if (wg == 0) {
            zacc(acc2);
            mmh<2, false>(VT, QtT, acc2, lane, mbF, nbF);
            updateT<2>(CTf, CTh, aCL, acc2, g, tg, mbF, nbF);
        } else {
            zacc(acc2);
            mmh<2, false>(KCT, KtT, acc2, lane, mbF, nbF);
            updateT<2>(GTf, GTh, aKL, acc2, g, tg, mbF, nbF);
        }
        __syncthreads();
    }
}

// ---------------------------------------------------------------------------
extern "C" void kernel_launch(void* const* d_in, const int* in_sizes, int n_in,
                              void* d_out, int out_size)
{
    const float* x   = (const float*)d_in[0];
    const float* Wq  = (const float*)d_in[1];
    const float* Wk  = (const float*)d_in[2];
    const float* Wv  = (const float*)d_in[3];
    const float* WgK = (const float*)d_in[4];
    const float* bgK = (const float*)d_in[5];
    const float* WgC = (const float*)d_in[6];
    const float* bgC = (const float*)d_in[7];
    const float* Wo  = (const float*)d_in[8];
    float* out = (float*)d_out;

    __half *projh = nullptr, *o2dh = nullptr, *xh = nullptr, *wth = nullptr;
    float  *projf = nullptr;
    cudaGetSymbolAddress((void**)&projh, g_projh);
    cudaGetSymbolAddress((void**)&projf, g_projf);
    cudaGetSymbolAddress((void**)&o2dh,  g_o2dh);
    cudaGetSymbolAddress((void**)&xh,    g_xh);
    cudaGetSymbolAddress((void**)&wth,   g_wth);
    const size_t PS = (size_t)64 * TSZ * DH;

    cudaFuncSetAttribute(gemm_fp16,
                         cudaFuncAttributeMaxDynamicSharedMemorySize,
                         GEMM2_SMEM);
    cudaFuncSetAttribute(scan_chunked,
                         cudaFuncAttributeMaxDynamicSharedMemorySize,
                         SCAN_SMEM_BYTES);

    half_x_kernel<<<(GM * GK) / 2048, 256>>>(x, xh);
    half_wt_kernel<<<dim3(32, 32, 6), 256>>>(Wq, Wk, Wv, WgK, WgC, Wo, wth);

    gemm_fp16<<<dim3(GN / 256, GM / 128, 5), 512, GEMM2_SMEM>>>(
        xh, wth, bgK, bgC, projf, projh, 1);

    scan_chunked<<<128, 512, SCAN_SMEM_BYTES>>>(
        projh, projh + PS, projh + 2 * PS, projf, projf + PS, o2dh);

    gemm_fp16<<<dim3(GN / 256, GM / 128, 1), 512, GEMM2_SMEM>>>(
        o2dh, wth + (size_t)5 * GN * GK, nullptr, nullptr, out, nullptr, 0);
}